// round 1
// baseline (speedup 1.0000x reference)
#include <cuda_runtime.h>

// ---------------- scratch (device globals; no dynamic alloc allowed) -------------
#define TOT (4*256*256*128)
static __device__ float g_xu[TOT];   // upsampled x, (B,H,W,C) = (4,256,256,128)
static __device__ float g_y [TOT];   // after attention + residual
static __device__ float g_t1[TOT];   // after conv1+bn1+relu

// ---------------- K1: bilinear 2x upsample (align_corners) on dims 2,3 ----------
__global__ void k_upsample(const float* __restrict__ xin) {
    int idx = blockIdx.x * 256 + threadIdx.x;          // 33,554,432 total
    int cc = idx & 127;
    int t  = idx >> 7;
    int ww = t & 255; t >>= 8;
    int hh = t & 255;
    int b  = t >> 8;
    float pw = ww * (127.0f / 255.0f);
    int wlo = (int)pw; float fw = pw - (float)wlo; int whi = min(wlo + 1, 127);
    float pc = cc * (63.0f / 127.0f);
    int clo = (int)pc; float fc = pc - (float)clo; int chi = min(clo + 1, 63);
    const float* base = xin + ((b * 256 + hh) * 128) * 64;
    float v00 = base[wlo * 64 + clo], v01 = base[wlo * 64 + chi];
    float v10 = base[whi * 64 + clo], v11 = base[whi * 64 + chi];
    g_xu[idx] = (1.f - fw) * ((1.f - fc) * v00 + fc * v01)
              +        fw  * ((1.f - fc) * v10 + fc * v11);
}

// ---------------- K2: shifted-window attention, one window per block ------------
// window 4x4, shift 3, 4 heads x headdim 32, C=128.
__global__ __launch_bounds__(128) void k_attn(
    const float* __restrict__ qkv_w, const float* __restrict__ qkv_b,
    const float* __restrict__ proj_w, const float* __restrict__ proj_b,
    const float* __restrict__ rpb)
{
    __shared__ float Xs[16][128];
    __shared__ float QKV[16][384];
    __shared__ float P[4][16][16];
    __shared__ float O[16][128];

    int tid  = threadIdx.x;
    int blk  = blockIdx.x;              // 16384 = 4 * 64 * 64
    int b    = blk >> 12;
    int widx = blk & 4095;
    int wh   = widx >> 6;
    int wc   = widx & 63;

    // load window (shifted coords -> rolled source coords). residual uses same tile.
    #pragma unroll
    for (int t = 0; t < 16; t++) {
        int hs = wh * 4 + (t >> 2), ws = wc * 4 + (t & 3);
        int h2 = (hs + 3) & 255, w2 = (ws + 3) & 255;
        Xs[t][tid] = g_xu[((b * 256 + h2) * 256 + w2) * 128 + tid];
    }
    __syncthreads();

    // qkv: each thread owns cols {tid, tid+128, tid+256} for all 16 tokens
    float a0[16], a1[16], a2[16];
    #pragma unroll
    for (int t = 0; t < 16; t++) { a0[t] = 0.f; a1[t] = 0.f; a2[t] = 0.f; }
    for (int k = 0; k < 128; k++) {
        float w0 = qkv_w[k * 384 + tid];
        float w1 = qkv_w[k * 384 + 128 + tid];
        float w2 = qkv_w[k * 384 + 256 + tid];
        #pragma unroll
        for (int t = 0; t < 16; t++) {
            float xv = Xs[t][k];
            a0[t] += xv * w0; a1[t] += xv * w1; a2[t] += xv * w2;
        }
    }
    {
        float b0 = qkv_b[tid], b1 = qkv_b[128 + tid], b2 = qkv_b[256 + tid];
        #pragma unroll
        for (int t = 0; t < 16; t++) {
            QKV[t][tid]       = a0[t] + b0;
            QKV[t][128 + tid] = a1[t] + b1;
            QKV[t][256 + tid] = a2[t] + b2;
        }
    }
    __syncthreads();

    int warp = tid >> 5, lane = tid & 31;
    // scores + softmax: warp = head, lanes 0..15 = query token
    if (lane < 16) {
        int t = lane, h = warp;
        float q[32];
        #pragma unroll
        for (int d = 0; d < 32; d++) q[d] = QKV[t][h * 32 + d] * 0.17677669529663687f;
        int i1 = t >> 2, j1 = t & 3;
        int rh1 = wh * 4 + i1, rw1 = wc * 4 + j1;
        int l1 = ((rh1 < 252) ? 0 : ((rh1 < 253) ? 1 : 2)) * 3
               + ((rw1 < 252) ? 0 : ((rw1 < 253) ? 1 : 2));
        float s[16];
        float mx = -1e30f;
        #pragma unroll
        for (int u = 0; u < 16; u++) {
            float dot = 0.f;
            #pragma unroll
            for (int d = 0; d < 32; d++) dot += q[d] * QKV[u][128 + h * 32 + d];
            int i2 = u >> 2, j2 = u & 3;
            int ridx = (i1 - i2 + 3) * 7 + (j1 - j2 + 3);
            dot += rpb[ridx * 4 + h];
            int rh2 = wh * 4 + i2, rw2 = wc * 4 + j2;
            int l2 = ((rh2 < 252) ? 0 : ((rh2 < 253) ? 1 : 2)) * 3
                   + ((rw2 < 252) ? 0 : ((rw2 < 253) ? 1 : 2));
            if (l1 != l2) dot -= 100.f;
            s[u] = dot;
            mx = fmaxf(mx, dot);
        }
        float sum = 0.f;
        #pragma unroll
        for (int u = 0; u < 16; u++) { s[u] = __expf(s[u] - mx); sum += s[u]; }
        float inv = 1.f / sum;
        #pragma unroll
        for (int u = 0; u < 16; u++) P[h][t][u] = s[u] * inv;
    }
    __syncwarp();

    // P @ V : warp = head, lane = output dim d
    {
        int h = warp, d = lane;
        #pragma unroll
        for (int t = 0; t < 16; t++) {
            float acc = 0.f;
            #pragma unroll
            for (int u = 0; u < 16; u++) acc += P[h][t][u] * QKV[u][256 + h * 32 + d];
            O[t][h * 32 + d] = acc;
        }
    }
    __syncthreads();

    // proj + bias + residual, scatter back to unshifted coords
    float pa[16];
    #pragma unroll
    for (int t = 0; t < 16; t++) pa[t] = 0.f;
    for (int k = 0; k < 128; k++) {
        float wv = proj_w[k * 128 + tid];
        #pragma unroll
        for (int t = 0; t < 16; t++) pa[t] += O[t][k] * wv;
    }
    float pb = proj_b[tid];
    #pragma unroll
    for (int t = 0; t < 16; t++) {
        int hs = wh * 4 + (t >> 2), ws = wc * 4 + (t & 3);
        int h2 = (hs + 3) & 255, w2 = (ws + 3) & 255;
        g_y[((b * 256 + h2) * 256 + w2) * 128 + tid] = pa[t] + pb + Xs[t][tid];
    }
}

// ---------------- K3/K4: 3x3 conv + BN (+relu / +1x1 identity branch) -----------
// NCHW view: N=4, C=256, H=256, W=128.
// Block tile: CO=64, H=4, W=32. Thread micro-tile: 8 co x 4 w.
// Warp-uniform co group => weight LDS is broadcast. Input rows padded to 35
// floats => conflict-free LDS.
template <int SECOND>
__global__ __launch_bounds__(256, 2) void k_conv(
    const float* __restrict__ cw, const float* __restrict__ cb,
    const float* __restrict__ bg, const float* __restrict__ bb,
    const float* __restrict__ bm, const float* __restrict__ bv,
    const float* __restrict__ iw, const float* __restrict__ ibi,
    const float* __restrict__ ig, const float* __restrict__ ib2,
    const float* __restrict__ im, const float* __restrict__ iv,
    float* __restrict__ out)
{
    __shared__ float in_s[8 * 6 * 35];
    __shared__ float wgt_s[64 * 72];
    __shared__ float y_s[SECOND ? 8 * 4 * 33 : 1];
    __shared__ float wi_s[SECOND ? 512 : 1];

    const float* in = SECOND ? g_t1 : g_y;

    int tid = threadIdx.x;
    int cog = tid >> 5;            // warp id == co group (uniform per warp)
    int rem = tid & 31;
    int hg  = rem >> 3;            // 0..3
    int wg  = rem & 7;             // 0..7
    int hb  = blockIdx.x >> 2, wb = blockIdx.x & 3;
    int co_b = blockIdx.y, n = blockIdx.z;
    int h0 = hb * 4, w0 = wb * 32;

    float acc[8][4];
    float iacc[8][4];
    #pragma unroll
    for (int i = 0; i < 8; i++)
        #pragma unroll
        for (int j = 0; j < 4; j++) { acc[i][j] = 0.f; iacc[i][j] = 0.f; }

    const float* inbase = in + n * 256 * 256 * 128;

    for (int ci0 = 0; ci0 < 256; ci0 += 8) {
        // input patch (with zero padding): 8 ci x 6 h x 34 w
        for (int idx = tid; idx < 8 * 6 * 34; idx += 256) {
            int ci = idx / 204; int r = idx - ci * 204;
            int dh = r / 34;    int dw = r - dh * 34;
            int gh = h0 - 1 + dh, gw = w0 - 1 + dw;
            float v = 0.f;
            if ((unsigned)gh < 256u && (unsigned)gw < 128u)
                v = inbase[((ci0 + ci) * 256 + gh) * 128 + gw];
            in_s[ci * 210 + dh * 35 + dw] = v;
        }
        // weights: co-major, contiguous copy (72 floats per co)
        for (int idx = tid; idx < 4608; idx += 256) {
            int co = idx / 72; int r = idx - co * 72;
            wgt_s[idx] = cw[((co_b * 64 + co) * 256 + ci0) * 9 + r];
        }
        if (SECOND) {
            for (int idx = tid; idx < 1024; idx += 256) {
                int ci = idx >> 7; int r = idx & 127;
                int dh = r >> 5;   int dw = r & 31;
                y_s[ci * 132 + dh * 33 + dw] =
                    g_y[((n * 256 + ci0 + ci) * 256 + h0 + dh) * 128 + w0 + dw];
            }
            for (int idx = tid; idx < 512; idx += 256) {
                int co = idx >> 3, ci = idx & 7;
                wi_s[idx] = iw[(co_b * 64 + co) * 256 + ci0 + ci];
            }
        }
        __syncthreads();

        #pragma unroll
        for (int ci = 0; ci < 8; ci++) {
            #pragma unroll
            for (int kh = 0; kh < 3; kh++) {
                float r[6];
                #pragma unroll
                for (int s = 0; s < 6; s++)
                    r[s] = in_s[ci * 210 + (hg + kh) * 35 + wg * 4 + s];
                #pragma unroll
                for (int kw = 0; kw < 3; kw++) {
                    #pragma unroll
                    for (int i = 0; i < 8; i++) {
                        float wv = wgt_s[(cog * 8 + i) * 72 + ci * 9 + kh * 3 + kw];
                        #pragma unroll
                        for (int j = 0; j < 4; j++) acc[i][j] += r[kw + j] * wv;
                    }
                }
            }
            if (SECOND) {
                float yv[4];
                #pragma unroll
                for (int j = 0; j < 4; j++) yv[j] = y_s[ci * 132 + hg * 33 + wg * 4 + j];
                #pragma unroll
                for (int i = 0; i < 8; i++) {
                    float wvi = wi_s[(cog * 8 + i) * 8 + ci];
                    #pragma unroll
                    for (int j = 0; j < 4; j++) iacc[i][j] += yv[j] * wvi;
                }
            }
        }
        __syncthreads();
    }

    // epilogue: fold BN, (+identity branch), relu
    #pragma unroll
    for (int i = 0; i < 8; i++) {
        int co = co_b * 64 + cog * 8 + i;
        float s    = bg[co] * rsqrtf(bv[co] + 1e-5f);
        float bias = cb[co] * s + bb[co] - bm[co] * s;
        float vals[4];
        if (SECOND) {
            float si    = ig[co] * rsqrtf(iv[co] + 1e-5f);
            float biasi = ibi[co] * si + ib2[co] - im[co] * si;
            #pragma unroll
            for (int j = 0; j < 4; j++)
                vals[j] = fmaxf(acc[i][j] * s + bias + iacc[i][j] * si + biasi, 0.f);
        } else {
            #pragma unroll
            for (int j = 0; j < 4; j++)
                vals[j] = fmaxf(acc[i][j] * s + bias, 0.f);
        }
        int h = h0 + hg, w = w0 + wg * 4;
        float* dstf = SECOND ? out : g_t1;
        float4* dst = (float4*)&dstf[((n * 256 + co) * 256 + h) * 128 + w];
        *dst = make_float4(vals[0], vals[1], vals[2], vals[3]);
    }
}

// ---------------- launcher ------------------------------------------------------
extern "C" void kernel_launch(void* const* d_in, const int* in_sizes, int n_in,
                              void* d_out, int out_size) {
    const float* x      = (const float*)d_in[0];
    const float* qkv_w  = (const float*)d_in[1];
    const float* qkv_b  = (const float*)d_in[2];
    const float* proj_w = (const float*)d_in[3];
    const float* proj_b = (const float*)d_in[4];
    const float* rpb    = (const float*)d_in[5];
    const float* c1w = (const float*)d_in[6];
    const float* c1b = (const float*)d_in[7];
    const float* b1g = (const float*)d_in[8];
    const float* b1b = (const float*)d_in[9];
    const float* b1m = (const float*)d_in[10];
    const float* b1v = (const float*)d_in[11];
    const float* c2w = (const float*)d_in[12];
    const float* c2b = (const float*)d_in[13];
    const float* b2g = (const float*)d_in[14];
    const float* b2b = (const float*)d_in[15];
    const float* b2m = (const float*)d_in[16];
    const float* b2v = (const float*)d_in[17];
    const float* idw = (const float*)d_in[18];
    const float* idb = (const float*)d_in[19];
    const float* big = (const float*)d_in[20];
    const float* bib = (const float*)d_in[21];
    const float* bim = (const float*)d_in[22];
    const float* biv = (const float*)d_in[23];
    float* out = (float*)d_out;

    k_upsample<<<TOT / 256, 256>>>(x);
    k_attn<<<16384, 128>>>(qkv_w, qkv_b, proj_w, proj_b, rpb);

    dim3 grid(256, 4, 4);  // x = h_block*4 + w_block, y = co_block, z = n
    k_conv<0><<<grid, 256>>>(c1w, c1b, b1g, b1b, b1m, b1v,
                             idw, idb, big, bib, bim, biv, out);
    k_conv<1><<<grid, 256>>>(c2w, c2b, b2g, b2b, b2m, b2v,
                             idw, idb, big, bib, bim, biv, out);
}

// round 2
// speedup vs baseline: 1.1341x; 1.1341x over previous
#include <cuda_runtime.h>

// ---------------- scratch (device globals; no dynamic alloc allowed) -------------
#define TOT (4*256*256*128)
static __device__ float g_xu[TOT];   // upsampled x, (B,H,W,C) = (4,256,256,128)
static __device__ float g_y [TOT];   // after attention + residual
static __device__ float g_t1[TOT];   // after conv1+bn1+relu

// ---------------- f32x2 packed-FMA helpers (sm_103a FFMA2) ----------------------
__device__ __forceinline__ unsigned long long pk2(float lo, float hi) {
    unsigned long long r;
    asm("mov.b64 %0, {%1, %2};" : "=l"(r) : "f"(lo), "f"(hi));
    return r;
}
__device__ __forceinline__ void ffma2(unsigned long long& d,
                                      unsigned long long a, unsigned long long b) {
    asm("fma.rn.f32x2 %0, %1, %2, %0;" : "+l"(d) : "l"(a), "l"(b));
}
__device__ __forceinline__ float2 upk(unsigned long long p) {
    float2 f;
    asm("mov.b64 {%0, %1}, %2;" : "=f"(f.x), "=f"(f.y) : "l"(p));
    return f;
}

// ---------------- K1: bilinear 2x upsample (align_corners) on dims 2,3 ----------
__global__ void k_upsample(const float* __restrict__ xin) {
    int idx = blockIdx.x * 256 + threadIdx.x;          // 33,554,432 total
    int cc = idx & 127;
    int t  = idx >> 7;
    int ww = t & 255; t >>= 8;
    int hh = t & 255;
    int b  = t >> 8;
    float pw = ww * (127.0f / 255.0f);
    int wlo = (int)pw; float fw = pw - (float)wlo; int whi = min(wlo + 1, 127);
    float pc = cc * (63.0f / 127.0f);
    int clo = (int)pc; float fc = pc - (float)clo; int chi = min(clo + 1, 63);
    const float* base = xin + ((b * 256 + hh) * 128) * 64;
    float v00 = base[wlo * 64 + clo], v01 = base[wlo * 64 + chi];
    float v10 = base[whi * 64 + clo], v11 = base[whi * 64 + chi];
    g_xu[idx] = (1.f - fw) * ((1.f - fc) * v00 + fc * v01)
              +        fw  * ((1.f - fc) * v10 + fc * v11);
}

// ---------------- K2: shifted-window attention, one window per block ------------
__global__ __launch_bounds__(128) void k_attn(
    const float* __restrict__ qkv_w, const float* __restrict__ qkv_b,
    const float* __restrict__ proj_w, const float* __restrict__ proj_b,
    const float* __restrict__ rpb)
{
    __shared__ float Xs[16][128];
    __shared__ float QKV[16][384];
    __shared__ float P[4][16][16];
    __shared__ float O[16][128];

    int tid  = threadIdx.x;
    int blk  = blockIdx.x;              // 16384 = 4 * 64 * 64
    int b    = blk >> 12;
    int widx = blk & 4095;
    int wh   = widx >> 6;
    int wc   = widx & 63;

    #pragma unroll
    for (int t = 0; t < 16; t++) {
        int hs = wh * 4 + (t >> 2), ws = wc * 4 + (t & 3);
        int h2 = (hs + 3) & 255, w2 = (ws + 3) & 255;
        Xs[t][tid] = g_xu[((b * 256 + h2) * 256 + w2) * 128 + tid];
    }
    __syncthreads();

    float a0[16], a1[16], a2[16];
    #pragma unroll
    for (int t = 0; t < 16; t++) { a0[t] = 0.f; a1[t] = 0.f; a2[t] = 0.f; }
    for (int k = 0; k < 128; k++) {
        float w0 = qkv_w[k * 384 + tid];
        float w1 = qkv_w[k * 384 + 128 + tid];
        float w2 = qkv_w[k * 384 + 256 + tid];
        #pragma unroll
        for (int t = 0; t < 16; t++) {
            float xv = Xs[t][k];
            a0[t] += xv * w0; a1[t] += xv * w1; a2[t] += xv * w2;
        }
    }
    {
        float b0 = qkv_b[tid], b1 = qkv_b[128 + tid], b2 = qkv_b[256 + tid];
        #pragma unroll
        for (int t = 0; t < 16; t++) {
            QKV[t][tid]       = a0[t] + b0;
            QKV[t][128 + tid] = a1[t] + b1;
            QKV[t][256 + tid] = a2[t] + b2;
        }
    }
    __syncthreads();

    int warp = tid >> 5, lane = tid & 31;
    if (lane < 16) {
        int t = lane, h = warp;
        float q[32];
        #pragma unroll
        for (int d = 0; d < 32; d++) q[d] = QKV[t][h * 32 + d] * 0.17677669529663687f;
        int i1 = t >> 2, j1 = t & 3;
        int rh1 = wh * 4 + i1, rw1 = wc * 4 + j1;
        int l1 = ((rh1 < 252) ? 0 : ((rh1 < 253) ? 1 : 2)) * 3
               + ((rw1 < 252) ? 0 : ((rw1 < 253) ? 1 : 2));
        float s[16];
        float mx = -1e30f;
        #pragma unroll
        for (int u = 0; u < 16; u++) {
            float dot = 0.f;
            #pragma unroll
            for (int d = 0; d < 32; d++) dot += q[d] * QKV[u][128 + h * 32 + d];
            int i2 = u >> 2, j2 = u & 3;
            int ridx = (i1 - i2 + 3) * 7 + (j1 - j2 + 3);
            dot += rpb[ridx * 4 + h];
            int rh2 = wh * 4 + i2, rw2 = wc * 4 + j2;
            int l2 = ((rh2 < 252) ? 0 : ((rh2 < 253) ? 1 : 2)) * 3
                   + ((rw2 < 252) ? 0 : ((rw2 < 253) ? 1 : 2));
            if (l1 != l2) dot -= 100.f;
            s[u] = dot;
            mx = fmaxf(mx, dot);
        }
        float sum = 0.f;
        #pragma unroll
        for (int u = 0; u < 16; u++) { s[u] = __expf(s[u] - mx); sum += s[u]; }
        float inv = 1.f / sum;
        #pragma unroll
        for (int u = 0; u < 16; u++) P[h][t][u] = s[u] * inv;
    }
    __syncwarp();

    {
        int h = warp, d = lane;
        #pragma unroll
        for (int t = 0; t < 16; t++) {
            float acc = 0.f;
            #pragma unroll
            for (int u = 0; u < 16; u++) acc += P[h][t][u] * QKV[u][256 + h * 32 + d];
            O[t][h * 32 + d] = acc;
        }
    }
    __syncthreads();

    float pa[16];
    #pragma unroll
    for (int t = 0; t < 16; t++) pa[t] = 0.f;
    for (int k = 0; k < 128; k++) {
        float wv = proj_w[k * 128 + tid];
        #pragma unroll
        for (int t = 0; t < 16; t++) pa[t] += O[t][k] * wv;
    }
    float pb = proj_b[tid];
    #pragma unroll
    for (int t = 0; t < 16; t++) {
        int hs = wh * 4 + (t >> 2), ws = wc * 4 + (t & 3);
        int h2 = (hs + 3) & 255, w2 = (ws + 3) & 255;
        g_y[((b * 256 + h2) * 256 + w2) * 128 + tid] = pa[t] + pb + Xs[t][tid];
    }
}

// ---------------- K3/K4: 3x3 conv + BN (+relu / +1x1 identity branch) -----------
// NCHW view: N=4, C=256, H=256, W=128.
// Block tile: CO=64, H=4, W=32. Thread micro-tile: 8 co x 4 w, computed as
// 4 co-PAIRS x 4 w with packed fma.rn.f32x2 (FFMA2).
// Weights stored co-pair-interleaved in smem: one LDS.64 loads {w_co, w_co+1},
// warp-uniform (broadcast). Input value broadcast-packed {r,r} once per reuse.
template <int SECOND>
__global__ __launch_bounds__(256, 2) void k_conv(
    const float* __restrict__ cw, const float* __restrict__ cb,
    const float* __restrict__ bg, const float* __restrict__ bb,
    const float* __restrict__ bm, const float* __restrict__ bv,
    const float* __restrict__ iw, const float* __restrict__ ibi,
    const float* __restrict__ ig, const float* __restrict__ ib2,
    const float* __restrict__ im, const float* __restrict__ iv,
    float* __restrict__ out)
{
    __shared__ float in_s[8 * 6 * 35];
    __shared__ unsigned long long wgt2_s[2304];           // [copair(32)][72] pairs
    __shared__ float y_s[SECOND ? 8 * 4 * 33 : 1];
    __shared__ unsigned long long wi2_s[SECOND ? 256 : 1]; // [copair(32)][8] pairs

    const float* in = SECOND ? g_t1 : g_y;

    int tid = threadIdx.x;
    int cog = tid >> 5;            // warp id == co group (uniform per warp)
    int rem = tid & 31;
    int hg  = rem >> 3;            // 0..3
    int wg  = rem & 7;             // 0..7
    int hb  = blockIdx.x >> 2, wb = blockIdx.x & 3;
    int co_b = blockIdx.y, n = blockIdx.z;
    int h0 = hb * 4, w0 = wb * 32;

    unsigned long long acc2[4][4];   // [copair][j] : {co_even, co_odd}
    unsigned long long iacc2[4][4];
    #pragma unroll
    for (int i = 0; i < 4; i++)
        #pragma unroll
        for (int j = 0; j < 4; j++) { acc2[i][j] = 0ull; iacc2[i][j] = 0ull; }

    const float* inbase = in + n * 256 * 256 * 128;
    float* wgt2f = (float*)wgt2_s;
    float* wi2f  = (float*)wi2_s;

    for (int ci0 = 0; ci0 < 256; ci0 += 8) {
        // input patch (with zero padding): 8 ci x 6 h x 34 w, rows padded to 35
        for (int idx = tid; idx < 8 * 6 * 34; idx += 256) {
            int ci = idx / 204; int r = idx - ci * 204;
            int dh = r / 34;    int dw = r - dh * 34;
            int gh = h0 - 1 + dh, gw = w0 - 1 + dw;
            float v = 0.f;
            if ((unsigned)gh < 256u && (unsigned)gw < 128u)
                v = inbase[((ci0 + ci) * 256 + gh) * 128 + gw];
            in_s[ci * 210 + dh * 35 + dw] = v;
        }
        // weights: co-pair interleaved. float view: f[copair*144 + r*2 + half]
        for (int idx = tid; idx < 4608; idx += 256) {
            int copair = idx / 144; int t2 = idx - copair * 144;
            int r = t2 >> 1; int half = t2 & 1;
            wgt2f[idx] = cw[((co_b * 64 + copair * 2 + half) * 256 + ci0) * 9 + r];
        }
        if (SECOND) {
            for (int idx = tid; idx < 1024; idx += 256) {
                int ci = idx >> 7; int r = idx & 127;
                int dh = r >> 5;   int dw = r & 31;
                y_s[ci * 132 + dh * 33 + dw] =
                    g_y[((n * 256 + ci0 + ci) * 256 + h0 + dh) * 128 + w0 + dw];
            }
            // identity weights pair-interleaved: f[copair*16 + ci*2 + half]
            for (int idx = tid; idx < 512; idx += 256) {
                int copair = idx >> 4; int t2 = idx & 15;
                int ci = t2 >> 1; int half = t2 & 1;
                wi2f[idx] = iw[(co_b * 64 + copair * 2 + half) * 256 + ci0 + ci];
            }
        }
        __syncthreads();

        #pragma unroll
        for (int ci = 0; ci < 8; ci++) {
            #pragma unroll
            for (int kh = 0; kh < 3; kh++) {
                unsigned long long rb[6];
                #pragma unroll
                for (int s = 0; s < 6; s++) {
                    float rv = in_s[ci * 210 + (hg + kh) * 35 + wg * 4 + s];
                    rb[s] = pk2(rv, rv);
                }
                #pragma unroll
                for (int kw = 0; kw < 3; kw++) {
                    #pragma unroll
                    for (int cp = 0; cp < 4; cp++) {
                        unsigned long long wp =
                            wgt2_s[(cog * 4 + cp) * 72 + ci * 9 + kh * 3 + kw];
                        #pragma unroll
                        for (int j = 0; j < 4; j++)
                            ffma2(acc2[cp][j], wp, rb[kw + j]);
                    }
                }
            }
            if (SECOND) {
                unsigned long long yb[4];
                #pragma unroll
                for (int j = 0; j < 4; j++) {
                    float yv = y_s[ci * 132 + hg * 33 + wg * 4 + j];
                    yb[j] = pk2(yv, yv);
                }
                #pragma unroll
                for (int cp = 0; cp < 4; cp++) {
                    unsigned long long wp = wi2_s[(cog * 4 + cp) * 8 + ci];
                    #pragma unroll
                    for (int j = 0; j < 4; j++)
                        ffma2(iacc2[cp][j], wp, yb[j]);
                }
            }
        }
        __syncthreads();
    }

    // epilogue: fold BN, (+identity branch), relu
    #pragma unroll
    for (int i = 0; i < 8; i++) {
        int cp = i >> 1, half = i & 1;
        int co = co_b * 64 + cog * 8 + i;
        float s    = bg[co] * rsqrtf(bv[co] + 1e-5f);
        float bias = cb[co] * s + bb[co] - bm[co] * s;
        float vals[4];
        if (SECOND) {
            float si    = ig[co] * rsqrtf(iv[co] + 1e-5f);
            float biasi = ibi[co] * si + ib2[co] - im[co] * si;
            #pragma unroll
            for (int j = 0; j < 4; j++) {
                float2 a = upk(acc2[cp][j]);
                float2 ia = upk(iacc2[cp][j]);
                float av = half ? a.y : a.x;
                float iv2 = half ? ia.y : ia.x;
                vals[j] = fmaxf(av * s + bias + iv2 * si + biasi, 0.f);
            }
        } else {
            #pragma unroll
            for (int j = 0; j < 4; j++) {
                float2 a = upk(acc2[cp][j]);
                float av = half ? a.y : a.x;
                vals[j] = fmaxf(av * s + bias, 0.f);
            }
        }
        int h = h0 + hg, w = w0 + wg * 4;
        float* dstf = SECOND ? out : g_t1;
        float4* dst = (float4*)&dstf[((n * 256 + co) * 256 + h) * 128 + w];
        *dst = make_float4(vals[0], vals[1], vals[2], vals[3]);
    }
}

// ---------------- launcher ------------------------------------------------------
extern "C" void kernel_launch(void* const* d_in, const int* in_sizes, int n_in,
                              void* d_out, int out_size) {
    const float* x      = (const float*)d_in[0];
    const float* qkv_w  = (const float*)d_in[1];
    const float* qkv_b  = (const float*)d_in[2];
    const float* proj_w = (const float*)d_in[3];
    const float* proj_b = (const float*)d_in[4];
    const float* rpb    = (const float*)d_in[5];
    const float* c1w = (const float*)d_in[6];
    const float* c1b = (const float*)d_in[7];
    const float* b1g = (const float*)d_in[8];
    const float* b1b = (const float*)d_in[9];
    const float* b1m = (const float*)d_in[10];
    const float* b1v = (const float*)d_in[11];
    const float* c2w = (const float*)d_in[12];
    const float* c2b = (const float*)d_in[13];
    const float* b2g = (const float*)d_in[14];
    const float* b2b = (const float*)d_in[15];
    const float* b2m = (const float*)d_in[16];
    const float* b2v = (const float*)d_in[17];
    const float* idw = (const float*)d_in[18];
    const float* idb = (const float*)d_in[19];
    const float* big = (const float*)d_in[20];
    const float* bib = (const float*)d_in[21];
    const float* bim = (const float*)d_in[22];
    const float* biv = (const float*)d_in[23];
    float* out = (float*)d_out;

    k_upsample<<<TOT / 256, 256>>>(x);
    k_attn<<<16384, 128>>>(qkv_w, qkv_b, proj_w, proj_b, rpb);

    dim3 grid(256, 4, 4);  // x = h_block*4 + w_block, y = co_block, z = n
    k_conv<0><<<grid, 256>>>(c1w, c1b, b1g, b1b, b1m, b1v,
                             idw, idb, big, bib, bim, biv, out);
    k_conv<1><<<grid, 256>>>(c2w, c2b, b2g, b2b, b2m, b2v,
                             idw, idb, big, bib, bim, biv, out);
}

// round 3
// speedup vs baseline: 1.4619x; 1.2890x over previous
#include <cuda_runtime.h>

// ---------------- scratch (device globals; no dynamic alloc allowed) -------------
#define TOT (4*256*256*128)
static __device__ float g_xu[TOT];   // upsampled x, (B,H,W,C) = (4,256,256,128)
static __device__ float g_y [TOT];   // after attention + residual
static __device__ float g_t1[TOT];   // after conv1+bn1+relu

// ---------------- f32x2 packed-FMA helpers (sm_103a FFMA2) ----------------------
__device__ __forceinline__ unsigned long long pk2(float lo, float hi) {
    unsigned long long r;
    asm("mov.b64 %0, {%1, %2};" : "=l"(r) : "f"(lo), "f"(hi));
    return r;
}
__device__ __forceinline__ void ffma2(unsigned long long& d,
                                      unsigned long long a, unsigned long long b) {
    asm("fma.rn.f32x2 %0, %1, %2, %0;" : "+l"(d) : "l"(a), "l"(b));
}
__device__ __forceinline__ float2 upk(unsigned long long p) {
    float2 f;
    asm("mov.b64 {%0, %1}, %2;" : "=f"(f.x), "=f"(f.y) : "l"(p));
    return f;
}

// ---------------- cp.async helpers ----------------------------------------------
__device__ __forceinline__ void cpa4(float* dst_smem, const float* src, bool valid) {
    unsigned dst = (unsigned)__cvta_generic_to_shared(dst_smem);
    int sz = valid ? 4 : 0;
    asm volatile("cp.async.ca.shared.global [%0], [%1], 4, %2;"
                 :: "r"(dst), "l"(src), "r"(sz));
}
__device__ __forceinline__ void cpa4u(float* dst_smem, const float* src) {
    unsigned dst = (unsigned)__cvta_generic_to_shared(dst_smem);
    asm volatile("cp.async.ca.shared.global [%0], [%1], 4;"
                 :: "r"(dst), "l"(src));
}
__device__ __forceinline__ void cpa_commit() {
    asm volatile("cp.async.commit_group;");
}
template <int N>
__device__ __forceinline__ void cpa_wait() {
    asm volatile("cp.async.wait_group %0;" :: "n"(N));
}

// ---------------- K1: bilinear 2x upsample (align_corners) on dims 2,3 ----------
__global__ void k_upsample(const float* __restrict__ xin) {
    int idx = blockIdx.x * 256 + threadIdx.x;          // 33,554,432 total
    int cc = idx & 127;
    int t  = idx >> 7;
    int ww = t & 255; t >>= 8;
    int hh = t & 255;
    int b  = t >> 8;
    float pw = ww * (127.0f / 255.0f);
    int wlo = (int)pw; float fw = pw - (float)wlo; int whi = min(wlo + 1, 127);
    float pc = cc * (63.0f / 127.0f);
    int clo = (int)pc; float fc = pc - (float)clo; int chi = min(clo + 1, 63);
    const float* base = xin + ((b * 256 + hh) * 128) * 64;
    float v00 = base[wlo * 64 + clo], v01 = base[wlo * 64 + chi];
    float v10 = base[whi * 64 + clo], v11 = base[whi * 64 + chi];
    g_xu[idx] = (1.f - fw) * ((1.f - fc) * v00 + fc * v01)
              +        fw  * ((1.f - fc) * v10 + fc * v11);
}

// ---------------- K2: shifted-window attention, one window per block ------------
__global__ __launch_bounds__(128) void k_attn(
    const float* __restrict__ qkv_w, const float* __restrict__ qkv_b,
    const float* __restrict__ proj_w, const float* __restrict__ proj_b,
    const float* __restrict__ rpb)
{
    __shared__ float Xs[16][128];
    __shared__ float QKV[16][384];
    __shared__ float P[4][16][16];
    __shared__ float O[16][128];

    int tid  = threadIdx.x;
    int blk  = blockIdx.x;              // 16384 = 4 * 64 * 64
    int b    = blk >> 12;
    int widx = blk & 4095;
    int wh   = widx >> 6;
    int wc   = widx & 63;

    #pragma unroll
    for (int t = 0; t < 16; t++) {
        int hs = wh * 4 + (t >> 2), ws = wc * 4 + (t & 3);
        int h2 = (hs + 3) & 255, w2 = (ws + 3) & 255;
        Xs[t][tid] = g_xu[((b * 256 + h2) * 256 + w2) * 128 + tid];
    }
    __syncthreads();

    float a0[16], a1[16], a2[16];
    #pragma unroll
    for (int t = 0; t < 16; t++) { a0[t] = 0.f; a1[t] = 0.f; a2[t] = 0.f; }
    for (int k = 0; k < 128; k++) {
        float w0 = qkv_w[k * 384 + tid];
        float w1 = qkv_w[k * 384 + 128 + tid];
        float w2 = qkv_w[k * 384 + 256 + tid];
        #pragma unroll
        for (int t = 0; t < 16; t++) {
            float xv = Xs[t][k];
            a0[t] += xv * w0; a1[t] += xv * w1; a2[t] += xv * w2;
        }
    }
    {
        float b0 = qkv_b[tid], b1 = qkv_b[128 + tid], b2 = qkv_b[256 + tid];
        #pragma unroll
        for (int t = 0; t < 16; t++) {
            QKV[t][tid]       = a0[t] + b0;
            QKV[t][128 + tid] = a1[t] + b1;
            QKV[t][256 + tid] = a2[t] + b2;
        }
    }
    __syncthreads();

    int warp = tid >> 5, lane = tid & 31;
    if (lane < 16) {
        int t = lane, h = warp;
        float q[32];
        #pragma unroll
        for (int d = 0; d < 32; d++) q[d] = QKV[t][h * 32 + d] * 0.17677669529663687f;
        int i1 = t >> 2, j1 = t & 3;
        int rh1 = wh * 4 + i1, rw1 = wc * 4 + j1;
        int l1 = ((rh1 < 252) ? 0 : ((rh1 < 253) ? 1 : 2)) * 3
               + ((rw1 < 252) ? 0 : ((rw1 < 253) ? 1 : 2));
        float s[16];
        float mx = -1e30f;
        #pragma unroll
        for (int u = 0; u < 16; u++) {
            float dot = 0.f;
            #pragma unroll
            for (int d = 0; d < 32; d++) dot += q[d] * QKV[u][128 + h * 32 + d];
            int i2 = u >> 2, j2 = u & 3;
            int ridx = (i1 - i2 + 3) * 7 + (j1 - j2 + 3);
            dot += rpb[ridx * 4 + h];
            int rh2 = wh * 4 + i2, rw2 = wc * 4 + j2;
            int l2 = ((rh2 < 252) ? 0 : ((rh2 < 253) ? 1 : 2)) * 3
                   + ((rw2 < 252) ? 0 : ((rw2 < 253) ? 1 : 2));
            if (l1 != l2) dot -= 100.f;
            s[u] = dot;
            mx = fmaxf(mx, dot);
        }
        float sum = 0.f;
        #pragma unroll
        for (int u = 0; u < 16; u++) { s[u] = __expf(s[u] - mx); sum += s[u]; }
        float inv = 1.f / sum;
        #pragma unroll
        for (int u = 0; u < 16; u++) P[h][t][u] = s[u] * inv;
    }
    __syncwarp();

    {
        int h = warp, d = lane;
        #pragma unroll
        for (int t = 0; t < 16; t++) {
            float acc = 0.f;
            #pragma unroll
            for (int u = 0; u < 16; u++) acc += P[h][t][u] * QKV[u][256 + h * 32 + d];
            O[t][h * 32 + d] = acc;
        }
    }
    __syncthreads();

    float pa[16];
    #pragma unroll
    for (int t = 0; t < 16; t++) pa[t] = 0.f;
    for (int k = 0; k < 128; k++) {
        float wv = proj_w[k * 128 + tid];
        #pragma unroll
        for (int t = 0; t < 16; t++) pa[t] += O[t][k] * wv;
    }
    float pb = proj_b[tid];
    #pragma unroll
    for (int t = 0; t < 16; t++) {
        int hs = wh * 4 + (t >> 2), ws = wc * 4 + (t & 3);
        int h2 = (hs + 3) & 255, w2 = (ws + 3) & 255;
        g_y[((b * 256 + h2) * 256 + w2) * 128 + tid] = pa[t] + pb + Xs[t][tid];
    }
}

// ---------------- K3/K4: 3x3 conv + BN (+relu / +1x1 identity branch) -----------
// NCHW view: N=4, C=256, H=256, W=128.
// Block tile: CO=64, H=4, W=32. Thread micro-tile: 4 co-pairs x 4 w (FFMA2).
// ci processed in chunks of 4, double-buffered smem, cp.async prefetch pipeline.
template <int SECOND>
__global__ __launch_bounds__(256, 2) void k_conv(
    const float* __restrict__ cw, const float* __restrict__ cb,
    const float* __restrict__ bg, const float* __restrict__ bb,
    const float* __restrict__ bm, const float* __restrict__ bv,
    const float* __restrict__ iw, const float* __restrict__ ibi,
    const float* __restrict__ ig, const float* __restrict__ ib2,
    const float* __restrict__ im, const float* __restrict__ iv,
    float* __restrict__ out)
{
    // per stage: 4 ci. in: 4*6*35 floats; wgt: 32 copair * 36 pairs; y: 4*4*33; wi: 128 pairs
    __shared__ float in_s[2][840];
    __shared__ unsigned long long wgt2_s[2][1152];          // [copair(32)][36]
    __shared__ float y_s[2][SECOND ? 528 : 1];
    __shared__ unsigned long long wi2_s[2][SECOND ? 128 : 1];

    const float* in = SECOND ? g_t1 : g_y;

    int tid = threadIdx.x;
    int cog = tid >> 5;            // warp id == co group (uniform per warp)
    int rem = tid & 31;
    int hg  = rem >> 3;            // 0..3
    int wg  = rem & 7;             // 0..7
    int hb  = blockIdx.x >> 2, wb = blockIdx.x & 3;
    int co_b = blockIdx.y, n = blockIdx.z;
    int h0 = hb * 4, w0 = wb * 32;

    unsigned long long acc2[4][4];   // [copair][j] : {co_even, co_odd}
    unsigned long long iacc2[4][4];
    #pragma unroll
    for (int i = 0; i < 4; i++)
        #pragma unroll
        for (int j = 0; j < 4; j++) { acc2[i][j] = 0ull; iacc2[i][j] = 0ull; }

    const float* inbase = in + n * 256 * 256 * 128;

    // ---- stage loader (cp.async only; no waits) ----
    auto load_stage = [&](int buf, int ci0) {
        // input patch: 4 ci x 6 h x 34 w, rows padded to 35, zero halo
        #pragma unroll
        for (int idx = tid; idx < 816; idx += 256) {
            int ci = idx / 204; int r = idx - ci * 204;
            int dh = r / 34;    int dw = r - dh * 34;
            int gh = h0 - 1 + dh, gw = w0 - 1 + dw;
            bool ok = ((unsigned)gh < 256u) && ((unsigned)gw < 128u);
            const float* src = inbase + (((ci0 + ci) * 256 + (ok ? gh : 0)) * 128 + (ok ? gw : 0));
            cpa4(&in_s[buf][ci * 210 + dh * 35 + dw], src, ok);
        }
        // weights, co-pair interleaved: float off = copair*72 + r*2 + half == idx
        float* wf = (float*)wgt2_s[buf];
        #pragma unroll
        for (int idx = tid; idx < 2304; idx += 256) {
            int copair = idx / 72; int t2 = idx - copair * 72;
            int r = t2 >> 1; int half = t2 & 1;
            cpa4u(&wf[idx], &cw[((co_b * 64 + copair * 2 + half) * 256 + ci0) * 9 + r]);
        }
        if (SECOND) {
            #pragma unroll
            for (int idx = tid; idx < 512; idx += 256) {
                int ci = idx >> 7; int r = idx & 127;
                int dh = r >> 5;   int dw = r & 31;
                cpa4u(&y_s[buf][ci * 132 + dh * 33 + dw],
                      &g_y[((n * 256 + ci0 + ci) * 256 + h0 + dh) * 128 + w0 + dw]);
            }
            float* wif = (float*)wi2_s[buf];
            {
                int idx = tid;
                if (idx < 256) {
                    int copair = idx >> 3; int t2 = idx & 7;
                    int ci = t2 >> 1; int half = t2 & 1;
                    cpa4u(&wif[idx], &iw[(co_b * 64 + copair * 2 + half) * 256 + ci0 + ci]);
                }
            }
        }
    };

    load_stage(0, 0);
    cpa_commit();

    for (int it = 0; it < 64; it++) {
        if (it + 1 < 64) {
            load_stage((it + 1) & 1, (it + 1) * 4);
            cpa_commit();
            cpa_wait<1>();
        } else {
            cpa_wait<0>();
        }
        __syncthreads();

        int buf = it & 1;
        #pragma unroll
        for (int ci = 0; ci < 4; ci++) {
            #pragma unroll
            for (int kh = 0; kh < 3; kh++) {
                unsigned long long rb[6];
                #pragma unroll
                for (int s = 0; s < 6; s++) {
                    float rv = in_s[buf][ci * 210 + (hg + kh) * 35 + wg * 4 + s];
                    rb[s] = pk2(rv, rv);
                }
                #pragma unroll
                for (int kw = 0; kw < 3; kw++) {
                    #pragma unroll
                    for (int cp = 0; cp < 4; cp++) {
                        unsigned long long wp =
                            wgt2_s[buf][(cog * 4 + cp) * 36 + ci * 9 + kh * 3 + kw];
                        #pragma unroll
                        for (int j = 0; j < 4; j++)
                            ffma2(acc2[cp][j], wp, rb[kw + j]);
                    }
                }
            }
            if (SECOND) {
                unsigned long long yb[4];
                #pragma unroll
                for (int j = 0; j < 4; j++) {
                    float yv = y_s[buf][ci * 132 + hg * 33 + wg * 4 + j];
                    yb[j] = pk2(yv, yv);
                }
                #pragma unroll
                for (int cp = 0; cp < 4; cp++) {
                    unsigned long long wp = wi2_s[buf][(cog * 4 + cp) * 4 + ci];
                    #pragma unroll
                    for (int j = 0; j < 4; j++)
                        ffma2(iacc2[cp][j], wp, yb[j]);
                }
            }
        }
        __syncthreads();
    }

    // epilogue: fold BN, (+identity branch), relu
    #pragma unroll
    for (int i = 0; i < 8; i++) {
        int cp = i >> 1, half = i & 1;
        int co = co_b * 64 + cog * 8 + i;
        float s    = bg[co] * rsqrtf(bv[co] + 1e-5f);
        float bias = cb[co] * s + bb[co] - bm[co] * s;
        float vals[4];
        if (SECOND) {
            float si    = ig[co] * rsqrtf(iv[co] + 1e-5f);
            float biasi = ibi[co] * si + ib2[co] - im[co] * si;
            #pragma unroll
            for (int j = 0; j < 4; j++) {
                float2 a = upk(acc2[cp][j]);
                float2 ia = upk(iacc2[cp][j]);
                float av = half ? a.y : a.x;
                float iv2 = half ? ia.y : ia.x;
                vals[j] = fmaxf(av * s + bias + iv2 * si + biasi, 0.f);
            }
        } else {
            #pragma unroll
            for (int j = 0; j < 4; j++) {
                float2 a = upk(acc2[cp][j]);
                float av = half ? a.y : a.x;
                vals[j] = fmaxf(av * s + bias, 0.f);
            }
        }
        int h = h0 + hg, w = w0 + wg * 4;
        float* dstf = SECOND ? out : g_t1;
        float4* dst = (float4*)&dstf[((n * 256 + co) * 256 + h) * 128 + w];
        *dst = make_float4(vals[0], vals[1], vals[2], vals[3]);
    }
}

// ---------------- launcher ------------------------------------------------------
extern "C" void kernel_launch(void* const* d_in, const int* in_sizes, int n_in,
                              void* d_out, int out_size) {
    const float* x      = (const float*)d_in[0];
    const float* qkv_w  = (const float*)d_in[1];
    const float* qkv_b  = (const float*)d_in[2];
    const float* proj_w = (const float*)d_in[3];
    const float* proj_b = (const float*)d_in[4];
    const float* rpb    = (const float*)d_in[5];
    const float* c1w = (const float*)d_in[6];
    const float* c1b = (const float*)d_in[7];
    const float* b1g = (const float*)d_in[8];
    const float* b1b = (const float*)d_in[9];
    const float* b1m = (const float*)d_in[10];
    const float* b1v = (const float*)d_in[11];
    const float* c2w = (const float*)d_in[12];
    const float* c2b = (const float*)d_in[13];
    const float* b2g = (const float*)d_in[14];
    const float* b2b = (const float*)d_in[15];
    const float* b2m = (const float*)d_in[16];
    const float* b2v = (const float*)d_in[17];
    const float* idw = (const float*)d_in[18];
    const float* idb = (const float*)d_in[19];
    const float* big = (const float*)d_in[20];
    const float* bib = (const float*)d_in[21];
    const float* bim = (const float*)d_in[22];
    const float* biv = (const float*)d_in[23];
    float* out = (float*)d_out;

    k_upsample<<<TOT / 256, 256>>>(x);
    k_attn<<<16384, 128>>>(qkv_w, qkv_b, proj_w, proj_b, rpb);

    dim3 grid(256, 4, 4);  // x = h_block*4 + w_block, y = co_block, z = n
    k_conv<0><<<grid, 256>>>(c1w, c1b, b1g, b1b, b1m, b1v,
                             idw, idb, big, bib, bim, biv, out);
    k_conv<1><<<grid, 256>>>(c2w, c2b, b2g, b2b, b2m, b2v,
                             idw, idb, big, bib, bim, biv, out);
}

// round 4
// speedup vs baseline: 1.4652x; 1.0023x over previous
#include <cuda_runtime.h>

// ---------------- scratch (device globals; no dynamic alloc allowed) -------------
#define TOT (4*256*256*128)
static __device__ float g_xu[TOT];   // upsampled x, (B,H,W,C) = (4,256,256,128)
static __device__ float g_y [TOT];   // after attention + residual
static __device__ float g_t1[TOT];   // after conv1+bn1+relu

// ---------------- f32x2 packed-FMA helpers (sm_103a FFMA2) ----------------------
__device__ __forceinline__ unsigned long long pk2(float lo, float hi) {
    unsigned long long r;
    asm("mov.b64 %0, {%1, %2};" : "=l"(r) : "f"(lo), "f"(hi));
    return r;
}
__device__ __forceinline__ void ffma2(unsigned long long& d,
                                      unsigned long long a, unsigned long long b) {
    asm("fma.rn.f32x2 %0, %1, %2, %0;" : "+l"(d) : "l"(a), "l"(b));
}
__device__ __forceinline__ float2 upk(unsigned long long p) {
    float2 f;
    asm("mov.b64 {%0, %1}, %2;" : "=f"(f.x), "=f"(f.y) : "l"(p));
    return f;
}

// ---------------- cp.async helpers ----------------------------------------------
__device__ __forceinline__ void cpa4(float* dst_smem, const float* src, bool valid) {
    unsigned dst = (unsigned)__cvta_generic_to_shared(dst_smem);
    int sz = valid ? 4 : 0;
    asm volatile("cp.async.ca.shared.global [%0], [%1], 4, %2;"
                 :: "r"(dst), "l"(src), "r"(sz));
}
__device__ __forceinline__ void cpa4u(float* dst_smem, const float* src) {
    unsigned dst = (unsigned)__cvta_generic_to_shared(dst_smem);
    asm volatile("cp.async.ca.shared.global [%0], [%1], 4;"
                 :: "r"(dst), "l"(src));
}
__device__ __forceinline__ void cpa_commit() {
    asm volatile("cp.async.commit_group;");
}
template <int N>
__device__ __forceinline__ void cpa_wait() {
    asm volatile("cp.async.wait_group %0;" :: "n"(N));
}

// ---------------- K1: bilinear 2x upsample (align_corners) on dims 2,3 ----------
__global__ void k_upsample(const float* __restrict__ xin) {
    int idx = blockIdx.x * 256 + threadIdx.x;          // 33,554,432 total
    int cc = idx & 127;
    int t  = idx >> 7;
    int ww = t & 255; t >>= 8;
    int hh = t & 255;
    int b  = t >> 8;
    float pw = ww * (127.0f / 255.0f);
    int wlo = (int)pw; float fw = pw - (float)wlo; int whi = min(wlo + 1, 127);
    float pc = cc * (63.0f / 127.0f);
    int clo = (int)pc; float fc = pc - (float)clo; int chi = min(clo + 1, 63);
    const float* base = xin + ((b * 256 + hh) * 128) * 64;
    float v00 = base[wlo * 64 + clo], v01 = base[wlo * 64 + chi];
    float v10 = base[whi * 64 + clo], v11 = base[whi * 64 + chi];
    g_xu[idx] = (1.f - fw) * ((1.f - fc) * v00 + fc * v01)
              +        fw  * ((1.f - fc) * v10 + fc * v11);
}

// ---------------- K2: shifted-window attention, one window per block ------------
__global__ __launch_bounds__(128) void k_attn(
    const float* __restrict__ qkv_w, const float* __restrict__ qkv_b,
    const float* __restrict__ proj_w, const float* __restrict__ proj_b,
    const float* __restrict__ rpb)
{
    __shared__ float Xs[16][128];
    __shared__ float QKV[16][384];
    __shared__ float P[4][16][16];
    __shared__ float O[16][128];

    int tid  = threadIdx.x;
    int blk  = blockIdx.x;              // 16384 = 4 * 64 * 64
    int b    = blk >> 12;
    int widx = blk & 4095;
    int wh   = widx >> 6;
    int wc   = widx & 63;

    #pragma unroll
    for (int t = 0; t < 16; t++) {
        int hs = wh * 4 + (t >> 2), ws = wc * 4 + (t & 3);
        int h2 = (hs + 3) & 255, w2 = (ws + 3) & 255;
        Xs[t][tid] = g_xu[((b * 256 + h2) * 256 + w2) * 128 + tid];
    }
    __syncthreads();

    float a0[16], a1[16], a2[16];
    #pragma unroll
    for (int t = 0; t < 16; t++) { a0[t] = 0.f; a1[t] = 0.f; a2[t] = 0.f; }
    for (int k = 0; k < 128; k++) {
        float w0 = qkv_w[k * 384 + tid];
        float w1 = qkv_w[k * 384 + 128 + tid];
        float w2 = qkv_w[k * 384 + 256 + tid];
        #pragma unroll
        for (int t = 0; t < 16; t++) {
            float xv = Xs[t][k];
            a0[t] += xv * w0; a1[t] += xv * w1; a2[t] += xv * w2;
        }
    }
    {
        float b0 = qkv_b[tid], b1 = qkv_b[128 + tid], b2 = qkv_b[256 + tid];
        #pragma unroll
        for (int t = 0; t < 16; t++) {
            QKV[t][tid]       = a0[t] + b0;
            QKV[t][128 + tid] = a1[t] + b1;
            QKV[t][256 + tid] = a2[t] + b2;
        }
    }
    __syncthreads();

    int warp = tid >> 5, lane = tid & 31;
    if (lane < 16) {
        int t = lane, h = warp;
        float q[32];
        #pragma unroll
        for (int d = 0; d < 32; d++) q[d] = QKV[t][h * 32 + d] * 0.17677669529663687f;
        int i1 = t >> 2, j1 = t & 3;
        int rh1 = wh * 4 + i1, rw1 = wc * 4 + j1;
        int l1 = ((rh1 < 252) ? 0 : ((rh1 < 253) ? 1 : 2)) * 3
               + ((rw1 < 252) ? 0 : ((rw1 < 253) ? 1 : 2));
        float s[16];
        float mx = -1e30f;
        #pragma unroll
        for (int u = 0; u < 16; u++) {
            float dot = 0.f;
            #pragma unroll
            for (int d = 0; d < 32; d++) dot += q[d] * QKV[u][128 + h * 32 + d];
            int i2 = u >> 2, j2 = u & 3;
            int ridx = (i1 - i2 + 3) * 7 + (j1 - j2 + 3);
            dot += rpb[ridx * 4 + h];
            int rh2 = wh * 4 + i2, rw2 = wc * 4 + j2;
            int l2 = ((rh2 < 252) ? 0 : ((rh2 < 253) ? 1 : 2)) * 3
                   + ((rw2 < 252) ? 0 : ((rw2 < 253) ? 1 : 2));
            if (l1 != l2) dot -= 100.f;
            s[u] = dot;
            mx = fmaxf(mx, dot);
        }
        float sum = 0.f;
        #pragma unroll
        for (int u = 0; u < 16; u++) { s[u] = __expf(s[u] - mx); sum += s[u]; }
        float inv = 1.f / sum;
        #pragma unroll
        for (int u = 0; u < 16; u++) P[h][t][u] = s[u] * inv;
    }
    __syncwarp();

    {
        int h = warp, d = lane;
        #pragma unroll
        for (int t = 0; t < 16; t++) {
            float acc = 0.f;
            #pragma unroll
            for (int u = 0; u < 16; u++) acc += P[h][t][u] * QKV[u][256 + h * 32 + d];
            O[t][h * 32 + d] = acc;
        }
    }
    __syncthreads();

    float pa[16];
    #pragma unroll
    for (int t = 0; t < 16; t++) pa[t] = 0.f;
    for (int k = 0; k < 128; k++) {
        float wv = proj_w[k * 128 + tid];
        #pragma unroll
        for (int t = 0; t < 16; t++) pa[t] += O[t][k] * wv;
    }
    float pb = proj_b[tid];
    #pragma unroll
    for (int t = 0; t < 16; t++) {
        int hs = wh * 4 + (t >> 2), ws = wc * 4 + (t & 3);
        int h2 = (hs + 3) & 255, w2 = (ws + 3) & 255;
        g_y[((b * 256 + h2) * 256 + w2) * 128 + tid] = pa[t] + pb + Xs[t][tid];
    }
}

// ---------------- K3/K4: 3x3 conv + BN (+relu / +1x1 identity branch) -----------
// NCHW view: N=4, C=256, H=256, W=128.
// Block tile: CO=64, H=4, W=32. Thread micro-tile: 4 co-pairs x 4 w (FFMA2).
// ci processed in chunks of 4, double-buffered smem, cp.async prefetch pipeline.
template <int SECOND>
__global__ __launch_bounds__(256, 2) void k_conv(
    const float* __restrict__ cw, const float* __restrict__ cb,
    const float* __restrict__ bg, const float* __restrict__ bb,
    const float* __restrict__ bm, const float* __restrict__ bv,
    const float* __restrict__ iw, const float* __restrict__ ibi,
    const float* __restrict__ ig, const float* __restrict__ ib2,
    const float* __restrict__ im, const float* __restrict__ iv,
    float* __restrict__ out)
{
    // per stage: 4 ci. in: 4*6*35 floats; wgt: 32 copair * 36 pairs; y: 4*4*33; wi: 128 pairs
    __shared__ float in_s[2][840];
    __shared__ unsigned long long wgt2_s[2][1152];          // [copair(32)][36]
    __shared__ float y_s[2][SECOND ? 528 : 1];
    __shared__ unsigned long long wi2_s[2][SECOND ? 128 : 1];

    const float* in = SECOND ? g_t1 : g_y;

    int tid = threadIdx.x;
    int cog = tid >> 5;            // warp id == co group (uniform per warp)
    int rem = tid & 31;
    int hg  = rem >> 3;            // 0..3
    int wg  = rem & 7;             // 0..7
    int hb  = blockIdx.x >> 2, wb = blockIdx.x & 3;
    int co_b = blockIdx.y, n = blockIdx.z;
    int h0 = hb * 4, w0 = wb * 32;

    unsigned long long acc2[4][4];   // [copair][j] : {co_even, co_odd}
    unsigned long long iacc2[4][4];
    #pragma unroll
    for (int i = 0; i < 4; i++)
        #pragma unroll
        for (int j = 0; j < 4; j++) { acc2[i][j] = 0ull; iacc2[i][j] = 0ull; }

    const float* inbase = in + n * 256 * 256 * 128;

    // ---- stage loader (cp.async only; no waits) ----
    auto load_stage = [&](int buf, int ci0) {
        // input patch: 4 ci x 6 h x 34 w, rows padded to 35, zero halo
        #pragma unroll
        for (int idx = tid; idx < 816; idx += 256) {
            int ci = idx / 204; int r = idx - ci * 204;
            int dh = r / 34;    int dw = r - dh * 34;
            int gh = h0 - 1 + dh, gw = w0 - 1 + dw;
            bool ok = ((unsigned)gh < 256u) && ((unsigned)gw < 128u);
            const float* src = inbase + (((ci0 + ci) * 256 + (ok ? gh : 0)) * 128 + (ok ? gw : 0));
            cpa4(&in_s[buf][ci * 210 + dh * 35 + dw], src, ok);
        }
        // weights, co-pair interleaved: float off = copair*72 + r*2 + half == idx
        float* wf = (float*)wgt2_s[buf];
        #pragma unroll
        for (int idx = tid; idx < 2304; idx += 256) {
            int copair = idx / 72; int t2 = idx - copair * 72;
            int r = t2 >> 1; int half = t2 & 1;
            cpa4u(&wf[idx], &cw[((co_b * 64 + copair * 2 + half) * 256 + ci0) * 9 + r]);
        }
        if (SECOND) {
            #pragma unroll
            for (int idx = tid; idx < 512; idx += 256) {
                int ci = idx >> 7; int r = idx & 127;
                int dh = r >> 5;   int dw = r & 31;
                cpa4u(&y_s[buf][ci * 132 + dh * 33 + dw],
                      &g_y[((n * 256 + ci0 + ci) * 256 + h0 + dh) * 128 + w0 + dw]);
            }
            float* wif = (float*)wi2_s[buf];
            {
                int idx = tid;
                if (idx < 256) {
                    int copair = idx >> 3; int t2 = idx & 7;
                    int ci = t2 >> 1; int half = t2 & 1;
                    cpa4u(&wif[idx], &iw[(co_b * 64 + copair * 2 + half) * 256 + ci0 + ci]);
                }
            }
        }
    };

    load_stage(0, 0);
    cpa_commit();

    for (int it = 0; it < 64; it++) {
        if (it + 1 < 64) {
            load_stage((it + 1) & 1, (it + 1) * 4);
            cpa_commit();
            cpa_wait<1>();
        } else {
            cpa_wait<0>();
        }
        __syncthreads();

        int buf = it & 1;
        #pragma unroll
        for (int ci = 0; ci < 4; ci++) {
            #pragma unroll
            for (int kh = 0; kh < 3; kh++) {
                unsigned long long rb[6];
                #pragma unroll
                for (int s = 0; s < 6; s++) {
                    float rv = in_s[buf][ci * 210 + (hg + kh) * 35 + wg * 4 + s];
                    rb[s] = pk2(rv, rv);
                }
                #pragma unroll
                for (int kw = 0; kw < 3; kw++) {
                    #pragma unroll
                    for (int cp = 0; cp < 4; cp++) {
                        unsigned long long wp =
                            wgt2_s[buf][(cog * 4 + cp) * 36 + ci * 9 + kh * 3 + kw];
                        #pragma unroll
                        for (int j = 0; j < 4; j++)
                            ffma2(acc2[cp][j], wp, rb[kw + j]);
                    }
                }
            }
            if (SECOND) {
                unsigned long long yb[4];
                #pragma unroll
                for (int j = 0; j < 4; j++) {
                    float yv = y_s[buf][ci * 132 + hg * 33 + wg * 4 + j];
                    yb[j] = pk2(yv, yv);
                }
                #pragma unroll
                for (int cp = 0; cp < 4; cp++) {
                    unsigned long long wp = wi2_s[buf][(cog * 4 + cp) * 4 + ci];
                    #pragma unroll
                    for (int j = 0; j < 4; j++)
                        ffma2(iacc2[cp][j], wp, yb[j]);
                }
            }
        }
        __syncthreads();
    }

    // epilogue: fold BN, (+identity branch), relu
    #pragma unroll
    for (int i = 0; i < 8; i++) {
        int cp = i >> 1, half = i & 1;
        int co = co_b * 64 + cog * 8 + i;
        float s    = bg[co] * rsqrtf(bv[co] + 1e-5f);
        float bias = cb[co] * s + bb[co] - bm[co] * s;
        float vals[4];
        if (SECOND) {
            float si    = ig[co] * rsqrtf(iv[co] + 1e-5f);
            float biasi = ibi[co] * si + ib2[co] - im[co] * si;
            #pragma unroll
            for (int j = 0; j < 4; j++) {
                float2 a = upk(acc2[cp][j]);
                float2 ia = upk(iacc2[cp][j]);
                float av = half ? a.y : a.x;
                float iv2 = half ? ia.y : ia.x;
                vals[j] = fmaxf(av * s + bias + iv2 * si + biasi, 0.f);
            }
        } else {
            #pragma unroll
            for (int j = 0; j < 4; j++) {
                float2 a = upk(acc2[cp][j]);
                float av = half ? a.y : a.x;
                vals[j] = fmaxf(av * s + bias, 0.f);
            }
        }
        int h = h0 + hg, w = w0 + wg * 4;
        float* dstf = SECOND ? out : g_t1;
        float4* dst = (float4*)&dstf[((n * 256 + co) * 256 + h) * 128 + w];
        *dst = make_float4(vals[0], vals[1], vals[2], vals[3]);
    }
}

// ---------------- launcher ------------------------------------------------------
extern "C" void kernel_launch(void* const* d_in, const int* in_sizes, int n_in,
                              void* d_out, int out_size) {
    const float* x      = (const float*)d_in[0];
    const float* qkv_w  = (const float*)d_in[1];
    const float* qkv_b  = (const float*)d_in[2];
    const float* proj_w = (const float*)d_in[3];
    const float* proj_b = (const float*)d_in[4];
    const float* rpb    = (const float*)d_in[5];
    const float* c1w = (const float*)d_in[6];
    const float* c1b = (const float*)d_in[7];
    const float* b1g = (const float*)d_in[8];
    const float* b1b = (const float*)d_in[9];
    const float* b1m = (const float*)d_in[10];
    const float* b1v = (const float*)d_in[11];
    const float* c2w = (const float*)d_in[12];
    const float* c2b = (const float*)d_in[13];
    const float* b2g = (const float*)d_in[14];
    const float* b2b = (const float*)d_in[15];
    const float* b2m = (const float*)d_in[16];
    const float* b2v = (const float*)d_in[17];
    const float* idw = (const float*)d_in[18];
    const float* idb = (const float*)d_in[19];
    const float* big = (const float*)d_in[20];
    const float* bib = (const float*)d_in[21];
    const float* bim = (const float*)d_in[22];
    const float* biv = (const float*)d_in[23];
    float* out = (float*)d_out;

    k_upsample<<<TOT / 256, 256>>>(x);
    k_attn<<<16384, 128>>>(qkv_w, qkv_b, proj_w, proj_b, rpb);

    dim3 grid(256, 4, 4);  // x = h_block*4 + w_block, y = co_block, z = n
    k_conv<0><<<grid, 256>>>(c1w, c1b, b1g, b1b, b1m, b1v,
                             idw, idb, big, bib, bim, biv, out);
    k_conv<1><<<grid, 256>>>(c2w, c2b, b2g, b2b, b2m, b2v,
                             idw, idb, big, bib, bim, biv, out);
}

// round 5
// speedup vs baseline: 1.4659x; 1.0005x over previous
#include <cuda_runtime.h>

// ---------------- scratch (device globals; no dynamic alloc allowed) -------------
#define TOT (4*256*256*128)
static __device__ float g_xu[TOT];   // upsampled x, (B,H,W,C) = (4,256,256,128)
static __device__ float g_y [TOT];   // after attention + residual
static __device__ float g_t1[TOT];   // after conv1+bn1+relu

// ---------------- f32x2 packed-FMA helpers (sm_103a FFMA2) ----------------------
__device__ __forceinline__ unsigned long long pk2(float lo, float hi) {
    unsigned long long r;
    asm("mov.b64 %0, {%1, %2};" : "=l"(r) : "f"(lo), "f"(hi));
    return r;
}
__device__ __forceinline__ void ffma2(unsigned long long& d,
                                      unsigned long long a, unsigned long long b) {
    asm("fma.rn.f32x2 %0, %1, %2, %0;" : "+l"(d) : "l"(a), "l"(b));
}
__device__ __forceinline__ float2 upk(unsigned long long p) {
    float2 f;
    asm("mov.b64 {%0, %1}, %2;" : "=f"(f.x), "=f"(f.y) : "l"(p));
    return f;
}

// ---------------- cp.async helpers ----------------------------------------------
__device__ __forceinline__ void cpa4(float* dst_smem, const float* src, bool valid) {
    unsigned dst = (unsigned)__cvta_generic_to_shared(dst_smem);
    int sz = valid ? 4 : 0;
    asm volatile("cp.async.ca.shared.global [%0], [%1], 4, %2;"
                 :: "r"(dst), "l"(src), "r"(sz));
}
__device__ __forceinline__ void cpa4u(float* dst_smem, const float* src) {
    unsigned dst = (unsigned)__cvta_generic_to_shared(dst_smem);
    asm volatile("cp.async.ca.shared.global [%0], [%1], 4;"
                 :: "r"(dst), "l"(src));
}
__device__ __forceinline__ void cpa_commit() {
    asm volatile("cp.async.commit_group;");
}
template <int N>
__device__ __forceinline__ void cpa_wait() {
    asm volatile("cp.async.wait_group %0;" :: "n"(N));
}

// ---------------- K1: bilinear 2x upsample (align_corners) on dims 2,3 ----------
__global__ void k_upsample(const float* __restrict__ xin) {
    int idx = blockIdx.x * 256 + threadIdx.x;          // 33,554,432 total
    int cc = idx & 127;
    int t  = idx >> 7;
    int ww = t & 255; t >>= 8;
    int hh = t & 255;
    int b  = t >> 8;
    float pw = ww * (127.0f / 255.0f);
    int wlo = (int)pw; float fw = pw - (float)wlo; int whi = min(wlo + 1, 127);
    float pc = cc * (63.0f / 127.0f);
    int clo = (int)pc; float fc = pc - (float)clo; int chi = min(clo + 1, 63);
    const float* base = xin + ((b * 256 + hh) * 128) * 64;
    float v00 = base[wlo * 64 + clo], v01 = base[wlo * 64 + chi];
    float v10 = base[whi * 64 + clo], v11 = base[whi * 64 + chi];
    g_xu[idx] = (1.f - fw) * ((1.f - fc) * v00 + fc * v01)
              +        fw  * ((1.f - fc) * v10 + fc * v11);
}

// ---------------- K2: shifted-window attention, one window per block ------------
__global__ __launch_bounds__(128) void k_attn(
    const float* __restrict__ qkv_w, const float* __restrict__ qkv_b,
    const float* __restrict__ proj_w, const float* __restrict__ proj_b,
    const float* __restrict__ rpb)
{
    __shared__ float Xs[16][128];
    __shared__ float QKV[16][384];
    __shared__ float P[4][16][16];
    __shared__ float O[16][128];

    int tid  = threadIdx.x;
    int blk  = blockIdx.x;              // 16384 = 4 * 64 * 64
    int b    = blk >> 12;
    int widx = blk & 4095;
    int wh   = widx >> 6;
    int wc   = widx & 63;

    #pragma unroll
    for (int t = 0; t < 16; t++) {
        int hs = wh * 4 + (t >> 2), ws = wc * 4 + (t & 3);
        int h2 = (hs + 3) & 255, w2 = (ws + 3) & 255;
        Xs[t][tid] = g_xu[((b * 256 + h2) * 256 + w2) * 128 + tid];
    }
    __syncthreads();

    float a0[16], a1[16], a2[16];
    #pragma unroll
    for (int t = 0; t < 16; t++) { a0[t] = 0.f; a1[t] = 0.f; a2[t] = 0.f; }
    for (int k = 0; k < 128; k++) {
        float w0 = qkv_w[k * 384 + tid];
        float w1 = qkv_w[k * 384 + 128 + tid];
        float w2 = qkv_w[k * 384 + 256 + tid];
        #pragma unroll
        for (int t = 0; t < 16; t++) {
            float xv = Xs[t][k];
            a0[t] += xv * w0; a1[t] += xv * w1; a2[t] += xv * w2;
        }
    }
    {
        float b0 = qkv_b[tid], b1 = qkv_b[128 + tid], b2 = qkv_b[256 + tid];
        #pragma unroll
        for (int t = 0; t < 16; t++) {
            QKV[t][tid]       = a0[t] + b0;
            QKV[t][128 + tid] = a1[t] + b1;
            QKV[t][256 + tid] = a2[t] + b2;
        }
    }
    __syncthreads();

    int warp = tid >> 5, lane = tid & 31;
    if (lane < 16) {
        int t = lane, h = warp;
        float q[32];
        #pragma unroll
        for (int d = 0; d < 32; d++) q[d] = QKV[t][h * 32 + d] * 0.17677669529663687f;
        int i1 = t >> 2, j1 = t & 3;
        int rh1 = wh * 4 + i1, rw1 = wc * 4 + j1;
        int l1 = ((rh1 < 252) ? 0 : ((rh1 < 253) ? 1 : 2)) * 3
               + ((rw1 < 252) ? 0 : ((rw1 < 253) ? 1 : 2));
        float s[16];
        float mx = -1e30f;
        #pragma unroll
        for (int u = 0; u < 16; u++) {
            float dot = 0.f;
            #pragma unroll
            for (int d = 0; d < 32; d++) dot += q[d] * QKV[u][128 + h * 32 + d];
            int i2 = u >> 2, j2 = u & 3;
            int ridx = (i1 - i2 + 3) * 7 + (j1 - j2 + 3);
            dot += rpb[ridx * 4 + h];
            int rh2 = wh * 4 + i2, rw2 = wc * 4 + j2;
            int l2 = ((rh2 < 252) ? 0 : ((rh2 < 253) ? 1 : 2)) * 3
                   + ((rw2 < 252) ? 0 : ((rw2 < 253) ? 1 : 2));
            if (l1 != l2) dot -= 100.f;
            s[u] = dot;
            mx = fmaxf(mx, dot);
        }
        float sum = 0.f;
        #pragma unroll
        for (int u = 0; u < 16; u++) { s[u] = __expf(s[u] - mx); sum += s[u]; }
        float inv = 1.f / sum;
        #pragma unroll
        for (int u = 0; u < 16; u++) P[h][t][u] = s[u] * inv;
    }
    __syncwarp();

    {
        int h = warp, d = lane;
        #pragma unroll
        for (int t = 0; t < 16; t++) {
            float acc = 0.f;
            #pragma unroll
            for (int u = 0; u < 16; u++) acc += P[h][t][u] * QKV[u][256 + h * 32 + d];
            O[t][h * 32 + d] = acc;
        }
    }
    __syncthreads();

    float pa[16];
    #pragma unroll
    for (int t = 0; t < 16; t++) pa[t] = 0.f;
    for (int k = 0; k < 128; k++) {
        float wv = proj_w[k * 128 + tid];
        #pragma unroll
        for (int t = 0; t < 16; t++) pa[t] += O[t][k] * wv;
    }
    float pb = proj_b[tid];
    #pragma unroll
    for (int t = 0; t < 16; t++) {
        int hs = wh * 4 + (t >> 2), ws = wc * 4 + (t & 3);
        int h2 = (hs + 3) & 255, w2 = (ws + 3) & 255;
        g_y[((b * 256 + h2) * 256 + w2) * 128 + tid] = pa[t] + pb + Xs[t][tid];
    }
}

// ---------------- K3/K4: 3x3 conv + BN (+relu / +1x1 identity branch) -----------
// NCHW view: N=4, C=256, H=256, W=128.
// Block tile: CO=64, H=4, W=32. Thread micro-tile: 4 co-pairs x 4 w (FFMA2).
// ci processed in chunks of 4, double-buffered smem, cp.async prefetch pipeline.
template <int SECOND>
__global__ __launch_bounds__(256, 2) void k_conv(
    const float* __restrict__ cw, const float* __restrict__ cb,
    const float* __restrict__ bg, const float* __restrict__ bb,
    const float* __restrict__ bm, const float* __restrict__ bv,
    const float* __restrict__ iw, const float* __restrict__ ibi,
    const float* __restrict__ ig, const float* __restrict__ ib2,
    const float* __restrict__ im, const float* __restrict__ iv,
    float* __restrict__ out)
{
    // per stage: 4 ci. in: 4*6*35 floats; wgt: 32 copair * 36 pairs; y: 4*4*33; wi: 128 pairs
    __shared__ float in_s[2][840];
    __shared__ unsigned long long wgt2_s[2][1152];          // [copair(32)][36]
    __shared__ float y_s[2][SECOND ? 528 : 1];
    __shared__ unsigned long long wi2_s[2][SECOND ? 128 : 1];

    const float* in = SECOND ? g_t1 : g_y;

    int tid = threadIdx.x;
    int cog = tid >> 5;            // warp id == co group (uniform per warp)
    int rem = tid & 31;
    int hg  = rem >> 3;            // 0..3
    int wg  = rem & 7;             // 0..7
    int hb  = blockIdx.x >> 2, wb = blockIdx.x & 3;
    int co_b = blockIdx.y, n = blockIdx.z;
    int h0 = hb * 4, w0 = wb * 32;

    unsigned long long acc2[4][4];   // [copair][j] : {co_even, co_odd}
    unsigned long long iacc2[4][4];
    #pragma unroll
    for (int i = 0; i < 4; i++)
        #pragma unroll
        for (int j = 0; j < 4; j++) { acc2[i][j] = 0ull; iacc2[i][j] = 0ull; }

    const float* inbase = in + n * 256 * 256 * 128;

    // ---- stage loader (cp.async only; no waits) ----
    auto load_stage = [&](int buf, int ci0) {
        // input patch: 4 ci x 6 h x 34 w, rows padded to 35, zero halo
        #pragma unroll
        for (int idx = tid; idx < 816; idx += 256) {
            int ci = idx / 204; int r = idx - ci * 204;
            int dh = r / 34;    int dw = r - dh * 34;
            int gh = h0 - 1 + dh, gw = w0 - 1 + dw;
            bool ok = ((unsigned)gh < 256u) && ((unsigned)gw < 128u);
            const float* src = inbase + (((ci0 + ci) * 256 + (ok ? gh : 0)) * 128 + (ok ? gw : 0));
            cpa4(&in_s[buf][ci * 210 + dh * 35 + dw], src, ok);
        }
        // weights, co-pair interleaved: float off = copair*72 + r*2 + half == idx
        float* wf = (float*)wgt2_s[buf];
        #pragma unroll
        for (int idx = tid; idx < 2304; idx += 256) {
            int copair = idx / 72; int t2 = idx - copair * 72;
            int r = t2 >> 1; int half = t2 & 1;
            cpa4u(&wf[idx], &cw[((co_b * 64 + copair * 2 + half) * 256 + ci0) * 9 + r]);
        }
        if (SECOND) {
            #pragma unroll
            for (int idx = tid; idx < 512; idx += 256) {
                int ci = idx >> 7; int r = idx & 127;
                int dh = r >> 5;   int dw = r & 31;
                cpa4u(&y_s[buf][ci * 132 + dh * 33 + dw],
                      &g_y[((n * 256 + ci0 + ci) * 256 + h0 + dh) * 128 + w0 + dw]);
            }
            float* wif = (float*)wi2_s[buf];
            {
                int idx = tid;
                if (idx < 256) {
                    int copair = idx >> 3; int t2 = idx & 7;
                    int ci = t2 >> 1; int half = t2 & 1;
                    cpa4u(&wif[idx], &iw[(co_b * 64 + copair * 2 + half) * 256 + ci0 + ci]);
                }
            }
        }
    };

    load_stage(0, 0);
    cpa_commit();

    for (int it = 0; it < 64; it++) {
        if (it + 1 < 64) {
            load_stage((it + 1) & 1, (it + 1) * 4);
            cpa_commit();
            cpa_wait<1>();
        } else {
            cpa_wait<0>();
        }
        __syncthreads();

        int buf = it & 1;
        #pragma unroll
        for (int ci = 0; ci < 4; ci++) {
            #pragma unroll
            for (int kh = 0; kh < 3; kh++) {
                unsigned long long rb[6];
                #pragma unroll
                for (int s = 0; s < 6; s++) {
                    float rv = in_s[buf][ci * 210 + (hg + kh) * 35 + wg * 4 + s];
                    rb[s] = pk2(rv, rv);
                }
                #pragma unroll
                for (int kw = 0; kw < 3; kw++) {
                    #pragma unroll
                    for (int cp = 0; cp < 4; cp++) {
                        unsigned long long wp =
                            wgt2_s[buf][(cog * 4 + cp) * 36 + ci * 9 + kh * 3 + kw];
                        #pragma unroll
                        for (int j = 0; j < 4; j++)
                            ffma2(acc2[cp][j], wp, rb[kw + j]);
                    }
                }
            }
            if (SECOND) {
                unsigned long long yb[4];
                #pragma unroll
                for (int j = 0; j < 4; j++) {
                    float yv = y_s[buf][ci * 132 + hg * 33 + wg * 4 + j];
                    yb[j] = pk2(yv, yv);
                }
                #pragma unroll
                for (int cp = 0; cp < 4; cp++) {
                    unsigned long long wp = wi2_s[buf][(cog * 4 + cp) * 4 + ci];
                    #pragma unroll
                    for (int j = 0; j < 4; j++)
                        ffma2(iacc2[cp][j], wp, yb[j]);
                }
            }
        }
        __syncthreads();
    }

    // epilogue: fold BN, (+identity branch), relu
    #pragma unroll
    for (int i = 0; i < 8; i++) {
        int cp = i >> 1, half = i & 1;
        int co = co_b * 64 + cog * 8 + i;
        float s    = bg[co] * rsqrtf(bv[co] + 1e-5f);
        float bias = cb[co] * s + bb[co] - bm[co] * s;
        float vals[4];
        if (SECOND) {
            float si    = ig[co] * rsqrtf(iv[co] + 1e-5f);
            float biasi = ibi[co] * si + ib2[co] - im[co] * si;
            #pragma unroll
            for (int j = 0; j < 4; j++) {
                float2 a = upk(acc2[cp][j]);
                float2 ia = upk(iacc2[cp][j]);
                float av = half ? a.y : a.x;
                float iv2 = half ? ia.y : ia.x;
                vals[j] = fmaxf(av * s + bias + iv2 * si + biasi, 0.f);
            }
        } else {
            #pragma unroll
            for (int j = 0; j < 4; j++) {
                float2 a = upk(acc2[cp][j]);
                float av = half ? a.y : a.x;
                vals[j] = fmaxf(av * s + bias, 0.f);
            }
        }
        int h = h0 + hg, w = w0 + wg * 4;
        float* dstf = SECOND ? out : g_t1;
        float4* dst = (float4*)&dstf[((n * 256 + co) * 256 + h) * 128 + w];
        *dst = make_float4(vals[0], vals[1], vals[2], vals[3]);
    }
}

// ---------------- launcher ------------------------------------------------------
extern "C" void kernel_launch(void* const* d_in, const int* in_sizes, int n_in,
                              void* d_out, int out_size) {
    const float* x      = (const float*)d_in[0];
    const float* qkv_w  = (const float*)d_in[1];
    const float* qkv_b  = (const float*)d_in[2];
    const float* proj_w = (const float*)d_in[3];
    const float* proj_b = (const float*)d_in[4];
    const float* rpb    = (const float*)d_in[5];
    const float* c1w = (const float*)d_in[6];
    const float* c1b = (const float*)d_in[7];
    const float* b1g = (const float*)d_in[8];
    const float* b1b = (const float*)d_in[9];
    const float* b1m = (const float*)d_in[10];
    const float* b1v = (const float*)d_in[11];
    const float* c2w = (const float*)d_in[12];
    const float* c2b = (const float*)d_in[13];
    const float* b2g = (const float*)d_in[14];
    const float* b2b = (const float*)d_in[15];
    const float* b2m = (const float*)d_in[16];
    const float* b2v = (const float*)d_in[17];
    const float* idw = (const float*)d_in[18];
    const float* idb = (const float*)d_in[19];
    const float* big = (const float*)d_in[20];
    const float* bib = (const float*)d_in[21];
    const float* bim = (const float*)d_in[22];
    const float* biv = (const float*)d_in[23];
    float* out = (float*)d_out;

    k_upsample<<<TOT / 256, 256>>>(x);
    k_attn<<<16384, 128>>>(qkv_w, qkv_b, proj_w, proj_b, rpb);

    dim3 grid(256, 4, 4);  // x = h_block*4 + w_block, y = co_block, z = n
    k_conv<0><<<grid, 256>>>(c1w, c1b, b1g, b1b, b1m, b1v,
                             idw, idb, big, bib, bim, biv, out);
    k_conv<1><<<grid, 256>>>(c2w, c2b, b2g, b2b, b2m, b2v,
                             idw, idb, big, bib, bim, biv, out);
}

// round 7
// speedup vs baseline: 2.4755x; 1.6887x over previous
#include <cuda_runtime.h>
#include <cuda_bf16.h>
#include <cstdint>

#define TOT (4*256*256*128)
static __device__ float g_xu[TOT];
static __device__ float g_y [TOT];
static __device__ uint32_t g_yhi[TOT/2];   // bf16-hi of y, ci-pair packed [n][cip][h][w]
static __device__ uint32_t g_ylo[TOT/2];
static __device__ uint32_t g_t1hi[TOT/2];  // conv1 output packed the same way
static __device__ uint32_t g_t1lo[TOT/2];
static __device__ unsigned short g_wc1[36*2*256*64]; // [(c*2+part)*256+co]*64+ci
static __device__ unsigned short g_wc2[40*2*256*64]; // conv2 (36) + identity (4)
static __device__ float g_b1[256], g_b2[256];

// ---------------- helpers -------------------------------------------------------
__device__ __forceinline__ uint32_t smem_u32(const void* p) {
    uint32_t r;
    asm("{ .reg .u64 t; cvta.to.shared.u64 t, %1; cvt.u32.u64 %0, t; }" : "=r"(r) : "l"(p));
    return r;
}
__device__ __forceinline__ void fsplit(float x, unsigned short& h, unsigned short& l) {
    __nv_bfloat16 bh = __float2bfloat16(x);
    float rem = x - __bfloat162float(bh);
    h = __bfloat16_as_ushort(bh);
    l = __bfloat16_as_ushort(__float2bfloat16(rem));
}
__device__ __forceinline__ void cpa4(void* dst_smem, const void* src, bool valid) {
    unsigned dst = (unsigned)__cvta_generic_to_shared(dst_smem);
    int sz = valid ? 4 : 0;
    asm volatile("cp.async.ca.shared.global [%0], [%1], 4, %2;"
                 :: "r"(dst), "l"(src), "r"(sz));
}
__device__ __forceinline__ void cp16(void* dst_smem, const void* src) {
    unsigned d = (unsigned)__cvta_generic_to_shared(dst_smem);
    asm volatile("cp.async.cg.shared.global [%0], [%1], 16;" :: "r"(d), "l"(src));
}
__device__ __forceinline__ void cpa_commit() { asm volatile("cp.async.commit_group;"); }
template <int N> __device__ __forceinline__ void cpa_wait() {
    asm volatile("cp.async.wait_group %0;" :: "n"(N));
}
__device__ __forceinline__ void ldmx4(uint32_t* r, uint32_t a) {
    asm volatile("ldmatrix.sync.aligned.m8n8.x4.shared.b16 {%0,%1,%2,%3}, [%4];"
                 : "=r"(r[0]), "=r"(r[1]), "=r"(r[2]), "=r"(r[3]) : "r"(a));
}
__device__ __forceinline__ void ldmx2(uint32_t* r, uint32_t a) {
    asm volatile("ldmatrix.sync.aligned.m8n8.x2.shared.b16 {%0,%1}, [%2];"
                 : "=r"(r[0]), "=r"(r[1]) : "r"(a));
}
__device__ __forceinline__ void mma16816(float* d, const uint32_t* a, const uint32_t* b) {
    asm volatile(
        "mma.sync.aligned.m16n8k16.row.col.f32.bf16.bf16.f32 "
        "{%0,%1,%2,%3}, {%4,%5,%6,%7}, {%8,%9}, {%0,%1,%2,%3};"
        : "+f"(d[0]), "+f"(d[1]), "+f"(d[2]), "+f"(d[3])
        : "r"(a[0]), "r"(a[1]), "r"(a[2]), "r"(a[3]), "r"(b[0]), "r"(b[1]));
}

// ---------------- K1: bilinear 2x upsample --------------------------------------
__global__ void k_upsample(const float* __restrict__ xin) {
    int idx = blockIdx.x * 256 + threadIdx.x;
    int cc = idx & 127;
    int t  = idx >> 7;
    int ww = t & 255; t >>= 8;
    int hh = t & 255;
    int b  = t >> 8;
    float pw = ww * (127.0f / 255.0f);
    int wlo = (int)pw; float fw = pw - (float)wlo; int whi = min(wlo + 1, 127);
    float pc = cc * (63.0f / 127.0f);
    int clo = (int)pc; float fc = pc - (float)clo; int chi = min(clo + 1, 63);
    const float* base = xin + ((b * 256 + hh) * 128) * 64;
    float v00 = base[wlo * 64 + clo], v01 = base[wlo * 64 + chi];
    float v10 = base[whi * 64 + clo], v11 = base[whi * 64 + chi];
    g_xu[idx] = (1.f - fw) * ((1.f - fc) * v00 + fc * v01)
              +        fw  * ((1.f - fc) * v10 + fc * v11);
}

// ---------------- K2: shifted-window attention (validated) ----------------------
__global__ __launch_bounds__(128) void k_attn(
    const float* __restrict__ qkv_w, const float* __restrict__ qkv_b,
    const float* __restrict__ proj_w, const float* __restrict__ proj_b,
    const float* __restrict__ rpb)
{
    __shared__ float Xs[16][128];
    __shared__ float QKV[16][384];
    __shared__ float P[4][16][16];
    __shared__ float O[16][128];
    int tid = threadIdx.x, blk = blockIdx.x;
    int b = blk >> 12, widx = blk & 4095, wh = widx >> 6, wc = widx & 63;
    #pragma unroll
    for (int t = 0; t < 16; t++) {
        int hs = wh * 4 + (t >> 2), ws = wc * 4 + (t & 3);
        int h2 = (hs + 3) & 255, w2 = (ws + 3) & 255;
        Xs[t][tid] = g_xu[((b * 256 + h2) * 256 + w2) * 128 + tid];
    }
    __syncthreads();
    float a0[16], a1[16], a2[16];
    #pragma unroll
    for (int t = 0; t < 16; t++) { a0[t] = 0.f; a1[t] = 0.f; a2[t] = 0.f; }
    for (int k = 0; k < 128; k++) {
        float w0 = qkv_w[k * 384 + tid];
        float w1 = qkv_w[k * 384 + 128 + tid];
        float w2 = qkv_w[k * 384 + 256 + tid];
        #pragma unroll
        for (int t = 0; t < 16; t++) {
            float xv = Xs[t][k];
            a0[t] += xv * w0; a1[t] += xv * w1; a2[t] += xv * w2;
        }
    }
    {
        float b0 = qkv_b[tid], b1 = qkv_b[128 + tid], b2 = qkv_b[256 + tid];
        #pragma unroll
        for (int t = 0; t < 16; t++) {
            QKV[t][tid] = a0[t] + b0;
            QKV[t][128 + tid] = a1[t] + b1;
            QKV[t][256 + tid] = a2[t] + b2;
        }
    }
    __syncthreads();
    int warp = tid >> 5, lane = tid & 31;
    if (lane < 16) {
        int t = lane, h = warp;
        float q[32];
        #pragma unroll
        for (int d = 0; d < 32; d++) q[d] = QKV[t][h * 32 + d] * 0.17677669529663687f;
        int i1 = t >> 2, j1 = t & 3;
        int rh1 = wh * 4 + i1, rw1 = wc * 4 + j1;
        int l1 = ((rh1 < 252) ? 0 : ((rh1 < 253) ? 1 : 2)) * 3
               + ((rw1 < 252) ? 0 : ((rw1 < 253) ? 1 : 2));
        float s[16], mx = -1e30f;
        #pragma unroll
        for (int u = 0; u < 16; u++) {
            float dot = 0.f;
            #pragma unroll
            for (int d = 0; d < 32; d++) dot += q[d] * QKV[u][128 + h * 32 + d];
            int i2 = u >> 2, j2 = u & 3;
            dot += rpb[((i1 - i2 + 3) * 7 + (j1 - j2 + 3)) * 4 + h];
            int rh2 = wh * 4 + i2, rw2 = wc * 4 + j2;
            int l2 = ((rh2 < 252) ? 0 : ((rh2 < 253) ? 1 : 2)) * 3
                   + ((rw2 < 252) ? 0 : ((rw2 < 253) ? 1 : 2));
            if (l1 != l2) dot -= 100.f;
            s[u] = dot; mx = fmaxf(mx, dot);
        }
        float sum = 0.f;
        #pragma unroll
        for (int u = 0; u < 16; u++) { s[u] = __expf(s[u] - mx); sum += s[u]; }
        float inv = 1.f / sum;
        #pragma unroll
        for (int u = 0; u < 16; u++) P[h][t][u] = s[u] * inv;
    }
    __syncwarp();
    {
        int h = warp, d = lane;
        #pragma unroll
        for (int t = 0; t < 16; t++) {
            float acc = 0.f;
            #pragma unroll
            for (int u = 0; u < 16; u++) acc += P[h][t][u] * QKV[u][256 + h * 32 + d];
            O[t][h * 32 + d] = acc;
        }
    }
    __syncthreads();
    float pa[16];
    #pragma unroll
    for (int t = 0; t < 16; t++) pa[t] = 0.f;
    for (int k = 0; k < 128; k++) {
        float wv = proj_w[k * 128 + tid];
        #pragma unroll
        for (int t = 0; t < 16; t++) pa[t] += O[t][k] * wv;
    }
    float pb = proj_b[tid];
    #pragma unroll
    for (int t = 0; t < 16; t++) {
        int hs = wh * 4 + (t >> 2), ws = wc * 4 + (t & 3);
        int h2 = (hs + 3) & 255, w2 = (ws + 3) & 255;
        g_y[((b * 256 + h2) * 256 + w2) * 128 + tid] = pa[t] + pb + Xs[t][tid];
    }
}

// ---------------- K3: split y into packed bf16 hi/lo ----------------------------
__global__ void k_cvt_y() {
    int idx = blockIdx.x * 256 + threadIdx.x;        // 16,777,216
    int w = idx & 127;
    int t = idx >> 7;
    int h = t & 255; t >>= 8;
    int cip = t & 127;
    int n = t >> 7;
    float x0 = g_y[((n * 256 + 2 * cip) * 256 + h) * 128 + w];
    float x1 = g_y[((n * 256 + 2 * cip + 1) * 256 + h) * 128 + w];
    unsigned short h0, l0, h1, l1;
    fsplit(x0, h0, l0); fsplit(x1, h1, l1);
    g_yhi[idx] = (uint32_t)h0 | ((uint32_t)h1 << 16);
    g_ylo[idx] = (uint32_t)l0 | ((uint32_t)l1 << 16);
}

// ---------------- weight prep: fold BN, split hi/lo -----------------------------
__global__ void k_cvt_w1(const float* __restrict__ cw, const float* __restrict__ cb,
                         const float* __restrict__ bg, const float* __restrict__ bb,
                         const float* __restrict__ bm, const float* __restrict__ bv) {
    int idx = blockIdx.x * 256 + threadIdx.x;
    if (idx >= 36 * 256 * 64) return;
    int ci = idx & 63;
    int t = idx >> 6;
    int co = t & 255;
    int c = t >> 8;
    int kh = c / 12, kw = (c >> 2) % 3, ci0 = (c & 3) << 6;
    float s = bg[co] * rsqrtf(bv[co] + 1e-5f);
    float wv = cw[((co * 256 + ci0 + ci) * 3 + kh) * 3 + kw] * s;
    unsigned short hi, lo; fsplit(wv, hi, lo);
    g_wc1[((c * 2 + 0) * 256 + co) * 64 + ci] = hi;
    g_wc1[((c * 2 + 1) * 256 + co) * 64 + ci] = lo;
    if (c == 0 && ci == 0) g_b1[co] = cb[co] * s + bb[co] - bm[co] * s;
}
__global__ void k_cvt_w2(const float* __restrict__ cw, const float* __restrict__ cb,
                         const float* __restrict__ bg, const float* __restrict__ bb,
                         const float* __restrict__ bm, const float* __restrict__ bv,
                         const float* __restrict__ iw, const float* __restrict__ ibi,
                         const float* __restrict__ ig, const float* __restrict__ ib2,
                         const float* __restrict__ im, const float* __restrict__ iv) {
    int idx = blockIdx.x * 256 + threadIdx.x;
    if (idx >= 40 * 256 * 64) return;
    int ci = idx & 63;
    int t = idx >> 6;
    int co = t & 255;
    int c = t >> 8;
    float wv;
    if (c < 36) {
        int kh = c / 12, kw = (c >> 2) % 3, ci0 = (c & 3) << 6;
        wv = cw[((co * 256 + ci0 + ci) * 3 + kh) * 3 + kw] * (bg[co] * rsqrtf(bv[co] + 1e-5f));
    } else {
        wv = iw[co * 256 + ((c - 36) << 6) + ci] * (ig[co] * rsqrtf(iv[co] + 1e-5f));
    }
    unsigned short hi, lo; fsplit(wv, hi, lo);
    g_wc2[((c * 2 + 0) * 256 + co) * 64 + ci] = hi;
    g_wc2[((c * 2 + 1) * 256 + co) * 64 + ci] = lo;
    if (c == 0 && ci == 0) {
        float s  = bg[co] * rsqrtf(bv[co] + 1e-5f);
        float si = ig[co] * rsqrtf(iv[co] + 1e-5f);
        g_b2[co] = cb[co] * s + bb[co] - bm[co] * s + ibi[co] * si + ib2[co] - im[co] * si;
    }
}

// ---------------- K4/K5: mma.sync bf16 implicit-GEMM conv -----------------------
// CTA = (n,h): M=128 pixels, N=256 co, K streamed as stages (tap x 64ci).
// 16 warps (4m x 4n); warp tile 32x64; 3-product bf16 split.
// smem stage: B[2 part][256 co][72] + A[2 part][128 px][72] bf16, 144B rows.
#define STG_BYTES 110592
#define A_OFF     73728
#define PART_B    36864
#define PART_A    18432
template <int SECOND>
__global__ __launch_bounds__(512, 1) void k_conv_tc(float* __restrict__ out) {
    extern __shared__ __align__(16) char smem[];
    const int G = SECOND ? 40 : 36;
    const unsigned short* Wc = SECOND ? g_wc2 : g_wc1;

    int tid = threadIdx.x;
    int n = blockIdx.x >> 8, h = blockIdx.x & 255;
    int warp = tid >> 5, lane = tid & 31;
    int wm = warp >> 2, wn = warp & 3;
    int gid = lane >> 2, tig = lane & 3;

    float acc[2][8][4];
    #pragma unroll
    for (int mt = 0; mt < 2; mt++)
        #pragma unroll
        for (int nt = 0; nt < 8; nt++)
            #pragma unroll
            for (int q = 0; q < 4; q++) acc[mt][nt][q] = 0.f;

    auto params = [&](int g, int& kh, int& kw, int& cib,
                      const uint32_t*& sH, const uint32_t*& sL) {
        if (!SECOND) { kh = g / 12; kw = (g >> 2) % 3; cib = g & 3; sH = g_yhi; sL = g_ylo; }
        else if (g < 36) { kh = g / 12; kw = (g >> 2) % 3; cib = g & 3; sH = g_t1hi; sL = g_t1lo; }
        else { kh = 1; kw = 1; cib = g - 36; sH = g_yhi; sL = g_ylo; }
    };
    auto load_stage = [&](char* dst, int g) {
        // B: 2 part x 256 co x 64 ci, 16B chunks
        const unsigned short* src = Wc + (size_t)g * 32768;
        for (int i = tid; i < 4096; i += 512) {
            int c16 = i & 7; int t = i >> 3; int co = t & 255; int part = t >> 8;
            cp16(dst + part * PART_B + co * 144 + c16 * 16,
                 src + (size_t)(part * 256 + co) * 64 + c16 * 8);
        }
        // A: 2 part x 128 px x 32 u32, halo zero-fill
        int kh, kw, cib; const uint32_t *sH, *sL;
        params(g, kh, kw, cib, sH, sL);
        int hh = h + kh - 1;
        bool okh = (unsigned)hh < 256u;
        int hc = okh ? hh : 0;
        for (int i = tid; i < 8192; i += 512) {
            int px = i & 127; int t = i >> 7; int j = t & 31; int part = t >> 5;
            int ww = px + kw - 1;
            bool ok = okh && ((unsigned)ww < 128u);
            const uint32_t* sp = part ? sL : sH;
            const uint32_t* s2 = sp + ((((size_t)n * 128 + cib * 32 + j) * 256 + hc) * 128
                                       + (ok ? ww : 0));
            cpa4(dst + A_OFF + part * PART_A + px * 144 + j * 4, s2, ok);
        }
    };

    load_stage(smem, 0);
    cpa_commit();

    for (int g = 0; g < G; g++) {
        if (g + 1 < G) {
            load_stage(smem + ((g + 1) & 1) * STG_BYTES, g + 1);
            cpa_commit();
            cpa_wait<1>();
        } else {
            cpa_wait<0>();
        }
        __syncthreads();

        uint32_t sb = smem_u32(smem + (g & 1) * STG_BYTES);
        uint32_t aB = sb + A_OFF;
        int arow = wm * 32 + (lane & 15);
        int acol = ((lane >> 4) & 1) * 16;           // +8 bf16 = 16B
        int brow = wn * 64 + (lane & 7);
        int bcol = ((lane >> 3) & 1) * 16;

        #pragma unroll
        for (int kc = 0; kc < 4; kc++) {
            uint32_t ah[2][4], al[2][4];
            #pragma unroll
            for (int mt = 0; mt < 2; mt++) {
                uint32_t ad = aB + (uint32_t)(arow + mt * 16) * 144 + kc * 32 + acol;
                ldmx4(ah[mt], ad);
                ldmx4(al[mt], ad + PART_A);
            }
            #pragma unroll
            for (int nt = 0; nt < 8; nt++) {
                uint32_t bd = sb + (uint32_t)(brow + nt * 8) * 144 + kc * 32 + bcol;
                uint32_t bh[2], bl[2];
                ldmx2(bh, bd);
                ldmx2(bl, bd + PART_B);
                #pragma unroll
                for (int mt = 0; mt < 2; mt++) {
                    mma16816(acc[mt][nt], ah[mt], bh);
                    mma16816(acc[mt][nt], al[mt], bh);
                    mma16816(acc[mt][nt], ah[mt], bl);
                }
            }
        }
        __syncthreads();
    }

    // epilogue
    const float* bsrc = SECOND ? g_b2 : g_b1;
    #pragma unroll
    for (int nt = 0; nt < 8; nt++) {
        int coe = wn * 64 + nt * 8 + 2 * tig;
        float b0 = bsrc[coe], b1 = bsrc[coe + 1];
        #pragma unroll
        for (int mt = 0; mt < 2; mt++) {
            int p0 = wm * 32 + mt * 16 + gid;
            float v00 = fmaxf(acc[mt][nt][0] + b0, 0.f);
            float v01 = fmaxf(acc[mt][nt][1] + b1, 0.f);
            float v10 = fmaxf(acc[mt][nt][2] + b0, 0.f);
            float v11 = fmaxf(acc[mt][nt][3] + b1, 0.f);
            if (SECOND) {
                size_t o0 = (((size_t)n * 256 + coe) * 256 + h) * 128;
                out[o0 + p0] = v00;
                out[o0 + p0 + 8] = v10;
                out[o0 + 32768 + p0] = v01;
                out[o0 + 32768 + p0 + 8] = v11;
            } else {
                unsigned short h0, l0, h1, l1;
                size_t o = (((size_t)n * 128 + (coe >> 1)) * 256 + h) * 128;
                fsplit(v00, h0, l0); fsplit(v01, h1, l1);
                g_t1hi[o + p0] = (uint32_t)h0 | ((uint32_t)h1 << 16);
                g_t1lo[o + p0] = (uint32_t)l0 | ((uint32_t)l1 << 16);
                fsplit(v10, h0, l0); fsplit(v11, h1, l1);
                g_t1hi[o + p0 + 8] = (uint32_t)h0 | ((uint32_t)h1 << 16);
                g_t1lo[o + p0 + 8] = (uint32_t)l0 | ((uint32_t)l1 << 16);
            }
        }
    }
}

// ---------------- launcher ------------------------------------------------------
extern "C" void kernel_launch(void* const* d_in, const int* in_sizes, int n_in,
                              void* d_out, int out_size) {
    const float* x      = (const float*)d_in[0];
    const float* qkv_w  = (const float*)d_in[1];
    const float* qkv_b  = (const float*)d_in[2];
    const float* proj_w = (const float*)d_in[3];
    const float* proj_b = (const float*)d_in[4];
    const float* rpb    = (const float*)d_in[5];
    const float* c1w = (const float*)d_in[6];
    const float* c1b = (const float*)d_in[7];
    const float* b1g = (const float*)d_in[8];
    const float* b1b = (const float*)d_in[9];
    const float* b1m = (const float*)d_in[10];
    const float* b1v = (const float*)d_in[11];
    const float* c2w = (const float*)d_in[12];
    const float* c2b = (const float*)d_in[13];
    const float* b2g = (const float*)d_in[14];
    const float* b2b = (const float*)d_in[15];
    const float* b2m = (const float*)d_in[16];
    const float* b2v = (const float*)d_in[17];
    const float* idw = (const float*)d_in[18];
    const float* idb = (const float*)d_in[19];
    const float* big = (const float*)d_in[20];
    const float* bib = (const float*)d_in[21];
    const float* bim = (const float*)d_in[22];
    const float* biv = (const float*)d_in[23];
    float* out = (float*)d_out;

    cudaFuncSetAttribute(k_conv_tc<0>, cudaFuncAttributeMaxDynamicSharedMemorySize, 2 * STG_BYTES);
    cudaFuncSetAttribute(k_conv_tc<1>, cudaFuncAttributeMaxDynamicSharedMemorySize, 2 * STG_BYTES);

    k_upsample<<<TOT / 256, 256>>>(x);
    k_attn<<<16384, 128>>>(qkv_w, qkv_b, proj_w, proj_b, rpb);
    k_cvt_y<<<65536, 256>>>();
    k_cvt_w1<<<2304, 256>>>(c1w, c1b, b1g, b1b, b1m, b1v);
    k_cvt_w2<<<2560, 256>>>(c2w, c2b, b2g, b2b, b2m, b2v,
                            idw, idb, big, bib, bim, biv);
    k_conv_tc<0><<<1024, 512, 2 * STG_BYTES>>>(out);
    k_conv_tc<1><<<1024, 512, 2 * STG_BYTES>>>(out);
}

// round 9
// speedup vs baseline: 2.7389x; 1.1064x over previous
#include <cuda_runtime.h>
#include <cuda_bf16.h>
#include <cstdint>

#define TOT (4*256*256*128)
static __device__ float g_xu[TOT];                    // upsampled x (B,H,W,C)
static __device__ unsigned short g_xuh[TOT];          // split bf16 of g_xu
static __device__ unsigned short g_xul[TOT];
static __device__ float g_qkv[(size_t)4*256*256*384]; // QKV per shifted pixel
static __device__ unsigned short g_oh[TOT];           // attention out O split (orig coords)
static __device__ unsigned short g_ol[TOT];
static __device__ float g_y[TOT];                     // attention + residual (fp32)
static __device__ uint32_t g_yhi[TOT/2];              // y packed ci-pair planes [n][cip][h][w]
static __device__ uint32_t g_ylo[TOT/2];
static __device__ uint32_t g_t1hi[TOT/2];             // conv1 out packed
static __device__ uint32_t g_t1lo[TOT/2];
static __device__ unsigned short g_wc1[36*2*256*64];
static __device__ unsigned short g_wc2[40*2*256*64];
static __device__ unsigned short g_wq[2*384*128];     // qkv_w split [part][n][k]
static __device__ unsigned short g_wp[2*128*128];     // proj_w split [part][n][k]
static __device__ float g_b1[256], g_b2[256], g_bq[384], g_bp[128];

// ---------------- helpers -------------------------------------------------------
__device__ __forceinline__ uint32_t smem_u32(const void* p) {
    uint32_t r;
    asm("{ .reg .u64 t; cvta.to.shared.u64 t, %1; cvt.u32.u64 %0, t; }" : "=r"(r) : "l"(p));
    return r;
}
__device__ __forceinline__ void fsplit(float x, unsigned short& h, unsigned short& l) {
    __nv_bfloat16 bh = __float2bfloat16(x);
    float rem = x - __bfloat162float(bh);
    h = __bfloat16_as_ushort(bh);
    l = __bfloat16_as_ushort(__float2bfloat16(rem));
}
__device__ __forceinline__ void cpa4(void* dst_smem, const void* src, bool valid) {
    unsigned dst = (unsigned)__cvta_generic_to_shared(dst_smem);
    int sz = valid ? 4 : 0;
    asm volatile("cp.async.ca.shared.global [%0], [%1], 4, %2;"
                 :: "r"(dst), "l"(src), "r"(sz));
}
__device__ __forceinline__ void cp16(void* dst_smem, const void* src) {
    unsigned d = (unsigned)__cvta_generic_to_shared(dst_smem);
    asm volatile("cp.async.cg.shared.global [%0], [%1], 16;" :: "r"(d), "l"(src));
}
__device__ __forceinline__ void cpa_commit() { asm volatile("cp.async.commit_group;"); }
template <int N> __device__ __forceinline__ void cpa_wait() {
    asm volatile("cp.async.wait_group %0;" :: "n"(N));
}
__device__ __forceinline__ void ldmx4(uint32_t* r, uint32_t a) {
    asm volatile("ldmatrix.sync.aligned.m8n8.x4.shared.b16 {%0,%1,%2,%3}, [%4];"
                 : "=r"(r[0]), "=r"(r[1]), "=r"(r[2]), "=r"(r[3]) : "r"(a));
}
__device__ __forceinline__ void ldmx2(uint32_t* r, uint32_t a) {
    asm volatile("ldmatrix.sync.aligned.m8n8.x2.shared.b16 {%0,%1}, [%2];"
                 : "=r"(r[0]), "=r"(r[1]) : "r"(a));
}
__device__ __forceinline__ void mma16816(float* d, const uint32_t* a, const uint32_t* b) {
    asm volatile(
        "mma.sync.aligned.m16n8k16.row.col.f32.bf16.bf16.f32 "
        "{%0,%1,%2,%3}, {%4,%5,%6,%7}, {%8,%9}, {%0,%1,%2,%3};"
        : "+f"(d[0]), "+f"(d[1]), "+f"(d[2]), "+f"(d[3])
        : "r"(a[0]), "r"(a[1]), "r"(a[2]), "r"(a[3]), "r"(b[0]), "r"(b[1]));
}

// ---------------- K1: bilinear 2x upsample + bf16 split -------------------------
__global__ void k_upsample(const float* __restrict__ xin) {
    int idx = blockIdx.x * 256 + threadIdx.x;
    int cc = idx & 127;
    int t  = idx >> 7;
    int ww = t & 255; t >>= 8;
    int hh = t & 255;
    int b  = t >> 8;
    float pw = ww * (127.0f / 255.0f);
    int wlo = (int)pw; float fw = pw - (float)wlo; int whi = min(wlo + 1, 127);
    float pc = cc * (63.0f / 127.0f);
    int clo = (int)pc; float fc = pc - (float)clo; int chi = min(clo + 1, 63);
    const float* base = xin + ((b * 256 + hh) * 128) * 64;
    float v00 = base[wlo * 64 + clo], v01 = base[wlo * 64 + chi];
    float v10 = base[whi * 64 + clo], v11 = base[whi * 64 + chi];
    float v = (1.f - fw) * ((1.f - fc) * v00 + fc * v01)
            +        fw  * ((1.f - fc) * v10 + fc * v11);
    g_xu[idx] = v;
    unsigned short h, l;
    fsplit(v, h, l);
    g_xuh[idx] = h;
    g_xul[idx] = l;
}

// ---------------- weight prep ---------------------------------------------------
__global__ void k_cvt_wq(const float* __restrict__ qkv_w, const float* __restrict__ qkv_b) {
    int idx = blockIdx.x * 256 + threadIdx.x;     // 384*128
    if (idx >= 49152) return;
    int k = idx & 127, nn = idx >> 7;
    unsigned short hi, lo;
    fsplit(qkv_w[k * 384 + nn], hi, lo);
    g_wq[nn * 128 + k] = hi;
    g_wq[49152 + nn * 128 + k] = lo;
    if (k == 0) g_bq[nn] = qkv_b[nn];
}
__global__ void k_cvt_wp(const float* __restrict__ proj_w, const float* __restrict__ proj_b) {
    int idx = blockIdx.x * 256 + threadIdx.x;     // 128*128
    if (idx >= 16384) return;
    int k = idx & 127, nn = idx >> 7;
    unsigned short hi, lo;
    fsplit(proj_w[k * 128 + nn], hi, lo);
    g_wp[nn * 128 + k] = hi;
    g_wp[16384 + nn * 128 + k] = lo;
    if (k == 0) g_bp[nn] = proj_b[nn];
}
__global__ void k_cvt_w1(const float* __restrict__ cw, const float* __restrict__ cb,
                         const float* __restrict__ bg, const float* __restrict__ bb,
                         const float* __restrict__ bm, const float* __restrict__ bv) {
    int idx = blockIdx.x * 256 + threadIdx.x;
    if (idx >= 36 * 256 * 64) return;
    int ci = idx & 63;
    int t = idx >> 6;
    int co = t & 255;
    int c = t >> 8;
    int kh = c / 12, kw = (c >> 2) % 3, ci0 = (c & 3) << 6;
    float s = bg[co] * rsqrtf(bv[co] + 1e-5f);
    float wv = cw[((co * 256 + ci0 + ci) * 3 + kh) * 3 + kw] * s;
    unsigned short hi, lo; fsplit(wv, hi, lo);
    g_wc1[((c * 2 + 0) * 256 + co) * 64 + ci] = hi;
    g_wc1[((c * 2 + 1) * 256 + co) * 64 + ci] = lo;
    if (c == 0 && ci == 0) g_b1[co] = cb[co] * s + bb[co] - bm[co] * s;
}
__global__ void k_cvt_w2(const float* __restrict__ cw, const float* __restrict__ cb,
                         const float* __restrict__ bg, const float* __restrict__ bb,
                         const float* __restrict__ bm, const float* __restrict__ bv,
                         const float* __restrict__ iw, const float* __restrict__ ibi,
                         const float* __restrict__ ig, const float* __restrict__ ib2,
                         const float* __restrict__ im, const float* __restrict__ iv) {
    int idx = blockIdx.x * 256 + threadIdx.x;
    if (idx >= 40 * 256 * 64) return;
    int ci = idx & 63;
    int t = idx >> 6;
    int co = t & 255;
    int c = t >> 8;
    float wv;
    if (c < 36) {
        int kh = c / 12, kw = (c >> 2) % 3, ci0 = (c & 3) << 6;
        wv = cw[((co * 256 + ci0 + ci) * 3 + kh) * 3 + kw] * (bg[co] * rsqrtf(bv[co] + 1e-5f));
    } else {
        wv = iw[co * 256 + ((c - 36) << 6) + ci] * (ig[co] * rsqrtf(iv[co] + 1e-5f));
    }
    unsigned short hi, lo; fsplit(wv, hi, lo);
    g_wc2[((c * 2 + 0) * 256 + co) * 64 + ci] = hi;
    g_wc2[((c * 2 + 1) * 256 + co) * 64 + ci] = lo;
    if (c == 0 && ci == 0) {
        float s  = bg[co] * rsqrtf(bv[co] + 1e-5f);
        float si = ig[co] * rsqrtf(iv[co] + 1e-5f);
        g_b2[co] = cb[co] * s + bb[co] - bm[co] * s + ibi[co] * si + ib2[co] - im[co] * si;
    }
}

// ---------------- K-QKV: [262144 x 128] @ [128 x 384] bf16-split mma ------------
#define QKV_STG 81920
__global__ __launch_bounds__(512, 1) void k_qkv() {
    extern __shared__ __align__(16) char smem[];
    int tid = threadIdx.x;
    int blk = blockIdx.x;                    // 2048
    int n = blk >> 9, hs = (blk >> 1) & 255, wb = blk & 1;
    int w0 = wb * 128;
    int h2 = (hs + 3) & 255;
    int warp = tid >> 5, lane = tid & 31;
    int wm = warp >> 2, wn = warp & 3;
    int gid = lane >> 2, tig = lane & 3;

    float acc[2][12][4];
    #pragma unroll
    for (int mt = 0; mt < 2; mt++)
        #pragma unroll
        for (int nt = 0; nt < 12; nt++)
            #pragma unroll
            for (int q = 0; q < 4; q++) acc[mt][nt][q] = 0.f;

    auto load_stage = [&](char* dst, int g) {
        int kc0 = g * 32;
        for (int i = tid; i < 3072; i += 512) {      // B: 2 part x 384 n x 32 k
            int c4 = i & 3; int t = i >> 2; int nr = t % 384; int part = t / 384;
            cp16(dst + part * 30720 + nr * 80 + c4 * 16,
                 g_wq + (size_t)part * 49152 + nr * 128 + kc0 + c4 * 8);
        }
        for (int i = tid; i < 1024; i += 512) {      // A: 2 part x 128 px x 32 k
            int c4 = i & 3; int t = i >> 2; int pr = t & 127; int part = t >> 7;
            int w2 = (w0 + pr + 3) & 255;
            const unsigned short* sp = part ? g_xul : g_xuh;
            cp16(dst + 61440 + part * 10240 + pr * 80 + c4 * 16,
                 sp + (((size_t)n * 256 + h2) * 256 + w2) * 128 + kc0 + c4 * 8);
        }
    };

    load_stage(smem, 0);
    cpa_commit();
    for (int g = 0; g < 4; g++) {
        if (g + 1 < 4) {
            load_stage(smem + ((g + 1) & 1) * QKV_STG, g + 1);
            cpa_commit();
            cpa_wait<1>();
        } else cpa_wait<0>();
        __syncthreads();

        uint32_t sb = smem_u32(smem + (g & 1) * QKV_STG);
        uint32_t aB = sb + 61440;
        int arow = wm * 32 + (lane & 15);
        int acol = ((lane >> 4) & 1) * 16;
        int brow = wn * 96 + (lane & 7);
        int bcol = ((lane >> 3) & 1) * 16;

        #pragma unroll
        for (int kc = 0; kc < 2; kc++) {
            uint32_t ah[2][4], al[2][4];
            #pragma unroll
            for (int mt = 0; mt < 2; mt++) {
                uint32_t ad = aB + (uint32_t)(arow + mt * 16) * 80 + kc * 32 + acol;
                ldmx4(ah[mt], ad);
                ldmx4(al[mt], ad + 10240);
            }
            #pragma unroll
            for (int nt = 0; nt < 12; nt++) {
                uint32_t bd = sb + (uint32_t)(brow + nt * 8) * 80 + kc * 32 + bcol;
                uint32_t bh[2], bl[2];
                ldmx2(bh, bd);
                ldmx2(bl, bd + 30720);
                #pragma unroll
                for (int mt = 0; mt < 2; mt++) {
                    mma16816(acc[mt][nt], ah[mt], bh);
                    mma16816(acc[mt][nt], al[mt], bh);
                    mma16816(acc[mt][nt], ah[mt], bl);
                }
            }
        }
        __syncthreads();
    }

    size_t pbase = ((size_t)n * 256 + hs) * 256 + w0;
    #pragma unroll
    for (int nt = 0; nt < 12; nt++) {
        int col = wn * 96 + nt * 8 + 2 * tig;
        float b0 = g_bq[col], b1 = g_bq[col + 1];
        float sc = (col < 128) ? 0.17677669529663687f : 1.f;
        #pragma unroll
        for (int mt = 0; mt < 2; mt++) {
            int r0 = wm * 32 + mt * 16 + gid;
            float2 v0 = make_float2((acc[mt][nt][0] + b0) * sc, (acc[mt][nt][1] + b1) * sc);
            float2 v1 = make_float2((acc[mt][nt][2] + b0) * sc, (acc[mt][nt][3] + b1) * sc);
            *(float2*)&g_qkv[(pbase + r0) * 384 + col] = v0;
            *(float2*)&g_qkv[(pbase + r0 + 8) * 384 + col] = v1;
        }
    }
}

// ---------------- attention core: scores/softmax/PV per window ------------------
__global__ __launch_bounds__(128) void k_attn_core(const float* __restrict__ rpb) {
    __shared__ float QKV[16][384];
    __shared__ float P[4][16][16];
    __shared__ float O[16][128];
    int tid = threadIdx.x, blk = blockIdx.x;
    int n = blk >> 12, widx = blk & 4095, wh = widx >> 6, wc = widx & 63;

    for (int idx = tid; idx < 6144; idx += 128) {
        int t = idx / 384, c = idx - t * 384;
        size_t ps = ((size_t)n * 256 + wh * 4 + (t >> 2)) * 256 + wc * 4 + (t & 3);
        QKV[t][c] = g_qkv[ps * 384 + c];
    }
    __syncthreads();

    int warp = tid >> 5, lane = tid & 31;
    if (lane < 16) {
        int t = lane, h = warp;
        float q[32];
        #pragma unroll
        for (int d = 0; d < 32; d++) q[d] = QKV[t][h * 32 + d];
        int i1 = t >> 2, j1 = t & 3;
        int rh1 = wh * 4 + i1, rw1 = wc * 4 + j1;
        int l1 = ((rh1 < 252) ? 0 : ((rh1 < 253) ? 1 : 2)) * 3
               + ((rw1 < 252) ? 0 : ((rw1 < 253) ? 1 : 2));
        float s[16], mx = -1e30f;
        #pragma unroll
        for (int u = 0; u < 16; u++) {
            float dot = 0.f;
            #pragma unroll
            for (int d = 0; d < 32; d++) dot += q[d] * QKV[u][128 + h * 32 + d];
            int i2 = u >> 2, j2 = u & 3;
            dot += rpb[((i1 - i2 + 3) * 7 + (j1 - j2 + 3)) * 4 + h];
            int rh2 = wh * 4 + i2, rw2 = wc * 4 + j2;
            int l2 = ((rh2 < 252) ? 0 : ((rh2 < 253) ? 1 : 2)) * 3
                   + ((rw2 < 252) ? 0 : ((rw2 < 253) ? 1 : 2));
            if (l1 != l2) dot -= 100.f;
            s[u] = dot; mx = fmaxf(mx, dot);
        }
        float sum = 0.f;
        #pragma unroll
        for (int u = 0; u < 16; u++) { s[u] = __expf(s[u] - mx); sum += s[u]; }
        float inv = 1.f / sum;
        #pragma unroll
        for (int u = 0; u < 16; u++) P[h][t][u] = s[u] * inv;
    }
    __syncwarp();
    {
        int h = warp, d = lane;
        #pragma unroll
        for (int t = 0; t < 16; t++) {
            float acc = 0.f;
            #pragma unroll
            for (int u = 0; u < 16; u++) acc += P[h][t][u] * QKV[u][256 + h * 32 + d];
            O[t][h * 32 + d] = acc;
        }
    }
    __syncthreads();

    // pack O split-bf16 at ORIGINAL pixel coords (roll back by +3)
    int t = tid >> 3, c0 = (tid & 7) * 16;
    int hs = wh * 4 + (t >> 2), ws = wc * 4 + (t & 3);
    int hh2 = (hs + 3) & 255, ww2 = (ws + 3) & 255;
    size_t po = (((size_t)n * 256 + hh2) * 256 + ww2) * 128;
    #pragma unroll
    for (int c = 0; c < 16; c++) {
        unsigned short h, l;
        fsplit(O[t][c0 + c], h, l);
        g_oh[po + c0 + c] = h;
        g_ol[po + c0 + c] = l;
    }
}

// ---------------- K-proj: [262144 x 128] @ [128 x 128] + bias + residual --------
// Writes fp32 g_y (original coords). Packing to conv planes done by k_cvt_y.
__global__ __launch_bounds__(512, 1) void k_proj() {
    extern __shared__ __align__(16) char smem[];
    int tid = threadIdx.x;
    int blk = blockIdx.x;                    // 2048
    size_t p0 = (size_t)blk * 128;
    int warp = tid >> 5, lane = tid & 31;
    int wm = warp >> 2, wn = warp & 3;
    int gid = lane >> 2, tig = lane & 3;

    for (int i = tid; i < 4096; i += 512) {  // B: proj_w split
        int c16 = i & 15; int t = i >> 4; int nr = t & 127; int part = t >> 7;
        cp16(smem + part * 34816 + nr * 272 + c16 * 16,
             g_wp + (size_t)part * 16384 + nr * 128 + c16 * 8);
    }
    for (int i = tid; i < 4096; i += 512) {  // A: O split
        int c16 = i & 15; int t = i >> 4; int pr = t & 127; int part = t >> 7;
        const unsigned short* sp = part ? g_ol : g_oh;
        cp16(smem + 69632 + part * 34816 + pr * 272 + c16 * 16,
             sp + (p0 + pr) * 128 + c16 * 8);
    }
    cpa_commit();
    cpa_wait<0>();
    __syncthreads();

    float acc[2][4][4];
    #pragma unroll
    for (int mt = 0; mt < 2; mt++)
        #pragma unroll
        for (int nt = 0; nt < 4; nt++)
            #pragma unroll
            for (int q = 0; q < 4; q++) acc[mt][nt][q] = 0.f;

    uint32_t sb = smem_u32(smem);
    uint32_t aB = sb + 69632;
    int arow = wm * 32 + (lane & 15);
    int acol = ((lane >> 4) & 1) * 16;
    int brow = wn * 32 + (lane & 7);
    int bcol = ((lane >> 3) & 1) * 16;

    #pragma unroll
    for (int kc = 0; kc < 8; kc++) {
        uint32_t ah[2][4], al[2][4];
        #pragma unroll
        for (int mt = 0; mt < 2; mt++) {
            uint32_t ad = aB + (uint32_t)(arow + mt * 16) * 272 + kc * 32 + acol;
            ldmx4(ah[mt], ad);
            ldmx4(al[mt], ad + 34816);
        }
        #pragma unroll
        for (int nt = 0; nt < 4; nt++) {
            uint32_t bd = sb + (uint32_t)(brow + nt * 8) * 272 + kc * 32 + bcol;
            uint32_t bh[2], bl[2];
            ldmx2(bh, bd);
            ldmx2(bl, bd + 34816);
            #pragma unroll
            for (int mt = 0; mt < 2; mt++) {
                mma16816(acc[mt][nt], ah[mt], bh);
                mma16816(acc[mt][nt], al[mt], bh);
                mma16816(acc[mt][nt], ah[mt], bl);
            }
        }
    }

    // epilogue: + bias + residual -> fp32 y
    #pragma unroll
    for (int nt = 0; nt < 4; nt++) {
        int coe = wn * 32 + nt * 8 + 2 * tig;
        float b0 = g_bp[coe], b1 = g_bp[coe + 1];
        #pragma unroll
        for (int mt = 0; mt < 2; mt++) {
            #pragma unroll
            for (int half = 0; half < 2; half++) {
                size_t p = p0 + wm * 32 + mt * 16 + gid + half * 8;
                float2 res = *(const float2*)&g_xu[p * 128 + coe];
                float v0 = acc[mt][nt][half * 2 + 0] + b0 + res.x;
                float v1 = acc[mt][nt][half * 2 + 1] + b1 + res.y;
                *(float2*)&g_y[p * 128 + coe] = make_float2(v0, v1);
            }
        }
    }
}

// ---------------- K-cvt-y: pack fp32 y into conv-plane split bf16 (validated) ---
__global__ void k_cvt_y() {
    int idx = blockIdx.x * 256 + threadIdx.x;        // 16,777,216
    int w = idx & 127;
    int t = idx >> 7;
    int h = t & 255; t >>= 8;
    int cip = t & 127;
    int n = t >> 7;
    float x0 = g_y[(((size_t)n * 256 + 2 * cip) * 256 + h) * 128 + w];
    float x1 = g_y[(((size_t)n * 256 + 2 * cip + 1) * 256 + h) * 128 + w];
    unsigned short h0, l0, h1, l1;
    fsplit(x0, h0, l0); fsplit(x1, h1, l1);
    g_yhi[idx] = (uint32_t)h0 | ((uint32_t)h1 << 16);
    g_ylo[idx] = (uint32_t)l0 | ((uint32_t)l1 << 16);
}

// ---------------- conv kernels (unchanged from R7, validated) -------------------
#define STG_BYTES 110592
#define A_OFF     73728
#define PART_B    36864
#define PART_A    18432
template <int SECOND>
__global__ __launch_bounds__(512, 1) void k_conv_tc(float* __restrict__ out) {
    extern __shared__ __align__(16) char smem[];
    const int G = SECOND ? 40 : 36;
    const unsigned short* Wc = SECOND ? g_wc2 : g_wc1;

    int tid = threadIdx.x;
    int n = blockIdx.x >> 8, h = blockIdx.x & 255;
    int warp = tid >> 5, lane = tid & 31;
    int wm = warp >> 2, wn = warp & 3;
    int gid = lane >> 2, tig = lane & 3;

    float acc[2][8][4];
    #pragma unroll
    for (int mt = 0; mt < 2; mt++)
        #pragma unroll
        for (int nt = 0; nt < 8; nt++)
            #pragma unroll
            for (int q = 0; q < 4; q++) acc[mt][nt][q] = 0.f;

    auto params = [&](int g, int& kh, int& kw, int& cib,
                      const uint32_t*& sH, const uint32_t*& sL) {
        if (!SECOND) { kh = g / 12; kw = (g >> 2) % 3; cib = g & 3; sH = g_yhi; sL = g_ylo; }
        else if (g < 36) { kh = g / 12; kw = (g >> 2) % 3; cib = g & 3; sH = g_t1hi; sL = g_t1lo; }
        else { kh = 1; kw = 1; cib = g - 36; sH = g_yhi; sL = g_ylo; }
    };
    auto load_stage = [&](char* dst, int g) {
        const unsigned short* src = Wc + (size_t)g * 32768;
        for (int i = tid; i < 4096; i += 512) {
            int c16 = i & 7; int t = i >> 3; int co = t & 255; int part = t >> 8;
            cp16(dst + part * PART_B + co * 144 + c16 * 16,
                 src + (size_t)(part * 256 + co) * 64 + c16 * 8);
        }
        int kh, kw, cib; const uint32_t *sH, *sL;
        params(g, kh, kw, cib, sH, sL);
        int hh = h + kh - 1;
        bool okh = (unsigned)hh < 256u;
        int hc = okh ? hh : 0;
        for (int i = tid; i < 8192; i += 512) {
            int px = i & 127; int t = i >> 7; int j = t & 31; int part = t >> 5;
            int ww = px + kw - 1;
            bool ok = okh && ((unsigned)ww < 128u);
            const uint32_t* sp = part ? sL : sH;
            const uint32_t* s2 = sp + ((((size_t)n * 128 + cib * 32 + j) * 256 + hc) * 128
                                       + (ok ? ww : 0));
            cpa4(dst + A_OFF + part * PART_A + px * 144 + j * 4, s2, ok);
        }
    };

    load_stage(smem, 0);
    cpa_commit();

    for (int g = 0; g < G; g++) {
        if (g + 1 < G) {
            load_stage(smem + ((g + 1) & 1) * STG_BYTES, g + 1);
            cpa_commit();
            cpa_wait<1>();
        } else cpa_wait<0>();
        __syncthreads();

        uint32_t sb = smem_u32(smem + (g & 1) * STG_BYTES);
        uint32_t aB = sb + A_OFF;
        int arow = wm * 32 + (lane & 15);
        int acol = ((lane >> 4) & 1) * 16;
        int brow = wn * 64 + (lane & 7);
        int bcol = ((lane >> 3) & 1) * 16;

        #pragma unroll
        for (int kc = 0; kc < 4; kc++) {
            uint32_t ah[2][4], al[2][4];
            #pragma unroll
            for (int mt = 0; mt < 2; mt++) {
                uint32_t ad = aB + (uint32_t)(arow + mt * 16) * 144 + kc * 32 + acol;
                ldmx4(ah[mt], ad);
                ldmx4(al[mt], ad + PART_A);
            }
            #pragma unroll
            for (int nt = 0; nt < 8; nt++) {
                uint32_t bd = sb + (uint32_t)(brow + nt * 8) * 144 + kc * 32 + bcol;
                uint32_t bh[2], bl[2];
                ldmx2(bh, bd);
                ldmx2(bl, bd + PART_B);
                #pragma unroll
                for (int mt = 0; mt < 2; mt++) {
                    mma16816(acc[mt][nt], ah[mt], bh);
                    mma16816(acc[mt][nt], al[mt], bh);
                    mma16816(acc[mt][nt], ah[mt], bl);
                }
            }
        }
        __syncthreads();
    }

    const float* bsrc = SECOND ? g_b2 : g_b1;
    #pragma unroll
    for (int nt = 0; nt < 8; nt++) {
        int coe = wn * 64 + nt * 8 + 2 * tig;
        float b0 = bsrc[coe], b1 = bsrc[coe + 1];
        #pragma unroll
        for (int mt = 0; mt < 2; mt++) {
            int p0 = wm * 32 + mt * 16 + gid;
            float v00 = fmaxf(acc[mt][nt][0] + b0, 0.f);
            float v01 = fmaxf(acc[mt][nt][1] + b1, 0.f);
            float v10 = fmaxf(acc[mt][nt][2] + b0, 0.f);
            float v11 = fmaxf(acc[mt][nt][3] + b1, 0.f);
            if (SECOND) {
                size_t o0 = (((size_t)n * 256 + coe) * 256 + h) * 128;
                out[o0 + p0] = v00;
                out[o0 + p0 + 8] = v10;
                out[o0 + 32768 + p0] = v01;
                out[o0 + 32768 + p0 + 8] = v11;
            } else {
                unsigned short h0, l0, h1, l1;
                size_t o = (((size_t)n * 128 + (coe >> 1)) * 256 + h) * 128;
                fsplit(v00, h0, l0); fsplit(v01, h1, l1);
                g_t1hi[o + p0] = (uint32_t)h0 | ((uint32_t)h1 << 16);
                g_t1lo[o + p0] = (uint32_t)l0 | ((uint32_t)l1 << 16);
                fsplit(v10, h0, l0); fsplit(v11, h1, l1);
                g_t1hi[o + p0 + 8] = (uint32_t)h0 | ((uint32_t)h1 << 16);
                g_t1lo[o + p0 + 8] = (uint32_t)l0 | ((uint32_t)l1 << 16);
            }
        }
    }
}

// ---------------- launcher ------------------------------------------------------
extern "C" void kernel_launch(void* const* d_in, const int* in_sizes, int n_in,
                              void* d_out, int out_size) {
    const float* x      = (const float*)d_in[0];
    const float* qkv_w  = (const float*)d_in[1];
    const float* qkv_b  = (const float*)d_in[2];
    const float* proj_w = (const float*)d_in[3];
    const float* proj_b = (const float*)d_in[4];
    const float* rpb    = (const float*)d_in[5];
    const float* c1w = (const float*)d_in[6];
    const float* c1b = (const float*)d_in[7];
    const float* b1g = (const float*)d_in[8];
    const float* b1b = (const float*)d_in[9];
    const float* b1m = (const float*)d_in[10];
    const float* b1v = (const float*)d_in[11];
    const float* c2w = (const float*)d_in[12];
    const float* c2b = (const float*)d_in[13];
    const float* b2g = (const float*)d_in[14];
    const float* b2b = (const float*)d_in[15];
    const float* b2m = (const float*)d_in[16];
    const float* b2v = (const float*)d_in[17];
    const float* idw = (const float*)d_in[18];
    const float* idb = (const float*)d_in[19];
    const float* big = (const float*)d_in[20];
    const float* bib = (const float*)d_in[21];
    const float* bim = (const float*)d_in[22];
    const float* biv = (const float*)d_in[23];
    float* out = (float*)d_out;

    cudaFuncSetAttribute(k_qkv, cudaFuncAttributeMaxDynamicSharedMemorySize, 2 * QKV_STG);
    cudaFuncSetAttribute(k_proj, cudaFuncAttributeMaxDynamicSharedMemorySize, 139264);
    cudaFuncSetAttribute(k_conv_tc<0>, cudaFuncAttributeMaxDynamicSharedMemorySize, 2 * STG_BYTES);
    cudaFuncSetAttribute(k_conv_tc<1>, cudaFuncAttributeMaxDynamicSharedMemorySize, 2 * STG_BYTES);

    k_upsample<<<TOT / 256, 256>>>(x);
    k_cvt_wq<<<192, 256>>>(qkv_w, qkv_b);
    k_cvt_wp<<<64, 256>>>(proj_w, proj_b);
    k_cvt_w1<<<2304, 256>>>(c1w, c1b, b1g, b1b, b1m, b1v);
    k_cvt_w2<<<2560, 256>>>(c2w, c2b, b2g, b2b, b2m, b2v,
                            idw, idb, big, bib, bim, biv);
    k_qkv<<<2048, 512, 2 * QKV_STG>>>();
    k_attn_core<<<16384, 128>>>(rpb);
    k_proj<<<2048, 512, 139264>>>();
    k_cvt_y<<<65536, 256>>>();
    k_conv_tc<0><<<1024, 512, 2 * STG_BYTES>>>(out);
    k_conv_tc<1><<<1024, 512, 2 * STG_BYTES>>>(out);
}

// round 10
// speedup vs baseline: 2.8709x; 1.0482x over previous
#include <cuda_runtime.h>
#include <cuda_bf16.h>
#include <cstdint>

#define TOT (4*256*256*128)
static __device__ float g_xu[TOT];                    // upsampled x (B,H,W,C)
static __device__ unsigned short g_xuh[TOT];          // split bf16 of g_xu
static __device__ unsigned short g_xul[TOT];
static __device__ float g_qkv[(size_t)4*256*256*384]; // QKV per shifted pixel
static __device__ unsigned short g_oh[TOT];           // attention out O split (orig coords)
static __device__ unsigned short g_ol[TOT];
static __device__ float g_y[TOT];                     // attention + residual (fp32)
// conv input planes, NEW layout: [n][cib(4)][h(256)][w(128)][j32(32 u32 = ci-pairs)]
static __device__ uint32_t g_yhi[TOT/2];
static __device__ uint32_t g_ylo[TOT/2];
static __device__ uint32_t g_t1hi[TOT/2];
static __device__ uint32_t g_t1lo[TOT/2];
static __device__ unsigned short g_wc1[36*2*256*64];
static __device__ unsigned short g_wc2[40*2*256*64];
static __device__ unsigned short g_wq[2*384*128];     // qkv_w split [part][n][k]
static __device__ unsigned short g_wp[2*128*128];     // proj_w split [part][n][k]
static __device__ float g_b1[256], g_b2[256], g_bq[384], g_bp[128];

// ---------------- helpers -------------------------------------------------------
__device__ __forceinline__ uint32_t smem_u32(const void* p) {
    uint32_t r;
    asm("{ .reg .u64 t; cvta.to.shared.u64 t, %1; cvt.u32.u64 %0, t; }" : "=r"(r) : "l"(p));
    return r;
}
__device__ __forceinline__ void fsplit(float x, unsigned short& h, unsigned short& l) {
    __nv_bfloat16 bh = __float2bfloat16(x);
    float rem = x - __bfloat162float(bh);
    h = __bfloat16_as_ushort(bh);
    l = __bfloat16_as_ushort(__float2bfloat16(rem));
}
__device__ __forceinline__ void cp16(void* dst_smem, const void* src) {
    unsigned d = (unsigned)__cvta_generic_to_shared(dst_smem);
    asm volatile("cp.async.cg.shared.global [%0], [%1], 16;" :: "r"(d), "l"(src));
}
__device__ __forceinline__ void cp16z(void* dst_smem, const void* src, bool valid) {
    unsigned d = (unsigned)__cvta_generic_to_shared(dst_smem);
    int sz = valid ? 16 : 0;
    asm volatile("cp.async.cg.shared.global [%0], [%1], 16, %2;"
                 :: "r"(d), "l"(src), "r"(sz));
}
__device__ __forceinline__ void cpa_commit() { asm volatile("cp.async.commit_group;"); }
template <int N> __device__ __forceinline__ void cpa_wait() {
    asm volatile("cp.async.wait_group %0;" :: "n"(N));
}
__device__ __forceinline__ void ldmx4(uint32_t* r, uint32_t a) {
    asm volatile("ldmatrix.sync.aligned.m8n8.x4.shared.b16 {%0,%1,%2,%3}, [%4];"
                 : "=r"(r[0]), "=r"(r[1]), "=r"(r[2]), "=r"(r[3]) : "r"(a));
}
__device__ __forceinline__ void ldmx2(uint32_t* r, uint32_t a) {
    asm volatile("ldmatrix.sync.aligned.m8n8.x2.shared.b16 {%0,%1}, [%2];"
                 : "=r"(r[0]), "=r"(r[1]) : "r"(a));
}
__device__ __forceinline__ void mma16816(float* d, const uint32_t* a, const uint32_t* b) {
    asm volatile(
        "mma.sync.aligned.m16n8k16.row.col.f32.bf16.bf16.f32 "
        "{%0,%1,%2,%3}, {%4,%5,%6,%7}, {%8,%9}, {%0,%1,%2,%3};"
        : "+f"(d[0]), "+f"(d[1]), "+f"(d[2]), "+f"(d[3])
        : "r"(a[0]), "r"(a[1]), "r"(a[2]), "r"(a[3]), "r"(b[0]), "r"(b[1]));
}

// ---------------- K1: bilinear 2x upsample + bf16 split -------------------------
__global__ void k_upsample(const float* __restrict__ xin) {
    int idx = blockIdx.x * 256 + threadIdx.x;
    int cc = idx & 127;
    int t  = idx >> 7;
    int ww = t & 255; t >>= 8;
    int hh = t & 255;
    int b  = t >> 8;
    float pw = ww * (127.0f / 255.0f);
    int wlo = (int)pw; float fw = pw - (float)wlo; int whi = min(wlo + 1, 127);
    float pc = cc * (63.0f / 127.0f);
    int clo = (int)pc; float fc = pc - (float)clo; int chi = min(clo + 1, 63);
    const float* base = xin + ((b * 256 + hh) * 128) * 64;
    float v00 = base[wlo * 64 + clo], v01 = base[wlo * 64 + chi];
    float v10 = base[whi * 64 + clo], v11 = base[whi * 64 + chi];
    float v = (1.f - fw) * ((1.f - fc) * v00 + fc * v01)
            +        fw  * ((1.f - fc) * v10 + fc * v11);
    g_xu[idx] = v;
    unsigned short h, l;
    fsplit(v, h, l);
    g_xuh[idx] = h;
    g_xul[idx] = l;
}

// ---------------- weight prep ---------------------------------------------------
__global__ void k_cvt_wq(const float* __restrict__ qkv_w, const float* __restrict__ qkv_b) {
    int idx = blockIdx.x * 256 + threadIdx.x;
    if (idx >= 49152) return;
    int k = idx & 127, nn = idx >> 7;
    unsigned short hi, lo;
    fsplit(qkv_w[k * 384 + nn], hi, lo);
    g_wq[nn * 128 + k] = hi;
    g_wq[49152 + nn * 128 + k] = lo;
    if (k == 0) g_bq[nn] = qkv_b[nn];
}
__global__ void k_cvt_wp(const float* __restrict__ proj_w, const float* __restrict__ proj_b) {
    int idx = blockIdx.x * 256 + threadIdx.x;
    if (idx >= 16384) return;
    int k = idx & 127, nn = idx >> 7;
    unsigned short hi, lo;
    fsplit(proj_w[k * 128 + nn], hi, lo);
    g_wp[nn * 128 + k] = hi;
    g_wp[16384 + nn * 128 + k] = lo;
    if (k == 0) g_bp[nn] = proj_b[nn];
}
__global__ void k_cvt_w1(const float* __restrict__ cw, const float* __restrict__ cb,
                         const float* __restrict__ bg, const float* __restrict__ bb,
                         const float* __restrict__ bm, const float* __restrict__ bv) {
    int idx = blockIdx.x * 256 + threadIdx.x;
    if (idx >= 36 * 256 * 64) return;
    int ci = idx & 63;
    int t = idx >> 6;
    int co = t & 255;
    int c = t >> 8;
    int kh = c / 12, kw = (c >> 2) % 3, ci0 = (c & 3) << 6;
    float s = bg[co] * rsqrtf(bv[co] + 1e-5f);
    float wv = cw[((co * 256 + ci0 + ci) * 3 + kh) * 3 + kw] * s;
    unsigned short hi, lo; fsplit(wv, hi, lo);
    g_wc1[((c * 2 + 0) * 256 + co) * 64 + ci] = hi;
    g_wc1[((c * 2 + 1) * 256 + co) * 64 + ci] = lo;
    if (c == 0 && ci == 0) g_b1[co] = cb[co] * s + bb[co] - bm[co] * s;
}
__global__ void k_cvt_w2(const float* __restrict__ cw, const float* __restrict__ cb,
                         const float* __restrict__ bg, const float* __restrict__ bb,
                         const float* __restrict__ bm, const float* __restrict__ bv,
                         const float* __restrict__ iw, const float* __restrict__ ibi,
                         const float* __restrict__ ig, const float* __restrict__ ib2,
                         const float* __restrict__ im, const float* __restrict__ iv) {
    int idx = blockIdx.x * 256 + threadIdx.x;
    if (idx >= 40 * 256 * 64) return;
    int ci = idx & 63;
    int t = idx >> 6;
    int co = t & 255;
    int c = t >> 8;
    float wv;
    if (c < 36) {
        int kh = c / 12, kw = (c >> 2) % 3, ci0 = (c & 3) << 6;
        wv = cw[((co * 256 + ci0 + ci) * 3 + kh) * 3 + kw] * (bg[co] * rsqrtf(bv[co] + 1e-5f));
    } else {
        wv = iw[co * 256 + ((c - 36) << 6) + ci] * (ig[co] * rsqrtf(iv[co] + 1e-5f));
    }
    unsigned short hi, lo; fsplit(wv, hi, lo);
    g_wc2[((c * 2 + 0) * 256 + co) * 64 + ci] = hi;
    g_wc2[((c * 2 + 1) * 256 + co) * 64 + ci] = lo;
    if (c == 0 && ci == 0) {
        float s  = bg[co] * rsqrtf(bv[co] + 1e-5f);
        float si = ig[co] * rsqrtf(iv[co] + 1e-5f);
        g_b2[co] = cb[co] * s + bb[co] - bm[co] * s + ibi[co] * si + ib2[co] - im[co] * si;
    }
}

// ---------------- K-QKV: [262144 x 128] @ [128 x 384] bf16-split mma ------------
#define QKV_STG 81920
__global__ __launch_bounds__(512, 1) void k_qkv() {
    extern __shared__ __align__(16) char smem[];
    int tid = threadIdx.x;
    int blk = blockIdx.x;                    // 2048
    int n = blk >> 9, hs = (blk >> 1) & 255, wb = blk & 1;
    int w0 = wb * 128;
    int h2 = (hs + 3) & 255;
    int warp = tid >> 5, lane = tid & 31;
    int wm = warp >> 2, wn = warp & 3;
    int gid = lane >> 2, tig = lane & 3;

    float acc[2][12][4];
    #pragma unroll
    for (int mt = 0; mt < 2; mt++)
        #pragma unroll
        for (int nt = 0; nt < 12; nt++)
            #pragma unroll
            for (int q = 0; q < 4; q++) acc[mt][nt][q] = 0.f;

    auto load_stage = [&](char* dst, int g) {
        int kc0 = g * 32;
        for (int i = tid; i < 3072; i += 512) {
            int c4 = i & 3; int t = i >> 2; int nr = t % 384; int part = t / 384;
            cp16(dst + part * 30720 + nr * 80 + c4 * 16,
                 g_wq + (size_t)part * 49152 + nr * 128 + kc0 + c4 * 8);
        }
        for (int i = tid; i < 1024; i += 512) {
            int c4 = i & 3; int t = i >> 2; int pr = t & 127; int part = t >> 7;
            int w2 = (w0 + pr + 3) & 255;
            const unsigned short* sp = part ? g_xul : g_xuh;
            cp16(dst + 61440 + part * 10240 + pr * 80 + c4 * 16,
                 sp + (((size_t)n * 256 + h2) * 256 + w2) * 128 + kc0 + c4 * 8);
        }
    };

    load_stage(smem, 0);
    cpa_commit();
    for (int g = 0; g < 4; g++) {
        if (g + 1 < 4) {
            load_stage(smem + ((g + 1) & 1) * QKV_STG, g + 1);
            cpa_commit();
            cpa_wait<1>();
        } else cpa_wait<0>();
        __syncthreads();

        uint32_t sb = smem_u32(smem + (g & 1) * QKV_STG);
        uint32_t aB = sb + 61440;
        int arow = wm * 32 + (lane & 15);
        int acol = ((lane >> 4) & 1) * 16;
        int brow = wn * 96 + (lane & 7);
        int bcol = ((lane >> 3) & 1) * 16;

        #pragma unroll
        for (int kc = 0; kc < 2; kc++) {
            uint32_t ah[2][4], al[2][4];
            #pragma unroll
            for (int mt = 0; mt < 2; mt++) {
                uint32_t ad = aB + (uint32_t)(arow + mt * 16) * 80 + kc * 32 + acol;
                ldmx4(ah[mt], ad);
                ldmx4(al[mt], ad + 10240);
            }
            #pragma unroll
            for (int nt = 0; nt < 12; nt++) {
                uint32_t bd = sb + (uint32_t)(brow + nt * 8) * 80 + kc * 32 + bcol;
                uint32_t bh[2], bl[2];
                ldmx2(bh, bd);
                ldmx2(bl, bd + 30720);
                #pragma unroll
                for (int mt = 0; mt < 2; mt++) {
                    mma16816(acc[mt][nt], ah[mt], bh);
                    mma16816(acc[mt][nt], al[mt], bh);
                    mma16816(acc[mt][nt], ah[mt], bl);
                }
            }
        }
        __syncthreads();
    }

    size_t pbase = ((size_t)n * 256 + hs) * 256 + w0;
    #pragma unroll
    for (int nt = 0; nt < 12; nt++) {
        int col = wn * 96 + nt * 8 + 2 * tig;
        float b0 = g_bq[col], b1 = g_bq[col + 1];
        float sc = (col < 128) ? 0.17677669529663687f : 1.f;
        #pragma unroll
        for (int mt = 0; mt < 2; mt++) {
            int r0 = wm * 32 + mt * 16 + gid;
            float2 v0 = make_float2((acc[mt][nt][0] + b0) * sc, (acc[mt][nt][1] + b1) * sc);
            float2 v1 = make_float2((acc[mt][nt][2] + b0) * sc, (acc[mt][nt][3] + b1) * sc);
            *(float2*)&g_qkv[(pbase + r0) * 384 + col] = v0;
            *(float2*)&g_qkv[(pbase + r0 + 8) * 384 + col] = v1;
        }
    }
}

// ---------------- attention core: scores/softmax/PV per window ------------------
__global__ __launch_bounds__(128) void k_attn_core(const float* __restrict__ rpb) {
    __shared__ float QKV[16][384];
    __shared__ float P[4][16][16];
    __shared__ float O[16][128];
    int tid = threadIdx.x, blk = blockIdx.x;
    int n = blk >> 12, widx = blk & 4095, wh = widx >> 6, wc = widx & 63;

    for (int idx = tid; idx < 6144; idx += 128) {
        int t = idx / 384, c = idx - t * 384;
        size_t ps = ((size_t)n * 256 + wh * 4 + (t >> 2)) * 256 + wc * 4 + (t & 3);
        QKV[t][c] = g_qkv[ps * 384 + c];
    }
    __syncthreads();

    int warp = tid >> 5, lane = tid & 31;
    if (lane < 16) {
        int t = lane, h = warp;
        float q[32];
        #pragma unroll
        for (int d = 0; d < 32; d++) q[d] = QKV[t][h * 32 + d];
        int i1 = t >> 2, j1 = t & 3;
        int rh1 = wh * 4 + i1, rw1 = wc * 4 + j1;
        int l1 = ((rh1 < 252) ? 0 : ((rh1 < 253) ? 1 : 2)) * 3
               + ((rw1 < 252) ? 0 : ((rw1 < 253) ? 1 : 2));
        float s[16], mx = -1e30f;
        #pragma unroll
        for (int u = 0; u < 16; u++) {
            float dot = 0.f;
            #pragma unroll
            for (int d = 0; d < 32; d++) dot += q[d] * QKV[u][128 + h * 32 + d];
            int i2 = u >> 2, j2 = u & 3;
            dot += rpb[((i1 - i2 + 3) * 7 + (j1 - j2 + 3)) * 4 + h];
            int rh2 = wh * 4 + i2, rw2 = wc * 4 + j2;
            int l2 = ((rh2 < 252) ? 0 : ((rh2 < 253) ? 1 : 2)) * 3
                   + ((rw2 < 252) ? 0 : ((rw2 < 253) ? 1 : 2));
            if (l1 != l2) dot -= 100.f;
            s[u] = dot; mx = fmaxf(mx, dot);
        }
        float sum = 0.f;
        #pragma unroll
        for (int u = 0; u < 16; u++) { s[u] = __expf(s[u] - mx); sum += s[u]; }
        float inv = 1.f / sum;
        #pragma unroll
        for (int u = 0; u < 16; u++) P[h][t][u] = s[u] * inv;
    }
    __syncwarp();
    {
        int h = warp, d = lane;
        #pragma unroll
        for (int t = 0; t < 16; t++) {
            float acc = 0.f;
            #pragma unroll
            for (int u = 0; u < 16; u++) acc += P[h][t][u] * QKV[u][256 + h * 32 + d];
            O[t][h * 32 + d] = acc;
        }
    }
    __syncthreads();

    int t = tid >> 3, c0 = (tid & 7) * 16;
    int hs = wh * 4 + (t >> 2), ws = wc * 4 + (t & 3);
    int hh2 = (hs + 3) & 255, ww2 = (ws + 3) & 255;
    size_t po = (((size_t)n * 256 + hh2) * 256 + ww2) * 128;
    #pragma unroll
    for (int c = 0; c < 16; c++) {
        unsigned short h, l;
        fsplit(O[t][c0 + c], h, l);
        g_oh[po + c0 + c] = h;
        g_ol[po + c0 + c] = l;
    }
}

// ---------------- K-proj: [262144 x 128] @ [128 x 128] + bias + residual --------
__global__ __launch_bounds__(512, 1) void k_proj() {
    extern __shared__ __align__(16) char smem[];
    int tid = threadIdx.x;
    int blk = blockIdx.x;
    size_t p0 = (size_t)blk * 128;
    int warp = tid >> 5, lane = tid & 31;
    int wm = warp >> 2, wn = warp & 3;
    int gid = lane >> 2, tig = lane & 3;

    for (int i = tid; i < 4096; i += 512) {
        int c16 = i & 15; int t = i >> 4; int nr = t & 127; int part = t >> 7;
        cp16(smem + part * 34816 + nr * 272 + c16 * 16,
             g_wp + (size_t)part * 16384 + nr * 128 + c16 * 8);
    }
    for (int i = tid; i < 4096; i += 512) {
        int c16 = i & 15; int t = i >> 4; int pr = t & 127; int part = t >> 7;
        const unsigned short* sp = part ? g_ol : g_oh;
        cp16(smem + 69632 + part * 34816 + pr * 272 + c16 * 16,
             sp + (p0 + pr) * 128 + c16 * 8);
    }
    cpa_commit();
    cpa_wait<0>();
    __syncthreads();

    float acc[2][4][4];
    #pragma unroll
    for (int mt = 0; mt < 2; mt++)
        #pragma unroll
        for (int nt = 0; nt < 4; nt++)
            #pragma unroll
            for (int q = 0; q < 4; q++) acc[mt][nt][q] = 0.f;

    uint32_t sb = smem_u32(smem);
    uint32_t aB = sb + 69632;
    int arow = wm * 32 + (lane & 15);
    int acol = ((lane >> 4) & 1) * 16;
    int brow = wn * 32 + (lane & 7);
    int bcol = ((lane >> 3) & 1) * 16;

    #pragma unroll
    for (int kc = 0; kc < 8; kc++) {
        uint32_t ah[2][4], al[2][4];
        #pragma unroll
        for (int mt = 0; mt < 2; mt++) {
            uint32_t ad = aB + (uint32_t)(arow + mt * 16) * 272 + kc * 32 + acol;
            ldmx4(ah[mt], ad);
            ldmx4(al[mt], ad + 34816);
        }
        #pragma unroll
        for (int nt = 0; nt < 4; nt++) {
            uint32_t bd = sb + (uint32_t)(brow + nt * 8) * 272 + kc * 32 + bcol;
            uint32_t bh[2], bl[2];
            ldmx2(bh, bd);
            ldmx2(bl, bd + 34816);
            #pragma unroll
            for (int mt = 0; mt < 2; mt++) {
                mma16816(acc[mt][nt], ah[mt], bh);
                mma16816(acc[mt][nt], al[mt], bh);
                mma16816(acc[mt][nt], ah[mt], bl);
            }
        }
    }

    #pragma unroll
    for (int nt = 0; nt < 4; nt++) {
        int coe = wn * 32 + nt * 8 + 2 * tig;
        float b0 = g_bp[coe], b1 = g_bp[coe + 1];
        #pragma unroll
        for (int mt = 0; mt < 2; mt++) {
            #pragma unroll
            for (int half = 0; half < 2; half++) {
                size_t p = p0 + wm * 32 + mt * 16 + gid + half * 8;
                float2 res = *(const float2*)&g_xu[p * 128 + coe];
                float v0 = acc[mt][nt][half * 2 + 0] + b0 + res.x;
                float v1 = acc[mt][nt][half * 2 + 1] + b1 + res.y;
                *(float2*)&g_y[p * 128 + coe] = make_float2(v0, v1);
            }
        }
    }
}

// ---------------- K-cvt-y: pack fp32 y into conv planes (smem transpose) --------
// Block = (n, cib, conv h). Planes layout [n][cib][h][w(128)][j32(32)].
__global__ __launch_bounds__(256) void k_cvt_y() {
    __shared__ unsigned short sh[8192];   // [ch(64)][w(128)]
    __shared__ unsigned short sl[8192];
    int blk = blockIdx.x;                 // 4096 = 4*4*256
    int h = blk & 255;                    // conv h = attention w
    int cib = (blk >> 8) & 3;
    int n = blk >> 10;
    int tid = threadIdx.x;

    // read 64 conv-channels (= attention h rows cib*64 .. +63), 128 w each
    for (int i = tid; i < 8192; i += 256) {
        int ch = i >> 7, w = i & 127;
        float v = g_y[(((size_t)n * 256 + cib * 64 + ch) * 256 + h) * 128 + w];
        unsigned short hi, lo;
        fsplit(v, hi, lo);
        sh[ch * 128 + w] = hi;
        sl[ch * 128 + w] = lo;
    }
    __syncthreads();

    // write [w][j] coalesced: out word j packs channels (2j, 2j+1)
    size_t base = (((size_t)(n * 4 + cib) * 256 + h) * 128) * 32;
    for (int o = tid; o < 4096; o += 256) {
        int w = o >> 5, j = o & 31;
        uint32_t hi = (uint32_t)sh[(2 * j) * 128 + w] | ((uint32_t)sh[(2 * j + 1) * 128 + w] << 16);
        uint32_t lo = (uint32_t)sl[(2 * j) * 128 + w] | ((uint32_t)sl[(2 * j + 1) * 128 + w] << 16);
        g_yhi[base + o] = hi;
        g_ylo[base + o] = lo;
    }
}

// ---------------- conv kernels: coalesced A staging (new plane layout) ----------
#define STG_BYTES 110592
#define A_OFF     73728
#define PART_B    36864
#define PART_A    18432
template <int SECOND>
__global__ __launch_bounds__(512, 1) void k_conv_tc(float* __restrict__ out) {
    extern __shared__ __align__(16) char smem[];
    const int G = SECOND ? 40 : 36;
    const unsigned short* Wc = SECOND ? g_wc2 : g_wc1;

    int tid = threadIdx.x;
    int n = blockIdx.x >> 8, h = blockIdx.x & 255;
    int warp = tid >> 5, lane = tid & 31;
    int wm = warp >> 2, wn = warp & 3;
    int gid = lane >> 2, tig = lane & 3;

    float acc[2][8][4];
    #pragma unroll
    for (int mt = 0; mt < 2; mt++)
        #pragma unroll
        for (int nt = 0; nt < 8; nt++)
            #pragma unroll
            for (int q = 0; q < 4; q++) acc[mt][nt][q] = 0.f;

    auto params = [&](int g, int& kh, int& kw, int& cib,
                      const uint32_t*& sH, const uint32_t*& sL) {
        if (!SECOND) { kh = g / 12; kw = (g >> 2) % 3; cib = g & 3; sH = g_yhi; sL = g_ylo; }
        else if (g < 36) { kh = g / 12; kw = (g >> 2) % 3; cib = g & 3; sH = g_t1hi; sL = g_t1lo; }
        else { kh = 1; kw = 1; cib = g - 36; sH = g_yhi; sL = g_ylo; }
    };
    auto load_stage = [&](char* dst, int g) {
        const unsigned short* src = Wc + (size_t)g * 32768;
        for (int i = tid; i < 4096; i += 512) {
            int c16 = i & 7; int t = i >> 3; int co = t & 255; int part = t >> 8;
            cp16(dst + part * PART_B + co * 144 + c16 * 16,
                 src + (size_t)(part * 256 + co) * 64 + c16 * 8);
        }
        int kh, kw, cib; const uint32_t *sH, *sL;
        params(g, kh, kw, cib, sH, sL);
        int hh = h + kh - 1;
        bool okh = (unsigned)hh < 256u;
        int hc = okh ? hh : 0;
        // A: [part][px] rows of 128B contiguous in the plane
        for (int i = tid; i < 2048; i += 512) {
            int c16 = i & 7; int t = i >> 3; int px = t & 127; int part = t >> 7;
            int ww = px + kw - 1;
            bool ok = okh && ((unsigned)ww < 128u);
            const uint32_t* sp = part ? sL : sH;
            const uint32_t* s2 = sp + ((((size_t)(n * 4 + cib) * 256 + hc) * 128
                                        + (ok ? ww : 0)) * 32 + c16 * 4);
            cp16z(dst + A_OFF + part * PART_A + px * 144 + c16 * 16, s2, ok);
        }
    };

    load_stage(smem, 0);
    cpa_commit();

    for (int g = 0; g < G; g++) {
        if (g + 1 < G) {
            load_stage(smem + ((g + 1) & 1) * STG_BYTES, g + 1);
            cpa_commit();
            cpa_wait<1>();
        } else cpa_wait<0>();
        __syncthreads();

        uint32_t sb = smem_u32(smem + (g & 1) * STG_BYTES);
        uint32_t aB = sb + A_OFF;
        int arow = wm * 32 + (lane & 15);
        int acol = ((lane >> 4) & 1) * 16;
        int brow = wn * 64 + (lane & 7);
        int bcol = ((lane >> 3) & 1) * 16;

        #pragma unroll
        for (int kc = 0; kc < 4; kc++) {
            uint32_t ah[2][4], al[2][4];
            #pragma unroll
            for (int mt = 0; mt < 2; mt++) {
                uint32_t ad = aB + (uint32_t)(arow + mt * 16) * 144 + kc * 32 + acol;
                ldmx4(ah[mt], ad);
                ldmx4(al[mt], ad + PART_A);
            }
            #pragma unroll
            for (int nt = 0; nt < 8; nt++) {
                uint32_t bd = sb + (uint32_t)(brow + nt * 8) * 144 + kc * 32 + bcol;
                uint32_t bh[2], bl[2];
                ldmx2(bh, bd);
                ldmx2(bl, bd + PART_B);
                #pragma unroll
                for (int mt = 0; mt < 2; mt++) {
                    mma16816(acc[mt][nt], ah[mt], bh);
                    mma16816(acc[mt][nt], al[mt], bh);
                    mma16816(acc[mt][nt], ah[mt], bl);
                }
            }
        }
        __syncthreads();
    }

    const float* bsrc = SECOND ? g_b2 : g_b1;
    #pragma unroll
    for (int nt = 0; nt < 8; nt++) {
        int coe = wn * 64 + nt * 8 + 2 * tig;
        float b0 = bsrc[coe], b1 = bsrc[coe + 1];
        int j = coe >> 1;                           // output channel-pair index
        #pragma unroll
        for (int mt = 0; mt < 2; mt++) {
            int p0 = wm * 32 + mt * 16 + gid;
            float v00 = fmaxf(acc[mt][nt][0] + b0, 0.f);
            float v01 = fmaxf(acc[mt][nt][1] + b1, 0.f);
            float v10 = fmaxf(acc[mt][nt][2] + b0, 0.f);
            float v11 = fmaxf(acc[mt][nt][3] + b1, 0.f);
            if (SECOND) {
                size_t o0 = (((size_t)n * 256 + coe) * 256 + h) * 128;
                out[o0 + p0] = v00;
                out[o0 + p0 + 8] = v10;
                out[o0 + 32768 + p0] = v01;
                out[o0 + 32768 + p0 + 8] = v11;
            } else {
                // new plane layout: ((n*4 + j/32)*256 + h)*128*32 + px*32 + (j&31)
                size_t ob = (((size_t)(n * 4 + (j >> 5)) * 256 + h) * 128) * 32 + (j & 31);
                unsigned short h0, l0, h1, l1;
                fsplit(v00, h0, l0); fsplit(v01, h1, l1);
                g_t1hi[ob + (size_t)p0 * 32] = (uint32_t)h0 | ((uint32_t)h1 << 16);
                g_t1lo[ob + (size_t)p0 * 32] = (uint32_t)l0 | ((uint32_t)l1 << 16);
                fsplit(v10, h0, l0); fsplit(v11, h1, l1);
                g_t1hi[ob + (size_t)(p0 + 8) * 32] = (uint32_t)h0 | ((uint32_t)h1 << 16);
                g_t1lo[ob + (size_t)(p0 + 8) * 32] = (uint32_t)l0 | ((uint32_t)l1 << 16);
            }
        }
    }
}

// ---------------- launcher ------------------------------------------------------
extern "C" void kernel_launch(void* const* d_in, const int* in_sizes, int n_in,
                              void* d_out, int out_size) {
    const float* x      = (const float*)d_in[0];
    const float* qkv_w  = (const float*)d_in[1];
    const float* qkv_b  = (const float*)d_in[2];
    const float* proj_w = (const float*)d_in[3];
    const float* proj_b = (const float*)d_in[4];
    const float* rpb    = (const float*)d_in[5];
    const float* c1w = (const float*)d_in[6];
    const float* c1b = (const float*)d_in[7];
    const float* b1g = (const float*)d_in[8];
    const float* b1b = (const float*)d_in[9];
    const float* b1m = (const float*)d_in[10];
    const float* b1v = (const float*)d_in[11];
    const float* c2w = (const float*)d_in[12];
    const float* c2b = (const float*)d_in[13];
    const float* b2g = (const float*)d_in[14];
    const float* b2b = (const float*)d_in[15];
    const float* b2m = (const float*)d_in[16];
    const float* b2v = (const float*)d_in[17];
    const float* idw = (const float*)d_in[18];
    const float* idb = (const float*)d_in[19];
    const float* big = (const float*)d_in[20];
    const float* bib = (const float*)d_in[21];
    const float* bim = (const float*)d_in[22];
    const float* biv = (const float*)d_in[23];
    float* out = (float*)d_out;

    cudaFuncSetAttribute(k_qkv, cudaFuncAttributeMaxDynamicSharedMemorySize, 2 * QKV_STG);
    cudaFuncSetAttribute(k_proj, cudaFuncAttributeMaxDynamicSharedMemorySize, 139264);
    cudaFuncSetAttribute(k_conv_tc<0>, cudaFuncAttributeMaxDynamicSharedMemorySize, 2 * STG_BYTES);
    cudaFuncSetAttribute(k_conv_tc<1>, cudaFuncAttributeMaxDynamicSharedMemorySize, 2 * STG_BYTES);

    k_upsample<<<TOT / 256, 256>>>(x);
    k_cvt_wq<<<192, 256>>>(qkv_w, qkv_b);
    k_cvt_wp<<<64, 256>>>(proj_w, proj_b);
    k_cvt_w1<<<2304, 256>>>(c1w, c1b, b1g, b1b, b1m, b1v);
    k_cvt_w2<<<2560, 256>>>(c2w, c2b, b2g, b2b, b2m, b2v,
                            idw, idb, big, bib, bim, biv);
    k_qkv<<<2048, 512, 2 * QKV_STG>>>();
    k_attn_core<<<16384, 128>>>(rpb);
    k_proj<<<2048, 512, 139264>>>();
    k_cvt_y<<<4096, 256>>>();
    k_conv_tc<0><<<1024, 512, 2 * STG_BYTES>>>(out);
    k_conv_tc<1><<<1024, 512, 2 * STG_BYTES>>>(out);
}

// round 11
// speedup vs baseline: 2.9116x; 1.0142x over previous
#include <cuda_runtime.h>
#include <cuda_bf16.h>
#include <cstdint>

#define TOT (4*256*256*128)
static __device__ float g_xu[TOT];                    // upsampled x (B,H,W,C)
static __device__ unsigned short g_xuh[TOT];          // split bf16 of g_xu
static __device__ unsigned short g_xul[TOT];
static __device__ float g_qkv[(size_t)4*256*256*384]; // QKV per shifted pixel
static __device__ unsigned short g_oh[TOT];           // attention out O split (orig coords)
static __device__ unsigned short g_ol[TOT];
static __device__ float g_y[TOT];                     // attention + residual (fp32)
// conv input planes: [n][cib(4)][h(256)][w(128)][j32(32 u32 = ci-pairs)]
static __device__ uint32_t g_yhi[TOT/2];
static __device__ uint32_t g_ylo[TOT/2];
static __device__ uint32_t g_t1hi[TOT/2];
static __device__ uint32_t g_t1lo[TOT/2];
static __device__ unsigned short g_wc1[36*2*256*64];
static __device__ unsigned short g_wc2[40*2*256*64];
static __device__ unsigned short g_wq[2*384*128];     // qkv_w split [part][n][k]
static __device__ unsigned short g_wp[2*128*128];     // proj_w split [part][n][k]
static __device__ float g_b1[256], g_b2[256], g_bq[384], g_bp[128];

// ---------------- helpers -------------------------------------------------------
__device__ __forceinline__ uint32_t smem_u32(const void* p) {
    uint32_t r;
    asm("{ .reg .u64 t; cvta.to.shared.u64 t, %1; cvt.u32.u64 %0, t; }" : "=r"(r) : "l"(p));
    return r;
}
__device__ __forceinline__ void fsplit(float x, unsigned short& h, unsigned short& l) {
    __nv_bfloat16 bh = __float2bfloat16(x);
    float rem = x - __bfloat162float(bh);
    h = __bfloat16_as_ushort(bh);
    l = __bfloat16_as_ushort(__float2bfloat16(rem));
}
__device__ __forceinline__ void cp16(void* dst_smem, const void* src) {
    unsigned d = (unsigned)__cvta_generic_to_shared(dst_smem);
    asm volatile("cp.async.cg.shared.global [%0], [%1], 16;" :: "r"(d), "l"(src));
}
__device__ __forceinline__ void cp16z(void* dst_smem, const void* src, bool valid) {
    unsigned d = (unsigned)__cvta_generic_to_shared(dst_smem);
    int sz = valid ? 16 : 0;
    asm volatile("cp.async.cg.shared.global [%0], [%1], 16, %2;"
                 :: "r"(d), "l"(src), "r"(sz));
}
__device__ __forceinline__ void cpa_commit() { asm volatile("cp.async.commit_group;"); }
template <int N> __device__ __forceinline__ void cpa_wait() {
    asm volatile("cp.async.wait_group %0;" :: "n"(N));
}
__device__ __forceinline__ void ldmx4(uint32_t* r, uint32_t a) {
    asm volatile("ldmatrix.sync.aligned.m8n8.x4.shared.b16 {%0,%1,%2,%3}, [%4];"
                 : "=r"(r[0]), "=r"(r[1]), "=r"(r[2]), "=r"(r[3]) : "r"(a));
}
__device__ __forceinline__ void ldmx2(uint32_t* r, uint32_t a) {
    asm volatile("ldmatrix.sync.aligned.m8n8.x2.shared.b16 {%0,%1}, [%2];"
                 : "=r"(r[0]), "=r"(r[1]) : "r"(a));
}
__device__ __forceinline__ void mma16816(float* d, const uint32_t* a, const uint32_t* b) {
    asm volatile(
        "mma.sync.aligned.m16n8k16.row.col.f32.bf16.bf16.f32 "
        "{%0,%1,%2,%3}, {%4,%5,%6,%7}, {%8,%9}, {%0,%1,%2,%3};"
        : "+f"(d[0]), "+f"(d[1]), "+f"(d[2]), "+f"(d[3])
        : "r"(a[0]), "r"(a[1]), "r"(a[2]), "r"(a[3]), "r"(b[0]), "r"(b[1]));
}

// ---------------- K1: bilinear 2x upsample + bf16 split -------------------------
__global__ void k_upsample(const float* __restrict__ xin) {
    int idx = blockIdx.x * 256 + threadIdx.x;
    int cc = idx & 127;
    int t  = idx >> 7;
    int ww = t & 255; t >>= 8;
    int hh = t & 255;
    int b  = t >> 8;
    float pw = ww * (127.0f / 255.0f);
    int wlo = (int)pw; float fw = pw - (float)wlo; int whi = min(wlo + 1, 127);
    float pc = cc * (63.0f / 127.0f);
    int clo = (int)pc; float fc = pc - (float)clo; int chi = min(clo + 1, 63);
    const float* base = xin + ((b * 256 + hh) * 128) * 64;
    float v00 = base[wlo * 64 + clo], v01 = base[wlo * 64 + chi];
    float v10 = base[whi * 64 + clo], v11 = base[whi * 64 + chi];
    float v = (1.f - fw) * ((1.f - fc) * v00 + fc * v01)
            +        fw  * ((1.f - fc) * v10 + fc * v11);
    g_xu[idx] = v;
    unsigned short h, l;
    fsplit(v, h, l);
    g_xuh[idx] = h;
    g_xul[idx] = l;
}

// ---------------- weight prep ---------------------------------------------------
__global__ void k_cvt_wq(const float* __restrict__ qkv_w, const float* __restrict__ qkv_b) {
    int idx = blockIdx.x * 256 + threadIdx.x;
    if (idx >= 49152) return;
    int k = idx & 127, nn = idx >> 7;
    unsigned short hi, lo;
    fsplit(qkv_w[k * 384 + nn], hi, lo);
    g_wq[nn * 128 + k] = hi;
    g_wq[49152 + nn * 128 + k] = lo;
    if (k == 0) g_bq[nn] = qkv_b[nn];
}
__global__ void k_cvt_wp(const float* __restrict__ proj_w, const float* __restrict__ proj_b) {
    int idx = blockIdx.x * 256 + threadIdx.x;
    if (idx >= 16384) return;
    int k = idx & 127, nn = idx >> 7;
    unsigned short hi, lo;
    fsplit(proj_w[k * 128 + nn], hi, lo);
    g_wp[nn * 128 + k] = hi;
    g_wp[16384 + nn * 128 + k] = lo;
    if (k == 0) g_bp[nn] = proj_b[nn];
}
__global__ void k_cvt_w1(const float* __restrict__ cw, const float* __restrict__ cb,
                         const float* __restrict__ bg, const float* __restrict__ bb,
                         const float* __restrict__ bm, const float* __restrict__ bv) {
    int idx = blockIdx.x * 256 + threadIdx.x;
    if (idx >= 36 * 256 * 64) return;
    int ci = idx & 63;
    int t = idx >> 6;
    int co = t & 255;
    int c = t >> 8;
    int kh = c / 12, kw = (c >> 2) % 3, ci0 = (c & 3) << 6;
    float s = bg[co] * rsqrtf(bv[co] + 1e-5f);
    float wv = cw[((co * 256 + ci0 + ci) * 3 + kh) * 3 + kw] * s;
    unsigned short hi, lo; fsplit(wv, hi, lo);
    g_wc1[((c * 2 + 0) * 256 + co) * 64 + ci] = hi;
    g_wc1[((c * 2 + 1) * 256 + co) * 64 + ci] = lo;
    if (c == 0 && ci == 0) g_b1[co] = cb[co] * s + bb[co] - bm[co] * s;
}
__global__ void k_cvt_w2(const float* __restrict__ cw, const float* __restrict__ cb,
                         const float* __restrict__ bg, const float* __restrict__ bb,
                         const float* __restrict__ bm, const float* __restrict__ bv,
                         const float* __restrict__ iw, const float* __restrict__ ibi,
                         const float* __restrict__ ig, const float* __restrict__ ib2,
                         const float* __restrict__ im, const float* __restrict__ iv) {
    int idx = blockIdx.x * 256 + threadIdx.x;
    if (idx >= 40 * 256 * 64) return;
    int ci = idx & 63;
    int t = idx >> 6;
    int co = t & 255;
    int c = t >> 8;
    float wv;
    if (c < 36) {
        int kh = c / 12, kw = (c >> 2) % 3, ci0 = (c & 3) << 6;
        wv = cw[((co * 256 + ci0 + ci) * 3 + kh) * 3 + kw] * (bg[co] * rsqrtf(bv[co] + 1e-5f));
    } else {
        wv = iw[co * 256 + ((c - 36) << 6) + ci] * (ig[co] * rsqrtf(iv[co] + 1e-5f));
    }
    unsigned short hi, lo; fsplit(wv, hi, lo);
    g_wc2[((c * 2 + 0) * 256 + co) * 64 + ci] = hi;
    g_wc2[((c * 2 + 1) * 256 + co) * 64 + ci] = lo;
    if (c == 0 && ci == 0) {
        float s  = bg[co] * rsqrtf(bv[co] + 1e-5f);
        float si = ig[co] * rsqrtf(iv[co] + 1e-5f);
        g_b2[co] = cb[co] * s + bb[co] - bm[co] * s + ibi[co] * si + ib2[co] - im[co] * si;
    }
}

// ---------------- K-QKV: [262144 x 128] @ [128 x 384] bf16-split mma ------------
#define QKV_STG 81920
__global__ __launch_bounds__(512, 1) void k_qkv() {
    extern __shared__ __align__(16) char smem[];
    int tid = threadIdx.x;
    int blk = blockIdx.x;                    // 2048
    int n = blk >> 9, hs = (blk >> 1) & 255, wb = blk & 1;
    int w0 = wb * 128;
    int h2 = (hs + 3) & 255;
    int warp = tid >> 5, lane = tid & 31;
    int wm = warp >> 2, wn = warp & 3;
    int gid = lane >> 2, tig = lane & 3;

    float acc[2][12][4];
    #pragma unroll
    for (int mt = 0; mt < 2; mt++)
        #pragma unroll
        for (int nt = 0; nt < 12; nt++)
            #pragma unroll
            for (int q = 0; q < 4; q++) acc[mt][nt][q] = 0.f;

    auto load_stage = [&](char* dst, int g) {
        int kc0 = g * 32;
        for (int i = tid; i < 3072; i += 512) {
            int c4 = i & 3; int t = i >> 2; int nr = t % 384; int part = t / 384;
            cp16(dst + part * 30720 + nr * 80 + c4 * 16,
                 g_wq + (size_t)part * 49152 + nr * 128 + kc0 + c4 * 8);
        }
        for (int i = tid; i < 1024; i += 512) {
            int c4 = i & 3; int t = i >> 2; int pr = t & 127; int part = t >> 7;
            int w2 = (w0 + pr + 3) & 255;
            const unsigned short* sp = part ? g_xul : g_xuh;
            cp16(dst + 61440 + part * 10240 + pr * 80 + c4 * 16,
                 sp + (((size_t)n * 256 + h2) * 256 + w2) * 128 + kc0 + c4 * 8);
        }
    };

    load_stage(smem, 0);
    cpa_commit();
    for (int g = 0; g < 4; g++) {
        if (g + 1 < 4) {
            load_stage(smem + ((g + 1) & 1) * QKV_STG, g + 1);
            cpa_commit();
            cpa_wait<1>();
        } else cpa_wait<0>();
        __syncthreads();

        uint32_t sb = smem_u32(smem + (g & 1) * QKV_STG);
        uint32_t aB = sb + 61440;
        int arow = wm * 32 + (lane & 15);
        int acol = ((lane >> 4) & 1) * 16;
        int brow = wn * 96 + (lane & 7);
        int bcol = ((lane >> 3) & 1) * 16;

        #pragma unroll
        for (int kc = 0; kc < 2; kc++) {
            uint32_t ah[2][4], al[2][4];
            #pragma unroll
            for (int mt = 0; mt < 2; mt++) {
                uint32_t ad = aB + (uint32_t)(arow + mt * 16) * 80 + kc * 32 + acol;
                ldmx4(ah[mt], ad);
                ldmx4(al[mt], ad + 10240);
            }
            #pragma unroll
            for (int nt = 0; nt < 12; nt++) {
                uint32_t bd = sb + (uint32_t)(brow + nt * 8) * 80 + kc * 32 + bcol;
                uint32_t bh[2], bl[2];
                ldmx2(bh, bd);
                ldmx2(bl, bd + 30720);
                #pragma unroll
                for (int mt = 0; mt < 2; mt++) {
                    mma16816(acc[mt][nt], ah[mt], bh);
                    mma16816(acc[mt][nt], al[mt], bh);
                    mma16816(acc[mt][nt], ah[mt], bl);
                }
            }
        }
        __syncthreads();
    }

    size_t pbase = ((size_t)n * 256 + hs) * 256 + w0;
    #pragma unroll
    for (int nt = 0; nt < 12; nt++) {
        int col = wn * 96 + nt * 8 + 2 * tig;
        float b0 = g_bq[col], b1 = g_bq[col + 1];
        float sc = (col < 128) ? 0.17677669529663687f : 1.f;
        #pragma unroll
        for (int mt = 0; mt < 2; mt++) {
            int r0 = wm * 32 + mt * 16 + gid;
            float2 v0 = make_float2((acc[mt][nt][0] + b0) * sc, (acc[mt][nt][1] + b1) * sc);
            float2 v1 = make_float2((acc[mt][nt][2] + b0) * sc, (acc[mt][nt][3] + b1) * sc);
            *(float2*)&g_qkv[(pbase + r0) * 384 + col] = v0;
            *(float2*)&g_qkv[(pbase + r0 + 8) * 384 + col] = v1;
        }
    }
}

// ---------------- attention core: scores/softmax/PV per window ------------------
__global__ __launch_bounds__(128) void k_attn_core(const float* __restrict__ rpb) {
    __shared__ float QKV[16][384];
    __shared__ float P[4][16][16];
    __shared__ float O[16][128];
    int tid = threadIdx.x, blk = blockIdx.x;
    int n = blk >> 12, widx = blk & 4095, wh = widx >> 6, wc = widx & 63;

    for (int idx = tid; idx < 6144; idx += 128) {
        int t = idx / 384, c = idx - t * 384;
        size_t ps = ((size_t)n * 256 + wh * 4 + (t >> 2)) * 256 + wc * 4 + (t & 3);
        QKV[t][c] = g_qkv[ps * 384 + c];
    }
    __syncthreads();

    int warp = tid >> 5, lane = tid & 31;
    if (lane < 16) {
        int t = lane, h = warp;
        float q[32];
        #pragma unroll
        for (int d = 0; d < 32; d++) q[d] = QKV[t][h * 32 + d];
        int i1 = t >> 2, j1 = t & 3;
        int rh1 = wh * 4 + i1, rw1 = wc * 4 + j1;
        int l1 = ((rh1 < 252) ? 0 : ((rh1 < 253) ? 1 : 2)) * 3
               + ((rw1 < 252) ? 0 : ((rw1 < 253) ? 1 : 2));
        float s[16], mx = -1e30f;
        #pragma unroll
        for (int u = 0; u < 16; u++) {
            float dot = 0.f;
            #pragma unroll
            for (int d = 0; d < 32; d++) dot += q[d] * QKV[u][128 + h * 32 + d];
            int i2 = u >> 2, j2 = u & 3;
            dot += rpb[((i1 - i2 + 3) * 7 + (j1 - j2 + 3)) * 4 + h];
            int rh2 = wh * 4 + i2, rw2 = wc * 4 + j2;
            int l2 = ((rh2 < 252) ? 0 : ((rh2 < 253) ? 1 : 2)) * 3
                   + ((rw2 < 252) ? 0 : ((rw2 < 253) ? 1 : 2));
            if (l1 != l2) dot -= 100.f;
            s[u] = dot; mx = fmaxf(mx, dot);
        }
        float sum = 0.f;
        #pragma unroll
        for (int u = 0; u < 16; u++) { s[u] = __expf(s[u] - mx); sum += s[u]; }
        float inv = 1.f / sum;
        #pragma unroll
        for (int u = 0; u < 16; u++) P[h][t][u] = s[u] * inv;
    }
    __syncwarp();
    {
        int h = warp, d = lane;
        #pragma unroll
        for (int t = 0; t < 16; t++) {
            float acc = 0.f;
            #pragma unroll
            for (int u = 0; u < 16; u++) acc += P[h][t][u] * QKV[u][256 + h * 32 + d];
            O[t][h * 32 + d] = acc;
        }
    }
    __syncthreads();

    int t = tid >> 3, c0 = (tid & 7) * 16;
    int hs = wh * 4 + (t >> 2), ws = wc * 4 + (t & 3);
    int hh2 = (hs + 3) & 255, ww2 = (ws + 3) & 255;
    size_t po = (((size_t)n * 256 + hh2) * 256 + ww2) * 128;
    #pragma unroll
    for (int c = 0; c < 16; c++) {
        unsigned short h, l;
        fsplit(O[t][c0 + c], h, l);
        g_oh[po + c0 + c] = h;
        g_ol[po + c0 + c] = l;
    }
}

// ---------------- K-proj: [262144 x 128] @ [128 x 128] + bias + residual --------
__global__ __launch_bounds__(512, 1) void k_proj() {
    extern __shared__ __align__(16) char smem[];
    int tid = threadIdx.x;
    int blk = blockIdx.x;
    size_t p0 = (size_t)blk * 128;
    int warp = tid >> 5, lane = tid & 31;
    int wm = warp >> 2, wn = warp & 3;
    int gid = lane >> 2, tig = lane & 3;

    for (int i = tid; i < 4096; i += 512) {
        int c16 = i & 15; int t = i >> 4; int nr = t & 127; int part = t >> 7;
        cp16(smem + part * 34816 + nr * 272 + c16 * 16,
             g_wp + (size_t)part * 16384 + nr * 128 + c16 * 8);
    }
    for (int i = tid; i < 4096; i += 512) {
        int c16 = i & 15; int t = i >> 4; int pr = t & 127; int part = t >> 7;
        const unsigned short* sp = part ? g_ol : g_oh;
        cp16(smem + 69632 + part * 34816 + pr * 272 + c16 * 16,
             sp + (p0 + pr) * 128 + c16 * 8);
    }
    cpa_commit();
    cpa_wait<0>();
    __syncthreads();

    float acc[2][4][4];
    #pragma unroll
    for (int mt = 0; mt < 2; mt++)
        #pragma unroll
        for (int nt = 0; nt < 4; nt++)
            #pragma unroll
            for (int q = 0; q < 4; q++) acc[mt][nt][q] = 0.f;

    uint32_t sb = smem_u32(smem);
    uint32_t aB = sb + 69632;
    int arow = wm * 32 + (lane & 15);
    int acol = ((lane >> 4) & 1) * 16;
    int brow = wn * 32 + (lane & 7);
    int bcol = ((lane >> 3) & 1) * 16;

    #pragma unroll
    for (int kc = 0; kc < 8; kc++) {
        uint32_t ah[2][4], al[2][4];
        #pragma unroll
        for (int mt = 0; mt < 2; mt++) {
            uint32_t ad = aB + (uint32_t)(arow + mt * 16) * 272 + kc * 32 + acol;
            ldmx4(ah[mt], ad);
            ldmx4(al[mt], ad + 34816);
        }
        #pragma unroll
        for (int nt = 0; nt < 4; nt++) {
            uint32_t bd = sb + (uint32_t)(brow + nt * 8) * 272 + kc * 32 + bcol;
            uint32_t bh[2], bl[2];
            ldmx2(bh, bd);
            ldmx2(bl, bd + 34816);
            #pragma unroll
            for (int mt = 0; mt < 2; mt++) {
                mma16816(acc[mt][nt], ah[mt], bh);
                mma16816(acc[mt][nt], al[mt], bh);
                mma16816(acc[mt][nt], ah[mt], bl);
            }
        }
    }

    #pragma unroll
    for (int nt = 0; nt < 4; nt++) {
        int coe = wn * 32 + nt * 8 + 2 * tig;
        float b0 = g_bp[coe], b1 = g_bp[coe + 1];
        #pragma unroll
        for (int mt = 0; mt < 2; mt++) {
            #pragma unroll
            for (int half = 0; half < 2; half++) {
                size_t p = p0 + wm * 32 + mt * 16 + gid + half * 8;
                float2 res = *(const float2*)&g_xu[p * 128 + coe];
                float v0 = acc[mt][nt][half * 2 + 0] + b0 + res.x;
                float v1 = acc[mt][nt][half * 2 + 1] + b1 + res.y;
                *(float2*)&g_y[p * 128 + coe] = make_float2(v0, v1);
            }
        }
    }
}

// ---------------- K-cvt-y: pack fp32 y into conv planes (smem transpose) --------
__global__ __launch_bounds__(256) void k_cvt_y() {
    __shared__ unsigned short sh[8192];
    __shared__ unsigned short sl[8192];
    int blk = blockIdx.x;                 // 4096 = 4*4*256
    int h = blk & 255;
    int cib = (blk >> 8) & 3;
    int n = blk >> 10;
    int tid = threadIdx.x;

    for (int i = tid; i < 8192; i += 256) {
        int ch = i >> 7, w = i & 127;
        float v = g_y[(((size_t)n * 256 + cib * 64 + ch) * 256 + h) * 128 + w];
        unsigned short hi, lo;
        fsplit(v, hi, lo);
        sh[ch * 128 + w] = hi;
        sl[ch * 128 + w] = lo;
    }
    __syncthreads();

    size_t base = (((size_t)(n * 4 + cib) * 256 + h) * 128) * 32;
    for (int o = tid; o < 4096; o += 256) {
        int w = o >> 5, j = o & 31;
        uint32_t hi = (uint32_t)sh[(2 * j) * 128 + w] | ((uint32_t)sh[(2 * j + 1) * 128 + w] << 16);
        uint32_t lo = (uint32_t)sl[(2 * j) * 128 + w] | ((uint32_t)sl[(2 * j + 1) * 128 + w] << 16);
        g_yhi[base + o] = hi;
        g_ylo[base + o] = lo;
    }
}

// ---------------- conv kernels: N=128 tiles, K-chunk 32, 2 CTAs/SM --------------
// CTA = (n, h, cob): M=128 pixels, N=128 co. Stage = one (tap, 32-ci half).
// Stage: B[2 part][128 co][80B] @0, A[2 part][128 px][80B] @20480. 40KB/stage.
#define CSTG 40960
#define CA_OFF 20480
#define CPART 10240
template <int SECOND>
__global__ __launch_bounds__(512, 2) void k_conv_tc(float* __restrict__ out) {
    extern __shared__ __align__(16) char smem[];
    const int G = SECOND ? 80 : 72;       // 2 K-halves per weight chunk
    const unsigned short* Wc = SECOND ? g_wc2 : g_wc1;

    int tid = threadIdx.x;
    int blk = blockIdx.x;                 // 2048 = n(4) x h(256) x cob(2)
    int cob = blk & 1;
    int h = (blk >> 1) & 255;
    int n = blk >> 9;
    int warp = tid >> 5, lane = tid & 31;
    int wm = warp >> 2, wn = warp & 3;
    int gid = lane >> 2, tig = lane & 3;

    float acc[2][4][4];
    #pragma unroll
    for (int mt = 0; mt < 2; mt++)
        #pragma unroll
        for (int nt = 0; nt < 4; nt++)
            #pragma unroll
            for (int q = 0; q < 4; q++) acc[mt][nt][q] = 0.f;

    auto params = [&](int c, int& kh, int& kw, int& cib,
                      const uint32_t*& sH, const uint32_t*& sL) {
        if (!SECOND) { kh = c / 12; kw = (c >> 2) % 3; cib = c & 3; sH = g_yhi; sL = g_ylo; }
        else if (c < 36) { kh = c / 12; kw = (c >> 2) % 3; cib = c & 3; sH = g_t1hi; sL = g_t1lo; }
        else { kh = 1; kw = 1; cib = c - 36; sH = g_yhi; sL = g_ylo; }
    };
    auto load_stage = [&](char* dst, int g) {
        int c = g >> 1, kh2 = g & 1;
        // B: 2 part x 128 co x 32 ci (64B) each
        for (int i = tid; i < 1024; i += 512) {
            int c4 = i & 3; int t = i >> 2; int row = t & 127; int part = t >> 7;
            cp16(dst + part * CPART + row * 80 + c4 * 16,
                 Wc + ((size_t)(c * 2 + part) * 256 + cob * 128 + row) * 64 + kh2 * 32 + c4 * 8);
        }
        // A: 2 part x 128 px x 16 u32 (64B) each, contiguous in plane rows
        int kh, kw, cib; const uint32_t *sH, *sL;
        params(c, kh, kw, cib, sH, sL);
        int hh = h + kh - 1;
        bool okh = (unsigned)hh < 256u;
        int hc = okh ? hh : 0;
        for (int i = tid; i < 1024; i += 512) {
            int c4 = i & 3; int t = i >> 2; int px = t & 127; int part = t >> 7;
            int ww = px + kw - 1;
            bool ok = okh && ((unsigned)ww < 128u);
            const uint32_t* sp = part ? sL : sH;
            const uint32_t* s2 = sp + ((((size_t)(n * 4 + cib) * 256 + hc) * 128
                                        + (ok ? ww : 0)) * 32 + kh2 * 16 + c4 * 4);
            cp16z(dst + CA_OFF + part * CPART + px * 80 + c4 * 16, s2, ok);
        }
    };

    load_stage(smem, 0);
    cpa_commit();

    for (int g = 0; g < G; g++) {
        if (g + 1 < G) {
            load_stage(smem + ((g + 1) & 1) * CSTG, g + 1);
            cpa_commit();
            cpa_wait<1>();
        } else cpa_wait<0>();
        __syncthreads();

        uint32_t sb = smem_u32(smem + (g & 1) * CSTG);
        uint32_t aB = sb + CA_OFF;
        int arow = wm * 32 + (lane & 15);
        int acol = ((lane >> 4) & 1) * 16;
        int brow = wn * 32 + (lane & 7);
        int bcol = ((lane >> 3) & 1) * 16;

        #pragma unroll
        for (int kc = 0; kc < 2; kc++) {
            uint32_t ah[2][4], al[2][4];
            #pragma unroll
            for (int mt = 0; mt < 2; mt++) {
                uint32_t ad = aB + (uint32_t)(arow + mt * 16) * 80 + kc * 32 + acol;
                ldmx4(ah[mt], ad);
                ldmx4(al[mt], ad + CPART);
            }
            #pragma unroll
            for (int nt = 0; nt < 4; nt++) {
                uint32_t bd = sb + (uint32_t)(brow + nt * 8) * 80 + kc * 32 + bcol;
                uint32_t bh[2], bl[2];
                ldmx2(bh, bd);
                ldmx2(bl, bd + CPART);
                #pragma unroll
                for (int mt = 0; mt < 2; mt++) {
                    mma16816(acc[mt][nt], ah[mt], bh);
                    mma16816(acc[mt][nt], al[mt], bh);
                    mma16816(acc[mt][nt], ah[mt], bl);
                }
            }
        }
        __syncthreads();
    }

    const float* bsrc = SECOND ? g_b2 : g_b1;
    #pragma unroll
    for (int nt = 0; nt < 4; nt++) {
        int coe = cob * 128 + wn * 32 + nt * 8 + 2 * tig;
        float b0 = bsrc[coe], b1 = bsrc[coe + 1];
        int j = coe >> 1;
        #pragma unroll
        for (int mt = 0; mt < 2; mt++) {
            int p0 = wm * 32 + mt * 16 + gid;
            float v00 = fmaxf(acc[mt][nt][0] + b0, 0.f);
            float v01 = fmaxf(acc[mt][nt][1] + b1, 0.f);
            float v10 = fmaxf(acc[mt][nt][2] + b0, 0.f);
            float v11 = fmaxf(acc[mt][nt][3] + b1, 0.f);
            if (SECOND) {
                size_t o0 = (((size_t)n * 256 + coe) * 256 + h) * 128;
                out[o0 + p0] = v00;
                out[o0 + p0 + 8] = v10;
                out[o0 + 32768 + p0] = v01;
                out[o0 + 32768 + p0 + 8] = v11;
            } else {
                size_t ob = (((size_t)(n * 4 + (j >> 5)) * 256 + h) * 128) * 32 + (j & 31);
                unsigned short h0, l0, h1, l1;
                fsplit(v00, h0, l0); fsplit(v01, h1, l1);
                g_t1hi[ob + (size_t)p0 * 32] = (uint32_t)h0 | ((uint32_t)h1 << 16);
                g_t1lo[ob + (size_t)p0 * 32] = (uint32_t)l0 | ((uint32_t)l1 << 16);
                fsplit(v10, h0, l0); fsplit(v11, h1, l1);
                g_t1hi[ob + (size_t)(p0 + 8) * 32] = (uint32_t)h0 | ((uint32_t)h1 << 16);
                g_t1lo[ob + (size_t)(p0 + 8) * 32] = (uint32_t)l0 | ((uint32_t)l1 << 16);
            }
        }
    }
}

// ---------------- launcher ------------------------------------------------------
extern "C" void kernel_launch(void* const* d_in, const int* in_sizes, int n_in,
                              void* d_out, int out_size) {
    const float* x      = (const float*)d_in[0];
    const float* qkv_w  = (const float*)d_in[1];
    const float* qkv_b  = (const float*)d_in[2];
    const float* proj_w = (const float*)d_in[3];
    const float* proj_b = (const float*)d_in[4];
    const float* rpb    = (const float*)d_in[5];
    const float* c1w = (const float*)d_in[6];
    const float* c1b = (const float*)d_in[7];
    const float* b1g = (const float*)d_in[8];
    const float* b1b = (const float*)d_in[9];
    const float* b1m = (const float*)d_in[10];
    const float* b1v = (const float*)d_in[11];
    const float* c2w = (const float*)d_in[12];
    const float* c2b = (const float*)d_in[13];
    const float* b2g = (const float*)d_in[14];
    const float* b2b = (const float*)d_in[15];
    const float* b2m = (const float*)d_in[16];
    const float* b2v = (const float*)d_in[17];
    const float* idw = (const float*)d_in[18];
    const float* idb = (const float*)d_in[19];
    const float* big = (const float*)d_in[20];
    const float* bib = (const float*)d_in[21];
    const float* bim = (const float*)d_in[22];
    const float* biv = (const float*)d_in[23];
    float* out = (float*)d_out;

    cudaFuncSetAttribute(k_qkv, cudaFuncAttributeMaxDynamicSharedMemorySize, 2 * QKV_STG);
    cudaFuncSetAttribute(k_proj, cudaFuncAttributeMaxDynamicSharedMemorySize, 139264);
    cudaFuncSetAttribute(k_conv_tc<0>, cudaFuncAttributeMaxDynamicSharedMemorySize, 2 * CSTG);
    cudaFuncSetAttribute(k_conv_tc<1>, cudaFuncAttributeMaxDynamicSharedMemorySize, 2 * CSTG);

    k_upsample<<<TOT / 256, 256>>>(x);
    k_cvt_wq<<<192, 256>>>(qkv_w, qkv_b);
    k_cvt_wp<<<64, 256>>>(proj_w, proj_b);
    k_cvt_w1<<<2304, 256>>>(c1w, c1b, b1g, b1b, b1m, b1v);
    k_cvt_w2<<<2560, 256>>>(c2w, c2b, b2g, b2b, b2m, b2v,
                            idw, idb, big, bib, bim, biv);
    k_qkv<<<2048, 512, 2 * QKV_STG>>>();
    k_attn_core<<<16384, 128>>>(rpb);
    k_proj<<<2048, 512, 139264>>>();
    k_cvt_y<<<4096, 256>>>();
    k_conv_tc<0><<<2048, 512, 2 * CSTG>>>(out);
    k_conv_tc<1><<<2048, 512, 2 * CSTG>>>(out);
}

// round 12
// speedup vs baseline: 3.5538x; 1.2206x over previous
#include <cuda_runtime.h>
#include <cuda_fp16.h>
#include <cstdint>

#define TOT (4*256*256*128)
static __device__ float g_xu[TOT];                    // upsampled x (B,H,W,C)
static __device__ unsigned short g_xuh[TOT];          // fp16 split of g_xu
static __device__ unsigned short g_xul[TOT];
static __device__ float g_qkv[(size_t)4*256*256*384]; // QKV per shifted pixel
static __device__ unsigned short g_oh[TOT];           // attention out O split (orig coords)
static __device__ unsigned short g_ol[TOT];
static __device__ float g_y[TOT];                     // attention + residual (fp32)
// conv input planes: [n][cib(4)][h(256)][w(128)][j32(32 u32 = ci-pairs)]
static __device__ uint32_t g_yhi[TOT/2];
static __device__ uint32_t g_ylo[TOT/2];
static __device__ uint32_t g_t1hi[TOT/2];
static __device__ uint32_t g_t1lo[TOT/2];
static __device__ unsigned short g_wc1[36*256*64];    // fp16 weights (single part)
static __device__ unsigned short g_wc2[40*256*64];
static __device__ unsigned short g_wq[384*128];       // qkv_w fp16 [n][k]
static __device__ unsigned short g_wp[128*128];       // proj_w fp16 [n][k]
static __device__ float g_b1[256], g_b2[256], g_bq[384], g_bp[128];

// ---------------- helpers -------------------------------------------------------
__device__ __forceinline__ uint32_t smem_u32(const void* p) {
    uint32_t r;
    asm("{ .reg .u64 t; cvta.to.shared.u64 t, %1; cvt.u32.u64 %0, t; }" : "=r"(r) : "l"(p));
    return r;
}
__device__ __forceinline__ void hsplit(float x, unsigned short& h, unsigned short& l) {
    __half hh = __float2half_rn(x);
    float rem = x - __half2float(hh);
    h = __half_as_ushort(hh);
    l = __half_as_ushort(__float2half_rn(rem));
}
__device__ __forceinline__ unsigned short h16(float x) {
    return __half_as_ushort(__float2half_rn(x));
}
__device__ __forceinline__ void cp16(void* dst_smem, const void* src) {
    unsigned d = (unsigned)__cvta_generic_to_shared(dst_smem);
    asm volatile("cp.async.cg.shared.global [%0], [%1], 16;" :: "r"(d), "l"(src));
}
__device__ __forceinline__ void cp16z(void* dst_smem, const void* src, bool valid) {
    unsigned d = (unsigned)__cvta_generic_to_shared(dst_smem);
    int sz = valid ? 16 : 0;
    asm volatile("cp.async.cg.shared.global [%0], [%1], 16, %2;"
                 :: "r"(d), "l"(src), "r"(sz));
}
__device__ __forceinline__ void cpa_commit() { asm volatile("cp.async.commit_group;"); }
template <int N> __device__ __forceinline__ void cpa_wait() {
    asm volatile("cp.async.wait_group %0;" :: "n"(N));
}
__device__ __forceinline__ void ldmx4(uint32_t* r, uint32_t a) {
    asm volatile("ldmatrix.sync.aligned.m8n8.x4.shared.b16 {%0,%1,%2,%3}, [%4];"
                 : "=r"(r[0]), "=r"(r[1]), "=r"(r[2]), "=r"(r[3]) : "r"(a));
}
__device__ __forceinline__ void ldmx2(uint32_t* r, uint32_t a) {
    asm volatile("ldmatrix.sync.aligned.m8n8.x2.shared.b16 {%0,%1}, [%2];"
                 : "=r"(r[0]), "=r"(r[1]) : "r"(a));
}
__device__ __forceinline__ void mmah(float* d, const uint32_t* a, const uint32_t* b) {
    asm volatile(
        "mma.sync.aligned.m16n8k16.row.col.f32.f16.f16.f32 "
        "{%0,%1,%2,%3}, {%4,%5,%6,%7}, {%8,%9}, {%0,%1,%2,%3};"
        : "+f"(d[0]), "+f"(d[1]), "+f"(d[2]), "+f"(d[3])
        : "r"(a[0]), "r"(a[1]), "r"(a[2]), "r"(a[3]), "r"(b[0]), "r"(b[1]));
}

// ---------------- K1: bilinear 2x upsample + fp16 split -------------------------
__global__ void k_upsample(const float* __restrict__ xin) {
    int idx = blockIdx.x * 256 + threadIdx.x;
    int cc = idx & 127;
    int t  = idx >> 7;
    int ww = t & 255; t >>= 8;
    int hh = t & 255;
    int b  = t >> 8;
    float pw = ww * (127.0f / 255.0f);
    int wlo = (int)pw; float fw = pw - (float)wlo; int whi = min(wlo + 1, 127);
    float pc = cc * (63.0f / 127.0f);
    int clo = (int)pc; float fc = pc - (float)clo; int chi = min(clo + 1, 63);
    const float* base = xin + ((b * 256 + hh) * 128) * 64;
    float v00 = base[wlo * 64 + clo], v01 = base[wlo * 64 + chi];
    float v10 = base[whi * 64 + clo], v11 = base[whi * 64 + chi];
    float v = (1.f - fw) * ((1.f - fc) * v00 + fc * v01)
            +        fw  * ((1.f - fc) * v10 + fc * v11);
    g_xu[idx] = v;
    unsigned short h, l;
    hsplit(v, h, l);
    g_xuh[idx] = h;
    g_xul[idx] = l;
}

// ---------------- weight prep (single fp16 part) --------------------------------
__global__ void k_cvt_wq(const float* __restrict__ qkv_w, const float* __restrict__ qkv_b) {
    int idx = blockIdx.x * 256 + threadIdx.x;
    if (idx >= 49152) return;
    int k = idx & 127, nn = idx >> 7;
    g_wq[nn * 128 + k] = h16(qkv_w[k * 384 + nn]);
    if (k == 0) g_bq[nn] = qkv_b[nn];
}
__global__ void k_cvt_wp(const float* __restrict__ proj_w, const float* __restrict__ proj_b) {
    int idx = blockIdx.x * 256 + threadIdx.x;
    if (idx >= 16384) return;
    int k = idx & 127, nn = idx >> 7;
    g_wp[nn * 128 + k] = h16(proj_w[k * 128 + nn]);
    if (k == 0) g_bp[nn] = proj_b[nn];
}
__global__ void k_cvt_w1(const float* __restrict__ cw, const float* __restrict__ cb,
                         const float* __restrict__ bg, const float* __restrict__ bb,
                         const float* __restrict__ bm, const float* __restrict__ bv) {
    int idx = blockIdx.x * 256 + threadIdx.x;
    if (idx >= 36 * 256 * 64) return;
    int ci = idx & 63;
    int t = idx >> 6;
    int co = t & 255;
    int c = t >> 8;
    int kh = c / 12, kw = (c >> 2) % 3, ci0 = (c & 3) << 6;
    float s = bg[co] * rsqrtf(bv[co] + 1e-5f);
    g_wc1[(c * 256 + co) * 64 + ci] = h16(cw[((co * 256 + ci0 + ci) * 3 + kh) * 3 + kw] * s);
    if (c == 0 && ci == 0) g_b1[co] = cb[co] * s + bb[co] - bm[co] * s;
}
__global__ void k_cvt_w2(const float* __restrict__ cw, const float* __restrict__ cb,
                         const float* __restrict__ bg, const float* __restrict__ bb,
                         const float* __restrict__ bm, const float* __restrict__ bv,
                         const float* __restrict__ iw, const float* __restrict__ ibi,
                         const float* __restrict__ ig, const float* __restrict__ ib2,
                         const float* __restrict__ im, const float* __restrict__ iv) {
    int idx = blockIdx.x * 256 + threadIdx.x;
    if (idx >= 40 * 256 * 64) return;
    int ci = idx & 63;
    int t = idx >> 6;
    int co = t & 255;
    int c = t >> 8;
    float wv;
    if (c < 36) {
        int kh = c / 12, kw = (c >> 2) % 3, ci0 = (c & 3) << 6;
        wv = cw[((co * 256 + ci0 + ci) * 3 + kh) * 3 + kw] * (bg[co] * rsqrtf(bv[co] + 1e-5f));
    } else {
        wv = iw[co * 256 + ((c - 36) << 6) + ci] * (ig[co] * rsqrtf(iv[co] + 1e-5f));
    }
    g_wc2[(c * 256 + co) * 64 + ci] = h16(wv);
    if (c == 0 && ci == 0) {
        float s  = bg[co] * rsqrtf(bv[co] + 1e-5f);
        float si = ig[co] * rsqrtf(iv[co] + 1e-5f);
        g_b2[co] = cb[co] * s + bb[co] - bm[co] * s + ibi[co] * si + ib2[co] - im[co] * si;
    }
}

// ---------------- K-QKV: [262144 x 128] @ [128 x 384] fp16 2-product ------------
// Stage: B[384 rows][80B] @0 (30720), A[2 part][128 px][80B] @30720. 51200/stage.
#define QKV_STG 51200
__global__ __launch_bounds__(512, 1) void k_qkv() {
    extern __shared__ __align__(16) char smem[];
    int tid = threadIdx.x;
    int blk = blockIdx.x;                    // 2048
    int n = blk >> 9, hs = (blk >> 1) & 255, wb = blk & 1;
    int w0 = wb * 128;
    int h2 = (hs + 3) & 255;
    int warp = tid >> 5, lane = tid & 31;
    int wm = warp >> 2, wn = warp & 3;
    int gid = lane >> 2, tig = lane & 3;

    float acc[2][12][4];
    #pragma unroll
    for (int mt = 0; mt < 2; mt++)
        #pragma unroll
        for (int nt = 0; nt < 12; nt++)
            #pragma unroll
            for (int q = 0; q < 4; q++) acc[mt][nt][q] = 0.f;

    auto load_stage = [&](char* dst, int g) {
        int kc0 = g * 32;
        for (int i = tid; i < 1536; i += 512) {
            int c4 = i & 3; int nr = i >> 2;
            cp16(dst + nr * 80 + c4 * 16, g_wq + nr * 128 + kc0 + c4 * 8);
        }
        for (int i = tid; i < 1024; i += 512) {
            int c4 = i & 3; int t = i >> 2; int pr = t & 127; int part = t >> 7;
            int w2 = (w0 + pr + 3) & 255;
            const unsigned short* sp = part ? g_xul : g_xuh;
            cp16(dst + 30720 + part * 10240 + pr * 80 + c4 * 16,
                 sp + (((size_t)n * 256 + h2) * 256 + w2) * 128 + kc0 + c4 * 8);
        }
    };

    load_stage(smem, 0);
    cpa_commit();
    for (int g = 0; g < 4; g++) {
        if (g + 1 < 4) {
            load_stage(smem + ((g + 1) & 1) * QKV_STG, g + 1);
            cpa_commit();
            cpa_wait<1>();
        } else cpa_wait<0>();
        __syncthreads();

        uint32_t sb = smem_u32(smem + (g & 1) * QKV_STG);
        uint32_t aB = sb + 30720;
        int arow = wm * 32 + (lane & 15);
        int acol = ((lane >> 4) & 1) * 16;
        int brow = wn * 96 + (lane & 7);
        int bcol = ((lane >> 3) & 1) * 16;

        #pragma unroll
        for (int kc = 0; kc < 2; kc++) {
            uint32_t ah[2][4], al[2][4];
            #pragma unroll
            for (int mt = 0; mt < 2; mt++) {
                uint32_t ad = aB + (uint32_t)(arow + mt * 16) * 80 + kc * 32 + acol;
                ldmx4(ah[mt], ad);
                ldmx4(al[mt], ad + 10240);
            }
            #pragma unroll
            for (int nt = 0; nt < 12; nt++) {
                uint32_t bd = sb + (uint32_t)(brow + nt * 8) * 80 + kc * 32 + bcol;
                uint32_t bv[2];
                ldmx2(bv, bd);
                #pragma unroll
                for (int mt = 0; mt < 2; mt++) {
                    mmah(acc[mt][nt], ah[mt], bv);
                    mmah(acc[mt][nt], al[mt], bv);
                }
            }
        }
        __syncthreads();
    }

    size_t pbase = ((size_t)n * 256 + hs) * 256 + w0;
    #pragma unroll
    for (int nt = 0; nt < 12; nt++) {
        int col = wn * 96 + nt * 8 + 2 * tig;
        float b0 = g_bq[col], b1 = g_bq[col + 1];
        float sc = (col < 128) ? 0.17677669529663687f : 1.f;
        #pragma unroll
        for (int mt = 0; mt < 2; mt++) {
            int r0 = wm * 32 + mt * 16 + gid;
            float2 v0 = make_float2((acc[mt][nt][0] + b0) * sc, (acc[mt][nt][1] + b1) * sc);
            float2 v1 = make_float2((acc[mt][nt][2] + b0) * sc, (acc[mt][nt][3] + b1) * sc);
            *(float2*)&g_qkv[(pbase + r0) * 384 + col] = v0;
            *(float2*)&g_qkv[(pbase + r0 + 8) * 384 + col] = v1;
        }
    }
}

// ---------------- attention core: scores/softmax/PV per window ------------------
__global__ __launch_bounds__(128) void k_attn_core(const float* __restrict__ rpb) {
    __shared__ float QKV[16][384];
    __shared__ float P[4][16][16];
    __shared__ float O[16][128];
    int tid = threadIdx.x, blk = blockIdx.x;
    int n = blk >> 12, widx = blk & 4095, wh = widx >> 6, wc = widx & 63;

    for (int idx = tid; idx < 6144; idx += 128) {
        int t = idx / 384, c = idx - t * 384;
        size_t ps = ((size_t)n * 256 + wh * 4 + (t >> 2)) * 256 + wc * 4 + (t & 3);
        QKV[t][c] = g_qkv[ps * 384 + c];
    }
    __syncthreads();

    int warp = tid >> 5, lane = tid & 31;
    if (lane < 16) {
        int t = lane, h = warp;
        float q[32];
        #pragma unroll
        for (int d = 0; d < 32; d++) q[d] = QKV[t][h * 32 + d];
        int i1 = t >> 2, j1 = t & 3;
        int rh1 = wh * 4 + i1, rw1 = wc * 4 + j1;
        int l1 = ((rh1 < 252) ? 0 : ((rh1 < 253) ? 1 : 2)) * 3
               + ((rw1 < 252) ? 0 : ((rw1 < 253) ? 1 : 2));
        float s[16], mx = -1e30f;
        #pragma unroll
        for (int u = 0; u < 16; u++) {
            float dot = 0.f;
            #pragma unroll
            for (int d = 0; d < 32; d++) dot += q[d] * QKV[u][128 + h * 32 + d];
            int i2 = u >> 2, j2 = u & 3;
            dot += rpb[((i1 - i2 + 3) * 7 + (j1 - j2 + 3)) * 4 + h];
            int rh2 = wh * 4 + i2, rw2 = wc * 4 + j2;
            int l2 = ((rh2 < 252) ? 0 : ((rh2 < 253) ? 1 : 2)) * 3
                   + ((rw2 < 252) ? 0 : ((rw2 < 253) ? 1 : 2));
            if (l1 != l2) dot -= 100.f;
            s[u] = dot; mx = fmaxf(mx, dot);
        }
        float sum = 0.f;
        #pragma unroll
        for (int u = 0; u < 16; u++) { s[u] = __expf(s[u] - mx); sum += s[u]; }
        float inv = 1.f / sum;
        #pragma unroll
        for (int u = 0; u < 16; u++) P[h][t][u] = s[u] * inv;
    }
    __syncwarp();
    {
        int h = warp, d = lane;
        #pragma unroll
        for (int t = 0; t < 16; t++) {
            float acc = 0.f;
            #pragma unroll
            for (int u = 0; u < 16; u++) acc += P[h][t][u] * QKV[u][256 + h * 32 + d];
            O[t][h * 32 + d] = acc;
        }
    }
    __syncthreads();

    int t = tid >> 3, c0 = (tid & 7) * 16;
    int hs = wh * 4 + (t >> 2), ws = wc * 4 + (t & 3);
    int hh2 = (hs + 3) & 255, ww2 = (ws + 3) & 255;
    size_t po = (((size_t)n * 256 + hh2) * 256 + ww2) * 128;
    #pragma unroll
    for (int c = 0; c < 16; c++) {
        unsigned short h, l;
        hsplit(O[t][c0 + c], h, l);
        g_oh[po + c0 + c] = h;
        g_ol[po + c0 + c] = l;
    }
}

// ---------------- K-proj: [262144 x 128] @ [128 x 128] + bias + residual --------
// B[128 rows][272B] @0 (34816), A[2 part][128 px][272B] @34816.
__global__ __launch_bounds__(512, 1) void k_proj() {
    extern __shared__ __align__(16) char smem[];
    int tid = threadIdx.x;
    int blk = blockIdx.x;
    size_t p0 = (size_t)blk * 128;
    int warp = tid >> 5, lane = tid & 31;
    int wm = warp >> 2, wn = warp & 3;
    int gid = lane >> 2, tig = lane & 3;

    for (int i = tid; i < 2048; i += 512) {
        int c16 = i & 15; int nr = i >> 4;
        cp16(smem + nr * 272 + c16 * 16, g_wp + nr * 128 + c16 * 8);
    }
    for (int i = tid; i < 4096; i += 512) {
        int c16 = i & 15; int t = i >> 4; int pr = t & 127; int part = t >> 7;
        const unsigned short* sp = part ? g_ol : g_oh;
        cp16(smem + 34816 + part * 34816 + pr * 272 + c16 * 16,
             sp + (p0 + pr) * 128 + c16 * 8);
    }
    cpa_commit();
    cpa_wait<0>();
    __syncthreads();

    float acc[2][4][4];
    #pragma unroll
    for (int mt = 0; mt < 2; mt++)
        #pragma unroll
        for (int nt = 0; nt < 4; nt++)
            #pragma unroll
            for (int q = 0; q < 4; q++) acc[mt][nt][q] = 0.f;

    uint32_t sb = smem_u32(smem);
    uint32_t aB = sb + 34816;
    int arow = wm * 32 + (lane & 15);
    int acol = ((lane >> 4) & 1) * 16;
    int brow = wn * 32 + (lane & 7);
    int bcol = ((lane >> 3) & 1) * 16;

    #pragma unroll
    for (int kc = 0; kc < 8; kc++) {
        uint32_t ah[2][4], al[2][4];
        #pragma unroll
        for (int mt = 0; mt < 2; mt++) {
            uint32_t ad = aB + (uint32_t)(arow + mt * 16) * 272 + kc * 32 + acol;
            ldmx4(ah[mt], ad);
            ldmx4(al[mt], ad + 34816);
        }
        #pragma unroll
        for (int nt = 0; nt < 4; nt++) {
            uint32_t bd = sb + (uint32_t)(brow + nt * 8) * 272 + kc * 32 + bcol;
            uint32_t bv[2];
            ldmx2(bv, bd);
            #pragma unroll
            for (int mt = 0; mt < 2; mt++) {
                mmah(acc[mt][nt], ah[mt], bv);
                mmah(acc[mt][nt], al[mt], bv);
            }
        }
    }

    #pragma unroll
    for (int nt = 0; nt < 4; nt++) {
        int coe = wn * 32 + nt * 8 + 2 * tig;
        float b0 = g_bp[coe], b1 = g_bp[coe + 1];
        #pragma unroll
        for (int mt = 0; mt < 2; mt++) {
            #pragma unroll
            for (int half = 0; half < 2; half++) {
                size_t p = p0 + wm * 32 + mt * 16 + gid + half * 8;
                float2 res = *(const float2*)&g_xu[p * 128 + coe];
                float v0 = acc[mt][nt][half * 2 + 0] + b0 + res.x;
                float v1 = acc[mt][nt][half * 2 + 1] + b1 + res.y;
                *(float2*)&g_y[p * 128 + coe] = make_float2(v0, v1);
            }
        }
    }
}

// ---------------- K-cvt-y: pack fp32 y into conv planes (smem transpose) --------
__global__ __launch_bounds__(256) void k_cvt_y() {
    __shared__ unsigned short sh[8192];
    __shared__ unsigned short sl[8192];
    int blk = blockIdx.x;                 // 4096 = 4*4*256
    int h = blk & 255;
    int cib = (blk >> 8) & 3;
    int n = blk >> 10;
    int tid = threadIdx.x;

    for (int i = tid; i < 8192; i += 256) {
        int ch = i >> 7, w = i & 127;
        float v = g_y[(((size_t)n * 256 + cib * 64 + ch) * 256 + h) * 128 + w];
        unsigned short hi, lo;
        hsplit(v, hi, lo);
        sh[ch * 128 + w] = hi;
        sl[ch * 128 + w] = lo;
    }
    __syncthreads();

    size_t base = (((size_t)(n * 4 + cib) * 256 + h) * 128) * 32;
    for (int o = tid; o < 4096; o += 256) {
        int w = o >> 5, j = o & 31;
        uint32_t hi = (uint32_t)sh[(2 * j) * 128 + w] | ((uint32_t)sh[(2 * j + 1) * 128 + w] << 16);
        uint32_t lo = (uint32_t)sl[(2 * j) * 128 + w] | ((uint32_t)sl[(2 * j + 1) * 128 + w] << 16);
        g_yhi[base + o] = hi;
        g_ylo[base + o] = lo;
    }
}

// ---------------- conv: fp16 2-product, N=128, K-chunk 32, 2 CTAs/SM ------------
// Stage: B[128 co][80B] @0 (10240), A[2 part][128 px][80B] @10240. 30720/stage.
#define CSTG 30720
#define CA_OFF 10240
#define CPART 10240
template <int SECOND>
__global__ __launch_bounds__(512, 2) void k_conv_tc(float* __restrict__ out) {
    extern __shared__ __align__(16) char smem[];
    const int G = SECOND ? 80 : 72;       // 2 K-halves per weight chunk
    const unsigned short* Wc = SECOND ? g_wc2 : g_wc1;

    int tid = threadIdx.x;
    int blk = blockIdx.x;                 // 2048 = n(4) x h(256) x cob(2)
    int cob = blk & 1;
    int h = (blk >> 1) & 255;
    int n = blk >> 9;
    int warp = tid >> 5, lane = tid & 31;
    int wm = warp >> 2, wn = warp & 3;
    int gid = lane >> 2, tig = lane & 3;

    float acc[2][4][4];
    #pragma unroll
    for (int mt = 0; mt < 2; mt++)
        #pragma unroll
        for (int nt = 0; nt < 4; nt++)
            #pragma unroll
            for (int q = 0; q < 4; q++) acc[mt][nt][q] = 0.f;

    auto params = [&](int c, int& kh, int& kw, int& cib,
                      const uint32_t*& sH, const uint32_t*& sL) {
        if (!SECOND) { kh = c / 12; kw = (c >> 2) % 3; cib = c & 3; sH = g_yhi; sL = g_ylo; }
        else if (c < 36) { kh = c / 12; kw = (c >> 2) % 3; cib = c & 3; sH = g_t1hi; sL = g_t1lo; }
        else { kh = 1; kw = 1; cib = c - 36; sH = g_yhi; sL = g_ylo; }
    };
    auto load_stage = [&](char* dst, int g) {
        int c = g >> 1, kh2 = g & 1;
        // B: 128 co x 32 ci fp16 (64B/row)
        for (int i = tid; i < 512; i += 512) {
            int c4 = i & 3; int row = i >> 2;
            cp16(dst + row * 80 + c4 * 16,
                 Wc + ((size_t)c * 256 + cob * 128 + row) * 64 + kh2 * 32 + c4 * 8);
        }
        // A: 2 part x 128 px x 16 u32 (64B), contiguous plane rows
        int kh, kw, cib; const uint32_t *sH, *sL;
        params(c, kh, kw, cib, sH, sL);
        int hh = h + kh - 1;
        bool okh = (unsigned)hh < 256u;
        int hc = okh ? hh : 0;
        for (int i = tid; i < 1024; i += 512) {
            int c4 = i & 3; int t = i >> 2; int px = t & 127; int part = t >> 7;
            int ww = px + kw - 1;
            bool ok = okh && ((unsigned)ww < 128u);
            const uint32_t* sp = part ? sL : sH;
            const uint32_t* s2 = sp + ((((size_t)(n * 4 + cib) * 256 + hc) * 128
                                        + (ok ? ww : 0)) * 32 + kh2 * 16 + c4 * 4);
            cp16z(dst + CA_OFF + part * CPART + px * 80 + c4 * 16, s2, ok);
        }
    };

    load_stage(smem, 0);
    cpa_commit();

    for (int g = 0; g < G; g++) {
        if (g + 1 < G) {
            load_stage(smem + ((g + 1) & 1) * CSTG, g + 1);
            cpa_commit();
            cpa_wait<1>();
        } else cpa_wait<0>();
        __syncthreads();

        uint32_t sb = smem_u32(smem + (g & 1) * CSTG);
        uint32_t aB = sb + CA_OFF;
        int arow = wm * 32 + (lane & 15);
        int acol = ((lane >> 4) & 1) * 16;
        int brow = wn * 32 + (lane & 7);
        int bcol = ((lane >> 3) & 1) * 16;

        #pragma unroll
        for (int kc = 0; kc < 2; kc++) {
            uint32_t ah[2][4], al[2][4];
            #pragma unroll
            for (int mt = 0; mt < 2; mt++) {
                uint32_t ad = aB + (uint32_t)(arow + mt * 16) * 80 + kc * 32 + acol;
                ldmx4(ah[mt], ad);
                ldmx4(al[mt], ad + CPART);
            }
            #pragma unroll
            for (int nt = 0; nt < 4; nt++) {
                uint32_t bd = sb + (uint32_t)(brow + nt * 8) * 80 + kc * 32 + bcol;
                uint32_t bv[2];
                ldmx2(bv, bd);
                #pragma unroll
                for (int mt = 0; mt < 2; mt++) {
                    mmah(acc[mt][nt], ah[mt], bv);
                    mmah(acc[mt][nt], al[mt], bv);
                }
            }
        }
        __syncthreads();
    }

    const float* bsrc = SECOND ? g_b2 : g_b1;
    #pragma unroll
    for (int nt = 0; nt < 4; nt++) {
        int coe = cob * 128 + wn * 32 + nt * 8 + 2 * tig;
        float b0 = bsrc[coe], b1 = bsrc[coe + 1];
        int j = coe >> 1;
        #pragma unroll
        for (int mt = 0; mt < 2; mt++) {
            int p0 = wm * 32 + mt * 16 + gid;
            float v00 = fmaxf(acc[mt][nt][0] + b0, 0.f);
            float v01 = fmaxf(acc[mt][nt][1] + b1, 0.f);
            float v10 = fmaxf(acc[mt][nt][2] + b0, 0.f);
            float v11 = fmaxf(acc[mt][nt][3] + b1, 0.f);
            if (SECOND) {
                size_t o0 = (((size_t)n * 256 + coe) * 256 + h) * 128;
                out[o0 + p0] = v00;
                out[o0 + p0 + 8] = v10;
                out[o0 + 32768 + p0] = v01;
                out[o0 + 32768 + p0 + 8] = v11;
            } else {
                size_t ob = (((size_t)(n * 4 + (j >> 5)) * 256 + h) * 128) * 32 + (j & 31);
                unsigned short h0, l0, h1, l1;
                hsplit(v00, h0, l0); hsplit(v01, h1, l1);
                g_t1hi[ob + (size_t)p0 * 32] = (uint32_t)h0 | ((uint32_t)h1 << 16);
                g_t1lo[ob + (size_t)p0 * 32] = (uint32_t)l0 | ((uint32_t)l1 << 16);
                hsplit(v10, h0, l0); hsplit(v11, h1, l1);
                g_t1hi[ob + (size_t)(p0 + 8) * 32] = (uint32_t)h0 | ((uint32_t)h1 << 16);
                g_t1lo[ob + (size_t)(p0 + 8) * 32] = (uint32_t)l0 | ((uint32_t)l1 << 16);
            }
        }
    }
}

// ---------------- launcher ------------------------------------------------------
extern "C" void kernel_launch(void* const* d_in, const int* in_sizes, int n_in,
                              void* d_out, int out_size) {
    const float* x      = (const float*)d_in[0];
    const float* qkv_w  = (const float*)d_in[1];
    const float* qkv_b  = (const float*)d_in[2];
    const float* proj_w = (const float*)d_in[3];
    const float* proj_b = (const float*)d_in[4];
    const float* rpb    = (const float*)d_in[5];
    const float* c1w = (const float*)d_in[6];
    const float* c1b = (const float*)d_in[7];
    const float* b1g = (const float*)d_in[8];
    const float* b1b = (const float*)d_in[9];
    const float* b1m = (const float*)d_in[10];
    const float* b1v = (const float*)d_in[11];
    const float* c2w = (const float*)d_in[12];
    const float* c2b = (const float*)d_in[13];
    const float* b2g = (const float*)d_in[14];
    const float* b2b = (const float*)d_in[15];
    const float* b2m = (const float*)d_in[16];
    const float* b2v = (const float*)d_in[17];
    const float* idw = (const float*)d_in[18];
    const float* idb = (const float*)d_in[19];
    const float* big = (const float*)d_in[20];
    const float* bib = (const float*)d_in[21];
    const float* bim = (const float*)d_in[22];
    const float* biv = (const float*)d_in[23];
    float* out = (float*)d_out;

    cudaFuncSetAttribute(k_qkv, cudaFuncAttributeMaxDynamicSharedMemorySize, 2 * QKV_STG);
    cudaFuncSetAttribute(k_proj, cudaFuncAttributeMaxDynamicSharedMemorySize, 104448);
    cudaFuncSetAttribute(k_conv_tc<0>, cudaFuncAttributeMaxDynamicSharedMemorySize, 2 * CSTG);
    cudaFuncSetAttribute(k_conv_tc<1>, cudaFuncAttributeMaxDynamicSharedMemorySize, 2 * CSTG);

    k_upsample<<<TOT / 256, 256>>>(x);
    k_cvt_wq<<<192, 256>>>(qkv_w, qkv_b);
    k_cvt_wp<<<64, 256>>>(proj_w, proj_b);
    k_cvt_w1<<<2304, 256>>>(c1w, c1b, b1g, b1b, b1m, b1v);
    k_cvt_w2<<<2560, 256>>>(c2w, c2b, b2g, b2b, b2m, b2v,
                            idw, idb, big, bib, bim, biv);
    k_qkv<<<2048, 512, 2 * QKV_STG>>>();
    k_attn_core<<<16384, 128>>>(rpb);
    k_proj<<<2048, 512, 104448>>>();
    k_cvt_y<<<4096, 256>>>();
    k_conv_tc<0><<<2048, 512, 2 * CSTG>>>(out);
    k_conv_tc<1><<<2048, 512, 2 * CSTG>>>(out);
}

// round 13
// speedup vs baseline: 5.3171x; 1.4962x over previous
#include <cuda_runtime.h>
#include <cuda_fp16.h>
#include <cstdint>

#define TOT (4*256*256*128)
static __device__ float g_xu[TOT];                    // upsampled x (B,H,W,C)
static __device__ unsigned short g_xuh[TOT];          // fp16 of g_xu
static __device__ float g_qkv[(size_t)4*256*256*384]; // QKV per shifted pixel
static __device__ unsigned short g_oh[TOT];           // attention out O fp16 (orig coords)
static __device__ float g_y[TOT];                     // attention + residual (fp32)
// conv input planes: [n][cib(4)][h(256)][w(128)][j32(32 u32 = ci-pairs)]
static __device__ uint32_t g_yhi[TOT/2];
static __device__ uint32_t g_t1hi[TOT/2];
static __device__ unsigned short g_wc1[36*256*64];    // fp16 weights
static __device__ unsigned short g_wc2[40*256*64];
static __device__ unsigned short g_wq[384*128];       // qkv_w fp16 [n][k]
static __device__ unsigned short g_wp[128*128];       // proj_w fp16 [n][k]
static __device__ float g_b1[256], g_b2[256], g_bq[384], g_bp[128];

// ---------------- helpers -------------------------------------------------------
__device__ __forceinline__ uint32_t smem_u32(const void* p) {
    uint32_t r;
    asm("{ .reg .u64 t; cvta.to.shared.u64 t, %1; cvt.u32.u64 %0, t; }" : "=r"(r) : "l"(p));
    return r;
}
__device__ __forceinline__ unsigned short h16(float x) {
    return __half_as_ushort(__float2half_rn(x));
}
__device__ __forceinline__ void cp16(void* dst_smem, const void* src) {
    unsigned d = (unsigned)__cvta_generic_to_shared(dst_smem);
    asm volatile("cp.async.cg.shared.global [%0], [%1], 16;" :: "r"(d), "l"(src));
}
__device__ __forceinline__ void cp16z(void* dst_smem, const void* src, bool valid) {
    unsigned d = (unsigned)__cvta_generic_to_shared(dst_smem);
    int sz = valid ? 16 : 0;
    asm volatile("cp.async.cg.shared.global [%0], [%1], 16, %2;"
                 :: "r"(d), "l"(src), "r"(sz));
}
__device__ __forceinline__ void cpa_commit() { asm volatile("cp.async.commit_group;"); }
template <int N> __device__ __forceinline__ void cpa_wait() {
    asm volatile("cp.async.wait_group %0;" :: "n"(N));
}
__device__ __forceinline__ void ldmx4(uint32_t* r, uint32_t a) {
    asm volatile("ldmatrix.sync.aligned.m8n8.x4.shared.b16 {%0,%1,%2,%3}, [%4];"
                 : "=r"(r[0]), "=r"(r[1]), "=r"(r[2]), "=r"(r[3]) : "r"(a));
}
__device__ __forceinline__ void ldmx2(uint32_t* r, uint32_t a) {
    asm volatile("ldmatrix.sync.aligned.m8n8.x2.shared.b16 {%0,%1}, [%2];"
                 : "=r"(r[0]), "=r"(r[1]) : "r"(a));
}
__device__ __forceinline__ void mmah(float* d, const uint32_t* a, const uint32_t* b) {
    asm volatile(
        "mma.sync.aligned.m16n8k16.row.col.f32.f16.f16.f32 "
        "{%0,%1,%2,%3}, {%4,%5,%6,%7}, {%8,%9}, {%0,%1,%2,%3};"
        : "+f"(d[0]), "+f"(d[1]), "+f"(d[2]), "+f"(d[3])
        : "r"(a[0]), "r"(a[1]), "r"(a[2]), "r"(a[3]), "r"(b[0]), "r"(b[1]));
}

// ---------------- K1: bilinear 2x upsample + fp16 -------------------------------
__global__ void k_upsample(const float* __restrict__ xin) {
    int idx = blockIdx.x * 256 + threadIdx.x;
    int cc = idx & 127;
    int t  = idx >> 7;
    int ww = t & 255; t >>= 8;
    int hh = t & 255;
    int b  = t >> 8;
    float pw = ww * (127.0f / 255.0f);
    int wlo = (int)pw; float fw = pw - (float)wlo; int whi = min(wlo + 1, 127);
    float pc = cc * (63.0f / 127.0f);
    int clo = (int)pc; float fc = pc - (float)clo; int chi = min(clo + 1, 63);
    const float* base = xin + ((b * 256 + hh) * 128) * 64;
    float v00 = base[wlo * 64 + clo], v01 = base[wlo * 64 + chi];
    float v10 = base[whi * 64 + clo], v11 = base[whi * 64 + chi];
    float v = (1.f - fw) * ((1.f - fc) * v00 + fc * v01)
            +        fw  * ((1.f - fc) * v10 + fc * v11);
    g_xu[idx] = v;
    g_xuh[idx] = h16(v);
}

// ---------------- weight prep ---------------------------------------------------
__global__ void k_cvt_wq(const float* __restrict__ qkv_w, const float* __restrict__ qkv_b) {
    int idx = blockIdx.x * 256 + threadIdx.x;
    if (idx >= 49152) return;
    int k = idx & 127, nn = idx >> 7;
    g_wq[nn * 128 + k] = h16(qkv_w[k * 384 + nn]);
    if (k == 0) g_bq[nn] = qkv_b[nn];
}
__global__ void k_cvt_wp(const float* __restrict__ proj_w, const float* __restrict__ proj_b) {
    int idx = blockIdx.x * 256 + threadIdx.x;
    if (idx >= 16384) return;
    int k = idx & 127, nn = idx >> 7;
    g_wp[nn * 128 + k] = h16(proj_w[k * 128 + nn]);
    if (k == 0) g_bp[nn] = proj_b[nn];
}
__global__ void k_cvt_w1(const float* __restrict__ cw, const float* __restrict__ cb,
                         const float* __restrict__ bg, const float* __restrict__ bb,
                         const float* __restrict__ bm, const float* __restrict__ bv) {
    int idx = blockIdx.x * 256 + threadIdx.x;
    if (idx >= 36 * 256 * 64) return;
    int ci = idx & 63;
    int t = idx >> 6;
    int co = t & 255;
    int c = t >> 8;
    int kh = c / 12, kw = (c >> 2) % 3, ci0 = (c & 3) << 6;
    float s = bg[co] * rsqrtf(bv[co] + 1e-5f);
    g_wc1[(c * 256 + co) * 64 + ci] = h16(cw[((co * 256 + ci0 + ci) * 3 + kh) * 3 + kw] * s);
    if (c == 0 && ci == 0) g_b1[co] = cb[co] * s + bb[co] - bm[co] * s;
}
__global__ void k_cvt_w2(const float* __restrict__ cw, const float* __restrict__ cb,
                         const float* __restrict__ bg, const float* __restrict__ bb,
                         const float* __restrict__ bm, const float* __restrict__ bv,
                         const float* __restrict__ iw, const float* __restrict__ ibi,
                         const float* __restrict__ ig, const float* __restrict__ ib2,
                         const float* __restrict__ im, const float* __restrict__ iv) {
    int idx = blockIdx.x * 256 + threadIdx.x;
    if (idx >= 40 * 256 * 64) return;
    int ci = idx & 63;
    int t = idx >> 6;
    int co = t & 255;
    int c = t >> 8;
    float wv;
    if (c < 36) {
        int kh = c / 12, kw = (c >> 2) % 3, ci0 = (c & 3) << 6;
        wv = cw[((co * 256 + ci0 + ci) * 3 + kh) * 3 + kw] * (bg[co] * rsqrtf(bv[co] + 1e-5f));
    } else {
        wv = iw[co * 256 + ((c - 36) << 6) + ci] * (ig[co] * rsqrtf(iv[co] + 1e-5f));
    }
    g_wc2[(c * 256 + co) * 64 + ci] = h16(wv);
    if (c == 0 && ci == 0) {
        float s  = bg[co] * rsqrtf(bv[co] + 1e-5f);
        float si = ig[co] * rsqrtf(iv[co] + 1e-5f);
        g_b2[co] = cb[co] * s + bb[co] - bm[co] * s + ibi[co] * si + ib2[co] - im[co] * si;
    }
}

// ---------------- K-QKV: [262144 x 128] @ [128 x 384] fp16 ----------------------
// Stage: B[384 rows][80B] @0 (30720), A[128 px][80B] @30720 (10240). 40960/stage.
#define QKV_STG 40960
__global__ __launch_bounds__(512, 1) void k_qkv() {
    extern __shared__ __align__(16) char smem[];
    int tid = threadIdx.x;
    int blk = blockIdx.x;                    // 2048
    int n = blk >> 9, hs = (blk >> 1) & 255, wb = blk & 1;
    int w0 = wb * 128;
    int h2 = (hs + 3) & 255;
    int warp = tid >> 5, lane = tid & 31;
    int wm = warp >> 2, wn = warp & 3;
    int gid = lane >> 2, tig = lane & 3;

    float acc[2][12][4];
    #pragma unroll
    for (int mt = 0; mt < 2; mt++)
        #pragma unroll
        for (int nt = 0; nt < 12; nt++)
            #pragma unroll
            for (int q = 0; q < 4; q++) acc[mt][nt][q] = 0.f;

    auto load_stage = [&](char* dst, int g) {
        int kc0 = g * 32;
        for (int i = tid; i < 1536; i += 512) {
            int c4 = i & 3; int nr = i >> 2;
            cp16(dst + nr * 80 + c4 * 16, g_wq + nr * 128 + kc0 + c4 * 8);
        }
        for (int i = tid; i < 512; i += 512) {
            int c4 = i & 3; int pr = i >> 2;
            int w2 = (w0 + pr + 3) & 255;
            cp16(dst + 30720 + pr * 80 + c4 * 16,
                 g_xuh + (((size_t)n * 256 + h2) * 256 + w2) * 128 + kc0 + c4 * 8);
        }
    };

    load_stage(smem, 0);
    cpa_commit();
    for (int g = 0; g < 4; g++) {
        if (g + 1 < 4) {
            load_stage(smem + ((g + 1) & 1) * QKV_STG, g + 1);
            cpa_commit();
            cpa_wait<1>();
        } else cpa_wait<0>();
        __syncthreads();

        uint32_t sb = smem_u32(smem + (g & 1) * QKV_STG);
        uint32_t aB = sb + 30720;
        int arow = wm * 32 + (lane & 15);
        int acol = ((lane >> 4) & 1) * 16;
        int brow = wn * 96 + (lane & 7);
        int bcol = ((lane >> 3) & 1) * 16;

        #pragma unroll
        for (int kc = 0; kc < 2; kc++) {
            uint32_t ah[2][4];
            #pragma unroll
            for (int mt = 0; mt < 2; mt++) {
                ldmx4(ah[mt], aB + (uint32_t)(arow + mt * 16) * 80 + kc * 32 + acol);
            }
            #pragma unroll
            for (int nt = 0; nt < 12; nt++) {
                uint32_t bd = sb + (uint32_t)(brow + nt * 8) * 80 + kc * 32 + bcol;
                uint32_t bv[2];
                ldmx2(bv, bd);
                #pragma unroll
                for (int mt = 0; mt < 2; mt++) mmah(acc[mt][nt], ah[mt], bv);
            }
        }
        __syncthreads();
    }

    size_t pbase = ((size_t)n * 256 + hs) * 256 + w0;
    #pragma unroll
    for (int nt = 0; nt < 12; nt++) {
        int col = wn * 96 + nt * 8 + 2 * tig;
        float b0 = g_bq[col], b1 = g_bq[col + 1];
        float sc = (col < 128) ? 0.17677669529663687f : 1.f;
        #pragma unroll
        for (int mt = 0; mt < 2; mt++) {
            int r0 = wm * 32 + mt * 16 + gid;
            float2 v0 = make_float2((acc[mt][nt][0] + b0) * sc, (acc[mt][nt][1] + b1) * sc);
            float2 v1 = make_float2((acc[mt][nt][2] + b0) * sc, (acc[mt][nt][3] + b1) * sc);
            *(float2*)&g_qkv[(pbase + r0) * 384 + col] = v0;
            *(float2*)&g_qkv[(pbase + r0 + 8) * 384 + col] = v1;
        }
    }
}

// ---------------- attention core: scores/softmax/PV per window ------------------
__global__ __launch_bounds__(128) void k_attn_core(const float* __restrict__ rpb) {
    __shared__ float QKV[16][384];
    __shared__ float P[4][16][16];
    __shared__ float O[16][128];
    int tid = threadIdx.x, blk = blockIdx.x;
    int n = blk >> 12, widx = blk & 4095, wh = widx >> 6, wc = widx & 63;

    for (int idx = tid; idx < 6144; idx += 128) {
        int t = idx / 384, c = idx - t * 384;
        size_t ps = ((size_t)n * 256 + wh * 4 + (t >> 2)) * 256 + wc * 4 + (t & 3);
        QKV[t][c] = g_qkv[ps * 384 + c];
    }
    __syncthreads();

    int warp = tid >> 5, lane = tid & 31;
    if (lane < 16) {
        int t = lane, h = warp;
        float q[32];
        #pragma unroll
        for (int d = 0; d < 32; d++) q[d] = QKV[t][h * 32 + d];
        int i1 = t >> 2, j1 = t & 3;
        int rh1 = wh * 4 + i1, rw1 = wc * 4 + j1;
        int l1 = ((rh1 < 252) ? 0 : ((rh1 < 253) ? 1 : 2)) * 3
               + ((rw1 < 252) ? 0 : ((rw1 < 253) ? 1 : 2));
        float s[16], mx = -1e30f;
        #pragma unroll
        for (int u = 0; u < 16; u++) {
            float dot = 0.f;
            #pragma unroll
            for (int d = 0; d < 32; d++) dot += q[d] * QKV[u][128 + h * 32 + d];
            int i2 = u >> 2, j2 = u & 3;
            dot += rpb[((i1 - i2 + 3) * 7 + (j1 - j2 + 3)) * 4 + h];
            int rh2 = wh * 4 + i2, rw2 = wc * 4 + j2;
            int l2 = ((rh2 < 252) ? 0 : ((rh2 < 253) ? 1 : 2)) * 3
                   + ((rw2 < 252) ? 0 : ((rw2 < 253) ? 1 : 2));
            if (l1 != l2) dot -= 100.f;
            s[u] = dot; mx = fmaxf(mx, dot);
        }
        float sum = 0.f;
        #pragma unroll
        for (int u = 0; u < 16; u++) { s[u] = __expf(s[u] - mx); sum += s[u]; }
        float inv = 1.f / sum;
        #pragma unroll
        for (int u = 0; u < 16; u++) P[h][t][u] = s[u] * inv;
    }
    __syncwarp();
    {
        int h = warp, d = lane;
        #pragma unroll
        for (int t = 0; t < 16; t++) {
            float acc = 0.f;
            #pragma unroll
            for (int u = 0; u < 16; u++) acc += P[h][t][u] * QKV[u][256 + h * 32 + d];
            O[t][h * 32 + d] = acc;
        }
    }
    __syncthreads();

    int t = tid >> 3, c0 = (tid & 7) * 16;
    int hs = wh * 4 + (t >> 2), ws = wc * 4 + (t & 3);
    int hh2 = (hs + 3) & 255, ww2 = (ws + 3) & 255;
    size_t po = (((size_t)n * 256 + hh2) * 256 + ww2) * 128;
    #pragma unroll
    for (int c = 0; c < 16; c++) g_oh[po + c0 + c] = h16(O[t][c0 + c]);
}

// ---------------- K-proj: [262144 x 128] @ [128 x 128] + bias + residual --------
// B[128 rows][272B] @0 (34816), A[128 px][272B] @34816 (34816).
__global__ __launch_bounds__(512, 1) void k_proj() {
    extern __shared__ __align__(16) char smem[];
    int tid = threadIdx.x;
    int blk = blockIdx.x;
    size_t p0 = (size_t)blk * 128;
    int warp = tid >> 5, lane = tid & 31;
    int wm = warp >> 2, wn = warp & 3;
    int gid = lane >> 2, tig = lane & 3;

    for (int i = tid; i < 2048; i += 512) {
        int c16 = i & 15; int nr = i >> 4;
        cp16(smem + nr * 272 + c16 * 16, g_wp + nr * 128 + c16 * 8);
    }
    for (int i = tid; i < 2048; i += 512) {
        int c16 = i & 15; int pr = i >> 4;
        cp16(smem + 34816 + pr * 272 + c16 * 16, g_oh + (p0 + pr) * 128 + c16 * 8);
    }
    cpa_commit();
    cpa_wait<0>();
    __syncthreads();

    float acc[2][4][4];
    #pragma unroll
    for (int mt = 0; mt < 2; mt++)
        #pragma unroll
        for (int nt = 0; nt < 4; nt++)
            #pragma unroll
            for (int q = 0; q < 4; q++) acc[mt][nt][q] = 0.f;

    uint32_t sb = smem_u32(smem);
    uint32_t aB = sb + 34816;
    int arow = wm * 32 + (lane & 15);
    int acol = ((lane >> 4) & 1) * 16;
    int brow = wn * 32 + (lane & 7);
    int bcol = ((lane >> 3) & 1) * 16;

    #pragma unroll
    for (int kc = 0; kc < 8; kc++) {
        uint32_t ah[2][4];
        #pragma unroll
        for (int mt = 0; mt < 2; mt++) {
            ldmx4(ah[mt], aB + (uint32_t)(arow + mt * 16) * 272 + kc * 32 + acol);
        }
        #pragma unroll
        for (int nt = 0; nt < 4; nt++) {
            uint32_t bd = sb + (uint32_t)(brow + nt * 8) * 272 + kc * 32 + bcol;
            uint32_t bv[2];
            ldmx2(bv, bd);
            #pragma unroll
            for (int mt = 0; mt < 2; mt++) mmah(acc[mt][nt], ah[mt], bv);
        }
    }

    #pragma unroll
    for (int nt = 0; nt < 4; nt++) {
        int coe = wn * 32 + nt * 8 + 2 * tig;
        float b0 = g_bp[coe], b1 = g_bp[coe + 1];
        #pragma unroll
        for (int mt = 0; mt < 2; mt++) {
            #pragma unroll
            for (int half = 0; half < 2; half++) {
                size_t p = p0 + wm * 32 + mt * 16 + gid + half * 8;
                float2 res = *(const float2*)&g_xu[p * 128 + coe];
                float v0 = acc[mt][nt][half * 2 + 0] + b0 + res.x;
                float v1 = acc[mt][nt][half * 2 + 1] + b1 + res.y;
                *(float2*)&g_y[p * 128 + coe] = make_float2(v0, v1);
            }
        }
    }
}

// ---------------- K-cvt-y: pack fp32 y into conv planes (smem transpose) --------
__global__ __launch_bounds__(256) void k_cvt_y() {
    __shared__ unsigned short sh[8192];
    int blk = blockIdx.x;                 // 4096 = 4*4*256
    int h = blk & 255;
    int cib = (blk >> 8) & 3;
    int n = blk >> 10;
    int tid = threadIdx.x;

    for (int i = tid; i < 8192; i += 256) {
        int ch = i >> 7, w = i & 127;
        sh[ch * 128 + w] = h16(g_y[(((size_t)n * 256 + cib * 64 + ch) * 256 + h) * 128 + w]);
    }
    __syncthreads();

    size_t base = (((size_t)(n * 4 + cib) * 256 + h) * 128) * 32;
    for (int o = tid; o < 4096; o += 256) {
        int w = o >> 5, j = o & 31;
        g_yhi[base + o] = (uint32_t)sh[(2 * j) * 128 + w]
                        | ((uint32_t)sh[(2 * j + 1) * 128 + w] << 16);
    }
}

// ---------------- conv: fp16 single-product, N=128, K-chunk 32, 2 CTAs/SM -------
// Stage: B[128 co][80B] @0 (10240), A[128 px][80B] @10240 (10240). 20480/stage.
#define CSTG 20480
#define CA_OFF 10240
template <int SECOND>
__global__ __launch_bounds__(512, 2) void k_conv_tc(float* __restrict__ out) {
    extern __shared__ __align__(16) char smem[];
    const int G = SECOND ? 80 : 72;       // 2 K-halves per weight chunk
    const unsigned short* Wc = SECOND ? g_wc2 : g_wc1;

    int tid = threadIdx.x;
    int blk = blockIdx.x;                 // 2048 = n(4) x h(256) x cob(2)
    int cob = blk & 1;
    int h = (blk >> 1) & 255;
    int n = blk >> 9;
    int warp = tid >> 5, lane = tid & 31;
    int wm = warp >> 2, wn = warp & 3;
    int gid = lane >> 2, tig = lane & 3;

    float acc[2][4][4];
    #pragma unroll
    for (int mt = 0; mt < 2; mt++)
        #pragma unroll
        for (int nt = 0; nt < 4; nt++)
            #pragma unroll
            for (int q = 0; q < 4; q++) acc[mt][nt][q] = 0.f;

    auto params = [&](int c, int& kh, int& kw, int& cib, const uint32_t*& sH) {
        if (!SECOND) { kh = c / 12; kw = (c >> 2) % 3; cib = c & 3; sH = g_yhi; }
        else if (c < 36) { kh = c / 12; kw = (c >> 2) % 3; cib = c & 3; sH = g_t1hi; }
        else { kh = 1; kw = 1; cib = c - 36; sH = g_yhi; }
    };
    auto load_stage = [&](char* dst, int g) {
        int c = g >> 1, kh2 = g & 1;
        // B: 128 co x 32 ci fp16 (64B/row)
        if (tid < 512) {
            int c4 = tid & 3; int row = tid >> 2;
            if (row < 128)
                cp16(dst + row * 80 + c4 * 16,
                     Wc + ((size_t)c * 256 + cob * 128 + row) * 64 + kh2 * 32 + c4 * 8);
        }
        // A: 128 px x 16 u32 (64B), contiguous plane rows
        int kh, kw, cib; const uint32_t* sH;
        params(c, kh, kw, cib, sH);
        int hh = h + kh - 1;
        bool okh = (unsigned)hh < 256u;
        int hc = okh ? hh : 0;
        {
            int c4 = tid & 3; int px = tid >> 2;
            if (px < 128) {
                int ww = px + kw - 1;
                bool ok = okh && ((unsigned)ww < 128u);
                const uint32_t* s2 = sH + ((((size_t)(n * 4 + cib) * 256 + hc) * 128
                                            + (ok ? ww : 0)) * 32 + kh2 * 16 + c4 * 4);
                cp16z(dst + CA_OFF + px * 80 + c4 * 16, s2, ok);
            }
        }
    };

    load_stage(smem, 0);
    cpa_commit();

    for (int g = 0; g < G; g++) {
        if (g + 1 < G) {
            load_stage(smem + ((g + 1) & 1) * CSTG, g + 1);
            cpa_commit();
            cpa_wait<1>();
        } else cpa_wait<0>();
        __syncthreads();

        uint32_t sb = smem_u32(smem + (g & 1) * CSTG);
        uint32_t aB = sb + CA_OFF;
        int arow = wm * 32 + (lane & 15);
        int acol = ((lane >> 4) & 1) * 16;
        int brow = wn * 32 + (lane & 7);
        int bcol = ((lane >> 3) & 1) * 16;

        #pragma unroll
        for (int kc = 0; kc < 2; kc++) {
            uint32_t ah[2][4];
            #pragma unroll
            for (int mt = 0; mt < 2; mt++) {
                ldmx4(ah[mt], aB + (uint32_t)(arow + mt * 16) * 80 + kc * 32 + acol);
            }
            #pragma unroll
            for (int nt = 0; nt < 4; nt++) {
                uint32_t bd = sb + (uint32_t)(brow + nt * 8) * 80 + kc * 32 + bcol;
                uint32_t bv[2];
                ldmx2(bv, bd);
                #pragma unroll
                for (int mt = 0; mt < 2; mt++) mmah(acc[mt][nt], ah[mt], bv);
            }
        }
        __syncthreads();
    }

    const float* bsrc = SECOND ? g_b2 : g_b1;
    #pragma unroll
    for (int nt = 0; nt < 4; nt++) {
        int coe = cob * 128 + wn * 32 + nt * 8 + 2 * tig;
        float b0 = bsrc[coe], b1 = bsrc[coe + 1];
        int j = coe >> 1;
        #pragma unroll
        for (int mt = 0; mt < 2; mt++) {
            int p0 = wm * 32 + mt * 16 + gid;
            float v00 = fmaxf(acc[mt][nt][0] + b0, 0.f);
            float v01 = fmaxf(acc[mt][nt][1] + b1, 0.f);
            float v10 = fmaxf(acc[mt][nt][2] + b0, 0.f);
            float v11 = fmaxf(acc[mt][nt][3] + b1, 0.f);
            if (SECOND) {
                size_t o0 = (((size_t)n * 256 + coe) * 256 + h) * 128;
                out[o0 + p0] = v00;
                out[o0 + p0 + 8] = v10;
                out[o0 + 32768 + p0] = v01;
                out[o0 + 32768 + p0 + 8] = v11;
            } else {
                size_t ob = (((size_t)(n * 4 + (j >> 5)) * 256 + h) * 128) * 32 + (j & 31);
                g_t1hi[ob + (size_t)p0 * 32] =
                    (uint32_t)h16(v00) | ((uint32_t)h16(v01) << 16);
                g_t1hi[ob + (size_t)(p0 + 8) * 32] =
                    (uint32_t)h16(v10) | ((uint32_t)h16(v11) << 16);
            }
        }
    }
}

// ---------------- launcher ------------------------------------------------------
extern "C" void kernel_launch(void* const* d_in, const int* in_sizes, int n_in,
                              void* d_out, int out_size) {
    const float* x      = (const float*)d_in[0];
    const float* qkv_w  = (const float*)d_in[1];
    const float* qkv_b  = (const float*)d_in[2];
    const float* proj_w = (const float*)d_in[3];
    const float* proj_b = (const float*)d_in[4];
    const float* rpb    = (const float*)d_in[5];
    const float* c1w = (const float*)d_in[6];
    const float* c1b = (const float*)d_in[7];
    const float* b1g = (const float*)d_in[8];
    const float* b1b = (const float*)d_in[9];
    const float* b1m = (const float*)d_in[10];
    const float* b1v = (const float*)d_in[11];
    const float* c2w = (const float*)d_in[12];
    const float* c2b = (const float*)d_in[13];
    const float* b2g = (const float*)d_in[14];
    const float* b2b = (const float*)d_in[15];
    const float* b2m = (const float*)d_in[16];
    const float* b2v = (const float*)d_in[17];
    const float* idw = (const float*)d_in[18];
    const float* idb = (const float*)d_in[19];
    const float* big = (const float*)d_in[20];
    const float* bib = (const float*)d_in[21];
    const float* bim = (const float*)d_in[22];
    const float* biv = (const float*)d_in[23];
    float* out = (float*)d_out;

    cudaFuncSetAttribute(k_qkv, cudaFuncAttributeMaxDynamicSharedMemorySize, 2 * QKV_STG);
    cudaFuncSetAttribute(k_proj, cudaFuncAttributeMaxDynamicSharedMemorySize, 69632);
    cudaFuncSetAttribute(k_conv_tc<0>, cudaFuncAttributeMaxDynamicSharedMemorySize, 2 * CSTG);
    cudaFuncSetAttribute(k_conv_tc<1>, cudaFuncAttributeMaxDynamicSharedMemorySize, 2 * CSTG);

    k_upsample<<<TOT / 256, 256>>>(x);
    k_cvt_wq<<<192, 256>>>(qkv_w, qkv_b);
    k_cvt_wp<<<64, 256>>>(proj_w, proj_b);
    k_cvt_w1<<<2304, 256>>>(c1w, c1b, b1g, b1b, b1m, b1v);
    k_cvt_w2<<<2560, 256>>>(c2w, c2b, b2g, b2b, b2m, b2v,
                            idw, idb, big, bib, bim, biv);
    k_qkv<<<2048, 512, 2 * QKV_STG>>>();
    k_attn_core<<<16384, 128>>>(rpb);
    k_proj<<<2048, 512, 69632>>>();
    k_cvt_y<<<4096, 256>>>();
    k_conv_tc<0><<<2048, 512, 2 * CSTG>>>(out);
    k_conv_tc<1><<<2048, 512, 2 * CSTG>>>(out);
}

// round 14
// speedup vs baseline: 6.3245x; 1.1895x over previous
#include <cuda_runtime.h>
#include <cuda_fp16.h>
#include <cstdint>

#define TOT (4*256*256*128)
static __device__ float g_xu[TOT];                    // upsampled x (B,H,W,C)
static __device__ unsigned short g_xuh[TOT];          // fp16 of g_xu
static __device__ uint32_t g_qkvh[(size_t)4*256*256*192]; // QKV fp16, packed col-pairs
static __device__ unsigned short g_oh[TOT];           // attention out O fp16 (orig coords)
static __device__ float g_y[TOT];                     // attention + residual (fp32)
// conv input planes: [n][cib(4)][h(256)][w(128)][j32(32 u32 = ci-pairs)]
static __device__ uint32_t g_yhi[TOT/2];
static __device__ uint32_t g_t1hi[TOT/2];
static __device__ unsigned short g_wc1[36*256*64];    // fp16 weights
static __device__ unsigned short g_wc2[40*256*64];
static __device__ unsigned short g_wq[384*128];       // qkv_w fp16 [n][k]
static __device__ unsigned short g_wp[128*128];       // proj_w fp16 [n][k]
static __device__ float g_b1[256], g_b2[256], g_bq[384], g_bp[128];

// ---------------- helpers -------------------------------------------------------
__device__ __forceinline__ uint32_t smem_u32(const void* p) {
    uint32_t r;
    asm("{ .reg .u64 t; cvta.to.shared.u64 t, %1; cvt.u32.u64 %0, t; }" : "=r"(r) : "l"(p));
    return r;
}
__device__ __forceinline__ unsigned short h16(float x) {
    return __half_as_ushort(__float2half_rn(x));
}
__device__ __forceinline__ void cp16(void* dst_smem, const void* src) {
    unsigned d = (unsigned)__cvta_generic_to_shared(dst_smem);
    asm volatile("cp.async.cg.shared.global [%0], [%1], 16;" :: "r"(d), "l"(src));
}
__device__ __forceinline__ void cp16z(void* dst_smem, const void* src, bool valid) {
    unsigned d = (unsigned)__cvta_generic_to_shared(dst_smem);
    int sz = valid ? 16 : 0;
    asm volatile("cp.async.cg.shared.global [%0], [%1], 16, %2;"
                 :: "r"(d), "l"(src), "r"(sz));
}
__device__ __forceinline__ void cpa_commit() { asm volatile("cp.async.commit_group;"); }
template <int N> __device__ __forceinline__ void cpa_wait() {
    asm volatile("cp.async.wait_group %0;" :: "n"(N));
}
__device__ __forceinline__ void ldmx4(uint32_t* r, uint32_t a) {
    asm volatile("ldmatrix.sync.aligned.m8n8.x4.shared.b16 {%0,%1,%2,%3}, [%4];"
                 : "=r"(r[0]), "=r"(r[1]), "=r"(r[2]), "=r"(r[3]) : "r"(a));
}
__device__ __forceinline__ void ldmx2(uint32_t* r, uint32_t a) {
    asm volatile("ldmatrix.sync.aligned.m8n8.x2.shared.b16 {%0,%1}, [%2];"
                 : "=r"(r[0]), "=r"(r[1]) : "r"(a));
}
__device__ __forceinline__ void mmah(float* d, const uint32_t* a, const uint32_t* b) {
    asm volatile(
        "mma.sync.aligned.m16n8k16.row.col.f32.f16.f16.f32 "
        "{%0,%1,%2,%3}, {%4,%5,%6,%7}, {%8,%9}, {%0,%1,%2,%3};"
        : "+f"(d[0]), "+f"(d[1]), "+f"(d[2]), "+f"(d[3])
        : "r"(a[0]), "r"(a[1]), "r"(a[2]), "r"(a[3]), "r"(b[0]), "r"(b[1]));
}

// ---------------- K1: bilinear 2x upsample + fp16 -------------------------------
__global__ void k_upsample(const float* __restrict__ xin) {
    int idx = blockIdx.x * 256 + threadIdx.x;
    int cc = idx & 127;
    int t  = idx >> 7;
    int ww = t & 255; t >>= 8;
    int hh = t & 255;
    int b  = t >> 8;
    float pw = ww * (127.0f / 255.0f);
    int wlo = (int)pw; float fw = pw - (float)wlo; int whi = min(wlo + 1, 127);
    float pc = cc * (63.0f / 127.0f);
    int clo = (int)pc; float fc = pc - (float)clo; int chi = min(clo + 1, 63);
    const float* base = xin + ((b * 256 + hh) * 128) * 64;
    float v00 = base[wlo * 64 + clo], v01 = base[wlo * 64 + chi];
    float v10 = base[whi * 64 + clo], v11 = base[whi * 64 + chi];
    float v = (1.f - fw) * ((1.f - fc) * v00 + fc * v01)
            +        fw  * ((1.f - fc) * v10 + fc * v11);
    g_xu[idx] = v;
    g_xuh[idx] = h16(v);
}

// ---------------- weight prep ---------------------------------------------------
__global__ void k_cvt_wq(const float* __restrict__ qkv_w, const float* __restrict__ qkv_b) {
    int idx = blockIdx.x * 256 + threadIdx.x;
    if (idx >= 49152) return;
    int k = idx & 127, nn = idx >> 7;
    g_wq[nn * 128 + k] = h16(qkv_w[k * 384 + nn]);
    if (k == 0) g_bq[nn] = qkv_b[nn];
}
__global__ void k_cvt_wp(const float* __restrict__ proj_w, const float* __restrict__ proj_b) {
    int idx = blockIdx.x * 256 + threadIdx.x;
    if (idx >= 16384) return;
    int k = idx & 127, nn = idx >> 7;
    g_wp[nn * 128 + k] = h16(proj_w[k * 128 + nn]);
    if (k == 0) g_bp[nn] = proj_b[nn];
}
__global__ void k_cvt_w1(const float* __restrict__ cw, const float* __restrict__ cb,
                         const float* __restrict__ bg, const float* __restrict__ bb,
                         const float* __restrict__ bm, const float* __restrict__ bv) {
    int idx = blockIdx.x * 256 + threadIdx.x;
    if (idx >= 36 * 256 * 64) return;
    int ci = idx & 63;
    int t = idx >> 6;
    int co = t & 255;
    int c = t >> 8;
    int kh = c / 12, kw = (c >> 2) % 3, ci0 = (c & 3) << 6;
    float s = bg[co] * rsqrtf(bv[co] + 1e-5f);
    g_wc1[(c * 256 + co) * 64 + ci] = h16(cw[((co * 256 + ci0 + ci) * 3 + kh) * 3 + kw] * s);
    if (c == 0 && ci == 0) g_b1[co] = cb[co] * s + bb[co] - bm[co] * s;
}
__global__ void k_cvt_w2(const float* __restrict__ cw, const float* __restrict__ cb,
                         const float* __restrict__ bg, const float* __restrict__ bb,
                         const float* __restrict__ bm, const float* __restrict__ bv,
                         const float* __restrict__ iw, const float* __restrict__ ibi,
                         const float* __restrict__ ig, const float* __restrict__ ib2,
                         const float* __restrict__ im, const float* __restrict__ iv) {
    int idx = blockIdx.x * 256 + threadIdx.x;
    if (idx >= 40 * 256 * 64) return;
    int ci = idx & 63;
    int t = idx >> 6;
    int co = t & 255;
    int c = t >> 8;
    float wv;
    if (c < 36) {
        int kh = c / 12, kw = (c >> 2) % 3, ci0 = (c & 3) << 6;
        wv = cw[((co * 256 + ci0 + ci) * 3 + kh) * 3 + kw] * (bg[co] * rsqrtf(bv[co] + 1e-5f));
    } else {
        wv = iw[co * 256 + ((c - 36) << 6) + ci] * (ig[co] * rsqrtf(iv[co] + 1e-5f));
    }
    g_wc2[(c * 256 + co) * 64 + ci] = h16(wv);
    if (c == 0 && ci == 0) {
        float s  = bg[co] * rsqrtf(bv[co] + 1e-5f);
        float si = ig[co] * rsqrtf(iv[co] + 1e-5f);
        g_b2[co] = cb[co] * s + bb[co] - bm[co] * s + ibi[co] * si + ib2[co] - im[co] * si;
    }
}

// ---------------- K-QKV: [262144 x 128] @ [128 x 384] fp16 ----------------------
// Stage: B[384 rows][80B] @0 (30720), A[128 px][80B] @30720. 40960/stage.
#define QKV_STG 40960
__global__ __launch_bounds__(512, 1) void k_qkv() {
    extern __shared__ __align__(16) char smem[];
    int tid = threadIdx.x;
    int blk = blockIdx.x;                    // 2048
    int n = blk >> 9, hs = (blk >> 1) & 255, wb = blk & 1;
    int w0 = wb * 128;
    int h2 = (hs + 3) & 255;
    int warp = tid >> 5, lane = tid & 31;
    int wm = warp >> 2, wn = warp & 3;
    int gid = lane >> 2, tig = lane & 3;

    float acc[2][12][4];
    #pragma unroll
    for (int mt = 0; mt < 2; mt++)
        #pragma unroll
        for (int nt = 0; nt < 12; nt++)
            #pragma unroll
            for (int q = 0; q < 4; q++) acc[mt][nt][q] = 0.f;

    auto load_stage = [&](char* dst, int g) {
        int kc0 = g * 32;
        for (int i = tid; i < 1536; i += 512) {
            int c4 = i & 3; int nr = i >> 2;
            cp16(dst + nr * 80 + c4 * 16, g_wq + nr * 128 + kc0 + c4 * 8);
        }
        for (int i = tid; i < 512; i += 512) {
            int c4 = i & 3; int pr = i >> 2;
            int w2 = (w0 + pr + 3) & 255;
            cp16(dst + 30720 + pr * 80 + c4 * 16,
                 g_xuh + (((size_t)n * 256 + h2) * 256 + w2) * 128 + kc0 + c4 * 8);
        }
    };

    load_stage(smem, 0);
    cpa_commit();
    for (int g = 0; g < 4; g++) {
        if (g + 1 < 4) {
            load_stage(smem + ((g + 1) & 1) * QKV_STG, g + 1);
            cpa_commit();
            cpa_wait<1>();
        } else cpa_wait<0>();
        __syncthreads();

        uint32_t sb = smem_u32(smem + (g & 1) * QKV_STG);
        uint32_t aB = sb + 30720;
        int arow = wm * 32 + (lane & 15);
        int acol = ((lane >> 4) & 1) * 16;
        int brow = wn * 96 + (lane & 7);
        int bcol = ((lane >> 3) & 1) * 16;

        #pragma unroll
        for (int kc = 0; kc < 2; kc++) {
            uint32_t ah[2][4];
            #pragma unroll
            for (int mt = 0; mt < 2; mt++) {
                ldmx4(ah[mt], aB + (uint32_t)(arow + mt * 16) * 80 + kc * 32 + acol);
            }
            #pragma unroll
            for (int nt = 0; nt < 12; nt++) {
                uint32_t bd = sb + (uint32_t)(brow + nt * 8) * 80 + kc * 32 + bcol;
                uint32_t bv[2];
                ldmx2(bv, bd);
                #pragma unroll
                for (int mt = 0; mt < 2; mt++) mmah(acc[mt][nt], ah[mt], bv);
            }
        }
        __syncthreads();
    }

    size_t pbase = ((size_t)n * 256 + hs) * 256 + w0;
    #pragma unroll
    for (int nt = 0; nt < 12; nt++) {
        int col = wn * 96 + nt * 8 + 2 * tig;
        float b0 = g_bq[col], b1 = g_bq[col + 1];
        float sc = (col < 128) ? 0.17677669529663687f : 1.f;
        #pragma unroll
        for (int mt = 0; mt < 2; mt++) {
            int r0 = wm * 32 + mt * 16 + gid;
            uint32_t p0 = (uint32_t)h16((acc[mt][nt][0] + b0) * sc)
                        | ((uint32_t)h16((acc[mt][nt][1] + b1) * sc) << 16);
            uint32_t p1 = (uint32_t)h16((acc[mt][nt][2] + b0) * sc)
                        | ((uint32_t)h16((acc[mt][nt][3] + b1) * sc) << 16);
            g_qkvh[(pbase + r0) * 192 + (col >> 1)] = p0;
            g_qkvh[(pbase + r0 + 8) * 192 + (col >> 1)] = p1;
        }
    }
}

// ---------------- attention core: scores/softmax/PV per window ------------------
__global__ __launch_bounds__(128) void k_attn_core(const float* __restrict__ rpb) {
    __shared__ float QKV[16][384];
    __shared__ float P[4][16][16];
    __shared__ float O[16][128];
    int tid = threadIdx.x, blk = blockIdx.x;
    int n = blk >> 12, widx = blk & 4095, wh = widx >> 6, wc = widx & 63;

    for (int idx = tid; idx < 3072; idx += 128) {
        int t = idx / 192, c = idx - t * 192;
        size_t ps = ((size_t)n * 256 + wh * 4 + (t >> 2)) * 256 + wc * 4 + (t & 3);
        uint32_t pk = g_qkvh[ps * 192 + c];
        __half2 hv = *(__half2*)&pk;
        QKV[t][2 * c]     = __half2float(__low2half(hv));
        QKV[t][2 * c + 1] = __half2float(__high2half(hv));
    }
    __syncthreads();

    int warp = tid >> 5, lane = tid & 31;
    if (lane < 16) {
        int t = lane, h = warp;
        float q[32];
        #pragma unroll
        for (int d = 0; d < 32; d++) q[d] = QKV[t][h * 32 + d];
        int i1 = t >> 2, j1 = t & 3;
        int rh1 = wh * 4 + i1, rw1 = wc * 4 + j1;
        int l1 = ((rh1 < 252) ? 0 : ((rh1 < 253) ? 1 : 2)) * 3
               + ((rw1 < 252) ? 0 : ((rw1 < 253) ? 1 : 2));
        float s[16], mx = -1e30f;
        #pragma unroll
        for (int u = 0; u < 16; u++) {
            float dot = 0.f;
            #pragma unroll
            for (int d = 0; d < 32; d++) dot += q[d] * QKV[u][128 + h * 32 + d];
            int i2 = u >> 2, j2 = u & 3;
            dot += rpb[((i1 - i2 + 3) * 7 + (j1 - j2 + 3)) * 4 + h];
            int rh2 = wh * 4 + i2, rw2 = wc * 4 + j2;
            int l2 = ((rh2 < 252) ? 0 : ((rh2 < 253) ? 1 : 2)) * 3
                   + ((rw2 < 252) ? 0 : ((rw2 < 253) ? 1 : 2));
            if (l1 != l2) dot -= 100.f;
            s[u] = dot; mx = fmaxf(mx, dot);
        }
        float sum = 0.f;
        #pragma unroll
        for (int u = 0; u < 16; u++) { s[u] = __expf(s[u] - mx); sum += s[u]; }
        float inv = 1.f / sum;
        #pragma unroll
        for (int u = 0; u < 16; u++) P[h][t][u] = s[u] * inv;
    }
    __syncwarp();
    {
        int h = warp, d = lane;
        #pragma unroll
        for (int t = 0; t < 16; t++) {
            float acc = 0.f;
            #pragma unroll
            for (int u = 0; u < 16; u++) acc += P[h][t][u] * QKV[u][256 + h * 32 + d];
            O[t][h * 32 + d] = acc;
        }
    }
    __syncthreads();

    int t = tid >> 3, c0 = (tid & 7) * 16;
    int hs = wh * 4 + (t >> 2), ws = wc * 4 + (t & 3);
    int hh2 = (hs + 3) & 255, ww2 = (ws + 3) & 255;
    size_t po = (((size_t)n * 256 + hh2) * 256 + ww2) * 128;
    #pragma unroll
    for (int c = 0; c < 16; c++) g_oh[po + c0 + c] = h16(O[t][c0 + c]);
}

// ---------------- K-proj: [262144 x 128] @ [128 x 128] + bias + residual --------
__global__ __launch_bounds__(512, 1) void k_proj() {
    extern __shared__ __align__(16) char smem[];
    int tid = threadIdx.x;
    int blk = blockIdx.x;
    size_t p0 = (size_t)blk * 128;
    int warp = tid >> 5, lane = tid & 31;
    int wm = warp >> 2, wn = warp & 3;
    int gid = lane >> 2, tig = lane & 3;

    for (int i = tid; i < 2048; i += 512) {
        int c16 = i & 15; int nr = i >> 4;
        cp16(smem + nr * 272 + c16 * 16, g_wp + nr * 128 + c16 * 8);
    }
    for (int i = tid; i < 2048; i += 512) {
        int c16 = i & 15; int pr = i >> 4;
        cp16(smem + 34816 + pr * 272 + c16 * 16, g_oh + (p0 + pr) * 128 + c16 * 8);
    }
    cpa_commit();
    cpa_wait<0>();
    __syncthreads();

    float acc[2][4][4];
    #pragma unroll
    for (int mt = 0; mt < 2; mt++)
        #pragma unroll
        for (int nt = 0; nt < 4; nt++)
            #pragma unroll
            for (int q = 0; q < 4; q++) acc[mt][nt][q] = 0.f;

    uint32_t sb = smem_u32(smem);
    uint32_t aB = sb + 34816;
    int arow = wm * 32 + (lane & 15);
    int acol = ((lane >> 4) & 1) * 16;
    int brow = wn * 32 + (lane & 7);
    int bcol = ((lane >> 3) & 1) * 16;

    #pragma unroll
    for (int kc = 0; kc < 8; kc++) {
        uint32_t ah[2][4];
        #pragma unroll
        for (int mt = 0; mt < 2; mt++) {
            ldmx4(ah[mt], aB + (uint32_t)(arow + mt * 16) * 272 + kc * 32 + acol);
        }
        #pragma unroll
        for (int nt = 0; nt < 4; nt++) {
            uint32_t bd = sb + (uint32_t)(brow + nt * 8) * 272 + kc * 32 + bcol;
            uint32_t bv[2];
            ldmx2(bv, bd);
            #pragma unroll
            for (int mt = 0; mt < 2; mt++) mmah(acc[mt][nt], ah[mt], bv);
        }
    }

    #pragma unroll
    for (int nt = 0; nt < 4; nt++) {
        int coe = wn * 32 + nt * 8 + 2 * tig;
        float b0 = g_bp[coe], b1 = g_bp[coe + 1];
        #pragma unroll
        for (int mt = 0; mt < 2; mt++) {
            #pragma unroll
            for (int half = 0; half < 2; half++) {
                size_t p = p0 + wm * 32 + mt * 16 + gid + half * 8;
                float2 res = *(const float2*)&g_xu[p * 128 + coe];
                float v0 = acc[mt][nt][half * 2 + 0] + b0 + res.x;
                float v1 = acc[mt][nt][half * 2 + 1] + b1 + res.y;
                *(float2*)&g_y[p * 128 + coe] = make_float2(v0, v1);
            }
        }
    }
}

// ---------------- K-cvt-y: pack fp32 y into conv planes (smem transpose) --------
__global__ __launch_bounds__(256) void k_cvt_y() {
    __shared__ unsigned short sh[8192];
    int blk = blockIdx.x;                 // 4096 = 4*4*256
    int h = blk & 255;
    int cib = (blk >> 8) & 3;
    int n = blk >> 10;
    int tid = threadIdx.x;

    for (int i = tid; i < 8192; i += 256) {
        int ch = i >> 7, w = i & 127;
        sh[ch * 128 + w] = h16(g_y[(((size_t)n * 256 + cib * 64 + ch) * 256 + h) * 128 + w]);
    }
    __syncthreads();

    size_t base = (((size_t)(n * 4 + cib) * 256 + h) * 128) * 32;
    for (int o = tid; o < 4096; o += 256) {
        int w = o >> 5, j = o & 31;
        g_yhi[base + o] = (uint32_t)sh[(2 * j) * 128 + w]
                        | ((uint32_t)sh[(2 * j + 1) * 128 + w] << 16);
    }
}

// ---------------- conv: fp16, K-chunk 64 stages, N=128, 2 CTAs/SM ---------------
// Stage: B[128 co][144B] @0 (18432), A[128 px][144B] @18432. 36864/stage.
#define CSTG 36864
#define CA_OFF 18432
template <int SECOND>
__global__ __launch_bounds__(512, 2) void k_conv_tc(float* __restrict__ out) {
    extern __shared__ __align__(16) char smem[];
    const int G = SECOND ? 40 : 36;       // one stage per weight chunk (64 ci)
    const unsigned short* Wc = SECOND ? g_wc2 : g_wc1;

    int tid = threadIdx.x;
    int blk = blockIdx.x;                 // 2048 = n(4) x h(256) x cob(2)
    int cob = blk & 1;
    int h = (blk >> 1) & 255;
    int n = blk >> 9;
    int warp = tid >> 5, lane = tid & 31;
    int wm = warp >> 2, wn = warp & 3;
    int gid = lane >> 2, tig = lane & 3;

    float acc[2][4][4];
    #pragma unroll
    for (int mt = 0; mt < 2; mt++)
        #pragma unroll
        for (int nt = 0; nt < 4; nt++)
            #pragma unroll
            for (int q = 0; q < 4; q++) acc[mt][nt][q] = 0.f;

    auto params = [&](int c, int& kh, int& kw, int& cib, const uint32_t*& sH) {
        if (!SECOND) { kh = c / 12; kw = (c >> 2) % 3; cib = c & 3; sH = g_yhi; }
        else if (c < 36) { kh = c / 12; kw = (c >> 2) % 3; cib = c & 3; sH = g_t1hi; }
        else { kh = 1; kw = 1; cib = c - 36; sH = g_yhi; }
    };
    auto load_stage = [&](char* dst, int c) {
        // B: 128 co x 64 ci fp16 (128B/row), 8 cp16 per row
        for (int i = tid; i < 1024; i += 512) {
            int c8 = i & 7; int row = i >> 3;
            cp16(dst + row * 144 + c8 * 16,
                 Wc + ((size_t)c * 256 + cob * 128 + row) * 64 + c8 * 8);
        }
        // A: 128 px x 32 u32 (128B full plane row)
        int kh, kw, cib; const uint32_t* sH;
        params(c, kh, kw, cib, sH);
        int hh = h + kh - 1;
        bool okh = (unsigned)hh < 256u;
        int hc = okh ? hh : 0;
        for (int i = tid; i < 1024; i += 512) {
            int c8 = i & 7; int px = i >> 3;
            int ww = px + kw - 1;
            bool ok = okh && ((unsigned)ww < 128u);
            const uint32_t* s2 = sH + ((((size_t)(n * 4 + cib) * 256 + hc) * 128
                                        + (ok ? ww : 0)) * 32 + c8 * 4);
            cp16z(dst + CA_OFF + px * 144 + c8 * 16, s2, ok);
        }
    };

    load_stage(smem, 0);
    cpa_commit();

    for (int g = 0; g < G; g++) {
        if (g + 1 < G) {
            load_stage(smem + ((g + 1) & 1) * CSTG, g + 1);
            cpa_commit();
            cpa_wait<1>();
        } else cpa_wait<0>();
        __syncthreads();

        uint32_t sb = smem_u32(smem + (g & 1) * CSTG);
        uint32_t aB = sb + CA_OFF;
        int arow = wm * 32 + (lane & 15);
        int acol = ((lane >> 4) & 1) * 16;
        int brow = wn * 32 + (lane & 7);
        int bcol = ((lane >> 3) & 1) * 16;

        #pragma unroll
        for (int kc = 0; kc < 4; kc++) {
            uint32_t ah[2][4];
            #pragma unroll
            for (int mt = 0; mt < 2; mt++) {
                ldmx4(ah[mt], aB + (uint32_t)(arow + mt * 16) * 144 + kc * 32 + acol);
            }
            #pragma unroll
            for (int nt = 0; nt < 4; nt++) {
                uint32_t bd = sb + (uint32_t)(brow + nt * 8) * 144 + kc * 32 + bcol;
                uint32_t bv[2];
                ldmx2(bv, bd);
                #pragma unroll
                for (int mt = 0; mt < 2; mt++) mmah(acc[mt][nt], ah[mt], bv);
            }
        }
        __syncthreads();
    }

    const float* bsrc = SECOND ? g_b2 : g_b1;
    #pragma unroll
    for (int nt = 0; nt < 4; nt++) {
        int coe = cob * 128 + wn * 32 + nt * 8 + 2 * tig;
        float b0 = bsrc[coe], b1 = bsrc[coe + 1];
        int j = coe >> 1;
        #pragma unroll
        for (int mt = 0; mt < 2; mt++) {
            int p0 = wm * 32 + mt * 16 + gid;
            float v00 = fmaxf(acc[mt][nt][0] + b0, 0.f);
            float v01 = fmaxf(acc[mt][nt][1] + b1, 0.f);
            float v10 = fmaxf(acc[mt][nt][2] + b0, 0.f);
            float v11 = fmaxf(acc[mt][nt][3] + b1, 0.f);
            if (SECOND) {
                size_t o0 = (((size_t)n * 256 + coe) * 256 + h) * 128;
                out[o0 + p0] = v00;
                out[o0 + p0 + 8] = v10;
                out[o0 + 32768 + p0] = v01;
                out[o0 + 32768 + p0 + 8] = v11;
            } else {
                size_t ob = (((size_t)(n * 4 + (j >> 5)) * 256 + h) * 128) * 32 + (j & 31);
                g_t1hi[ob + (size_t)p0 * 32] =
                    (uint32_t)h16(v00) | ((uint32_t)h16(v01) << 16);
                g_t1hi[ob + (size_t)(p0 + 8) * 32] =
                    (uint32_t)h16(v10) | ((uint32_t)h16(v11) << 16);
            }
        }
    }
}

// ---------------- launcher ------------------------------------------------------
extern "C" void kernel_launch(void* const* d_in, const int* in_sizes, int n_in,
                              void* d_out, int out_size) {
    const float* x      = (const float*)d_in[0];
    const float* qkv_w  = (const float*)d_in[1];
    const float* qkv_b  = (const float*)d_in[2];
    const float* proj_w = (const float*)d_in[3];
    const float* proj_b = (const float*)d_in[4];
    const float* rpb    = (const float*)d_in[5];
    const float* c1w = (const float*)d_in[6];
    const float* c1b = (const float*)d_in[7];
    const float* b1g = (const float*)d_in[8];
    const float* b1b = (const float*)d_in[9];
    const float* b1m = (const float*)d_in[10];
    const float* b1v = (const float*)d_in[11];
    const float* c2w = (const float*)d_in[12];
    const float* c2b = (const float*)d_in[13];
    const float* b2g = (const float*)d_in[14];
    const float* b2b = (const float*)d_in[15];
    const float* b2m = (const float*)d_in[16];
    const float* b2v = (const float*)d_in[17];
    const float* idw = (const float*)d_in[18];
    const float* idb = (const float*)d_in[19];
    const float* big = (const float*)d_in[20];
    const float* bib = (const float*)d_in[21];
    const float* bim = (const float*)d_in[22];
    const float* biv = (const float*)d_in[23];
    float* out = (float*)d_out;

    cudaFuncSetAttribute(k_qkv, cudaFuncAttributeMaxDynamicSharedMemorySize, 2 * QKV_STG);
    cudaFuncSetAttribute(k_proj, cudaFuncAttributeMaxDynamicSharedMemorySize, 69632);
    cudaFuncSetAttribute(k_conv_tc<0>, cudaFuncAttributeMaxDynamicSharedMemorySize, 2 * CSTG);
    cudaFuncSetAttribute(k_conv_tc<1>, cudaFuncAttributeMaxDynamicSharedMemorySize, 2 * CSTG);

    k_upsample<<<TOT / 256, 256>>>(x);
    k_cvt_wq<<<192, 256>>>(qkv_w, qkv_b);
    k_cvt_wp<<<64, 256>>>(proj_w, proj_b);
    k_cvt_w1<<<2304, 256>>>(c1w, c1b, b1g, b1b, b1m, b1v);
    k_cvt_w2<<<2560, 256>>>(c2w, c2b, b2g, b2b, b2m, b2v,
                            idw, idb, big, bib, bim, biv);
    k_qkv<<<2048, 512, 2 * QKV_STG>>>();
    k_attn_core<<<16384, 128>>>(rpb);
    k_proj<<<2048, 512, 69632>>>();
    k_cvt_y<<<4096, 256>>>();
    k_conv_tc<0><<<2048, 512, 2 * CSTG>>>(out);
    k_conv_tc<1><<<2048, 512, 2 * CSTG>>>(out);
}